// round 2
// baseline (speedup 1.0000x reference)
#include <cuda_runtime.h>
#include <math_constants.h>

// Quantizer_33036888441545 — VQ argmin + gather + loss.
// x: [B=65536, 128] f32, codes: [1, 4096, 128] f32.
// Output (float32, concatenated): quantized [B*128], indices [B], loss [1].

#define DDIM   128
#define BM     128
#define BN     128
#define TPB    256
#define PITCH  132                       // 132*4 = 528 bytes, 16B-aligned rows
#define SMEM_BYTES (2 * DDIM * PITCH * 4)

__device__ float g_cnorm[8192];
__device__ float g_block_loss[1024];

// ---- ||c_j||^2 for every code (one warp per code) ----
__global__ void cnorm_kernel(const float* __restrict__ codes, int C)
{
    int j    = blockIdx.x * (TPB / 32) + (threadIdx.x >> 5);
    int lane = threadIdx.x & 31;
    if (j >= C) return;
    float4 v = reinterpret_cast<const float4*>(codes + (size_t)j * DDIM)[lane];
    float s = v.x * v.x + v.y * v.y + v.z * v.z + v.w * v.w;
#pragma unroll
    for (int o = 16; o; o >>= 1) s += __shfl_xor_sync(0xffffffffu, s, o);
    if (lane == 0) g_cnorm[j] = s;
}

// ---- main: 128x128-tile GEMM with fused online argmin + gather + loss ----
__global__ __launch_bounds__(TPB, 1)
void vq_main(const float* __restrict__ x, const float* __restrict__ codes,
             float* __restrict__ out_q, float* __restrict__ out_idx,
             int B, int C, int write_idx)
{
    extern __shared__ float smem[];
    float* xs = smem;                    // [k][row], pitch PITCH
    float* cs = smem + DDIM * PITCH;     // [k][col], pitch PITCH

    const int tid  = threadIdx.x;
    const int tx   = tid & 15;           // col group (8 cols)
    const int ty   = tid >> 4;           // row group (8 rows)
    const int row0 = blockIdx.x * BM;

    // Load x tile transposed into smem. Lane-consecutive rows -> conflict-free STS.
    for (int i = tid; i < BM * 32; i += TPB) {
        int row = i & (BM - 1);
        int k4  = i >> 7;                // BM == 128
        float4 v = reinterpret_cast<const float4*>(x)[(size_t)(row0 + row) * 32 + k4];
        xs[(k4 * 4 + 0) * PITCH + row] = v.x;
        xs[(k4 * 4 + 1) * PITCH + row] = v.y;
        xs[(k4 * 4 + 2) * PITCH + row] = v.z;
        xs[(k4 * 4 + 3) * PITCH + row] = v.w;
    }

    float acc[8][8];
#pragma unroll
    for (int i = 0; i < 8; i++)
#pragma unroll
        for (int j = 0; j < 8; j++) acc[i][j] = 0.0f;

    float bestv[8];
    int   besti[8];
#pragma unroll
    for (int i = 0; i < 8; i++) { bestv[i] = CUDART_INF_F; besti[i] = 0; }

    for (int col0 = 0; col0 < C; col0 += BN) {
        __syncthreads();
        // Load code tile transposed.
        for (int i = tid; i < BN * 32; i += TPB) {
            int col = i & (BN - 1);
            int k4  = i >> 7;
            float4 v = reinterpret_cast<const float4*>(codes)[(size_t)(col0 + col) * 32 + k4];
            cs[(k4 * 4 + 0) * PITCH + col] = v.x;
            cs[(k4 * 4 + 1) * PITCH + col] = v.y;
            cs[(k4 * 4 + 2) * PITCH + col] = v.z;
            cs[(k4 * 4 + 3) * PITCH + col] = v.w;
        }
        __syncthreads();

#pragma unroll 4
        for (int k = 0; k < DDIM; k++) {
            float4 a0 = *reinterpret_cast<const float4*>(&xs[k * PITCH + ty * 8]);
            float4 a1 = *reinterpret_cast<const float4*>(&xs[k * PITCH + ty * 8 + 4]);
            float4 b0 = *reinterpret_cast<const float4*>(&cs[k * PITCH + tx * 8]);
            float4 b1 = *reinterpret_cast<const float4*>(&cs[k * PITCH + tx * 8 + 4]);
            float a[8] = {a0.x, a0.y, a0.z, a0.w, a1.x, a1.y, a1.z, a1.w};
            float b[8] = {b0.x, b0.y, b0.z, b0.w, b1.x, b1.y, b1.z, b1.w};
#pragma unroll
            for (int i = 0; i < 8; i++)
#pragma unroll
                for (int j = 0; j < 8; j++)
                    acc[i][j] = fmaf(a[i], b[j], acc[i][j]);
        }

        // Online argmin on key = ||c||^2 - 2 x.c (same ordering as reference d2).
#pragma unroll
        for (int j = 0; j < 8; j++) {
            float cnj = g_cnorm[col0 + tx * 8 + j];
            int   cj  = col0 + tx * 8 + j;
#pragma unroll
            for (int i = 0; i < 8; i++) {
                float key = fmaf(-2.0f, acc[i][j], cnj);
                if (key < bestv[i]) { bestv[i] = key; besti[i] = cj; }
                acc[i][j] = 0.0f;
            }
        }
    }

    // Reduce (min, idx) across the 16 lanes sharing each row group; first-index tie-break.
    float thr_loss = 0.0f;
#pragma unroll
    for (int i = 0; i < 8; i++) {
        float v  = bestv[i];
        int   bi = besti[i];
#pragma unroll
        for (int o = 8; o; o >>= 1) {
            float vo = __shfl_xor_sync(0xffffffffu, v,  o);
            int   io = __shfl_xor_sync(0xffffffffu, bi, o);
            if (vo < v || (vo == v && io < bi)) { v = vo; bi = io; }
        }
        int row  = ty * 8 + i;
        int grow = row0 + row;
        if (tx == 0 && write_idx) out_idx[grow] = (float)bi;

        // Cooperative gather of codes[bi] (coalesced 512B/row) + loss partial.
        const float4* cq = reinterpret_cast<const float4*>(codes + (size_t)bi * DDIM + tx * 8);
        float4 q0 = cq[0], q1 = cq[1];
        reinterpret_cast<float4*>(out_q + (size_t)grow * DDIM + tx * 8)[0] = q0;
        reinterpret_cast<float4*>(out_q + (size_t)grow * DDIM + tx * 8)[1] = q1;
        float qv[8] = {q0.x, q0.y, q0.z, q0.w, q1.x, q1.y, q1.z, q1.w};
#pragma unroll
        for (int c = 0; c < 8; c++) {
            float xv = xs[(tx * 8 + c) * PITCH + row];
            float d  = xv - qv[c];
            thr_loss = fmaf(d, d, thr_loss);
        }
    }

    // Deterministic block reduction of the loss partial.
    __shared__ float red[TPB / 32];
#pragma unroll
    for (int o = 16; o; o >>= 1) thr_loss += __shfl_xor_sync(0xffffffffu, thr_loss, o);
    if ((tid & 31) == 0) red[tid >> 5] = thr_loss;
    __syncthreads();
    if (tid == 0) {
        float s = 0.0f;
#pragma unroll
        for (int w = 0; w < TPB / 32; w++) s += red[w];
        g_block_loss[blockIdx.x] = s;
    }
}

// ---- deterministic fixed-order final loss reduction ----
__global__ void finalize_kernel(float* __restrict__ out_loss, int nblocks, float invB)
{
    __shared__ float red[256];
    float s = 0.0f;
    for (int i = threadIdx.x; i < nblocks; i += 256) s += g_block_loss[i];
    red[threadIdx.x] = s;
    __syncthreads();
    for (int o = 128; o; o >>= 1) {
        if (threadIdx.x < o) red[threadIdx.x] += red[threadIdx.x + o];
        __syncthreads();
    }
    // loss = loss_commit + BETA*loss_codebook = (1 + 0.25) * mean ||x - q||^2
    if (threadIdx.x == 0) *out_loss = 1.25f * red[0] * invB;
}

extern "C" void kernel_launch(void* const* d_in, const int* in_sizes, int n_in,
                              void* d_out, int out_size)
{
    const float* x     = (const float*)d_in[0];
    const float* codes = (const float*)d_in[1];
    const int B = in_sizes[0] / DDIM;
    const int C = in_sizes[1] / DDIM;

    float* out      = (float*)d_out;
    float* out_q    = out;
    float* out_idx  = out + (size_t)B * DDIM;
    float* out_loss = out + (size_t)B * DDIM + B;

    const long long need_idx  = (long long)B * DDIM + B;
    const long long need_loss = need_idx + 1;
    const int write_idx  = ((long long)out_size >= need_idx)  ? 1 : 0;
    const int write_loss = ((long long)out_size >= need_loss) ? 1 : 0;

    (void)cudaFuncSetAttribute(vq_main, cudaFuncAttributeMaxDynamicSharedMemorySize, SMEM_BYTES);

    cnorm_kernel<<<(C + 7) / 8, TPB>>>(codes, C);
    vq_main<<<B / BM, TPB, SMEM_BYTES>>>(x, codes, out_q, out_idx, B, C, write_idx);
    if (write_loss)
        finalize_kernel<<<1, 256>>>(out_loss, B / BM, 1.0f / (float)B);
}

// round 4
// speedup vs baseline: 1.7014x; 1.7014x over previous
#include <cuda_runtime.h>
#include <math_constants.h>
#include <cstdint>

// Quantizer_33036888441545 — VQ argmin + gather + loss via legacy mma.sync tf32 (3xTF32 split).
// x: [B=65536, 128] f32, codes: [1, 4096, 128] f32.
// Output (f32, concat): quantized [B*128], indices [B], loss [1].

#define DDIM 128
#define BM   128
#define MAXB 65536
#define MAXC 4096

// Frag-packed splits (written by split kernels, consumed by main kernel via cp.async).
__device__ float g_xh[MAXB * DDIM];
__device__ float g_xl[MAXB * DDIM];
__device__ float g_ch[MAXC * DDIM];
__device__ float g_cl[MAXC * DDIM];
__device__ float g_cnorm[MAXC];
__device__ float g_block_loss[MAXB / BM];

// ---- smem map (bytes) ----
#define AH_OFF   0         // 64KB  A-hi frags, resident
#define AL_OFF   65536     // 64KB  A-lo frags, resident
#define SLOT_OFF 131072    // 4 x 16KB B-chunk ring
#define MB_OFF   196608    // full[4] @ +0, empty[4] @ +32
#define BV_OFF   196672    // float bestv[2][128]
#define BI_OFF   197696    // int   besti[2][128]
#define RED_OFF  198720    // float red[8]
#define SMEM_MAIN 198784

// ============ helpers ============
__device__ __forceinline__ uint32_t smem_u32(const void* p) {
    uint32_t a;
    asm("{ .reg .u64 t; cvta.to.shared.u64 t, %1; cvt.u32.u64 %0, t; }" : "=r"(a) : "l"(p));
    return a;
}
__device__ __forceinline__ void mbar_init(uint32_t a, uint32_t cnt) {
    asm volatile("mbarrier.init.shared.b64 [%0], %1;" :: "r"(a), "r"(cnt) : "memory");
}
__device__ __forceinline__ void mbar_arrive(uint32_t a) {
    asm volatile("mbarrier.arrive.shared.b64 _, [%0];" :: "r"(a) : "memory");
}
__device__ __forceinline__ void mbar_wait(uint32_t a, uint32_t parity) {
    uint32_t done = 0;
    while (!done) {
        asm volatile(
            "{ .reg .pred p; mbarrier.try_wait.parity.acquire.cta.shared::cta.b64 p, [%1], %2, 0x989680; selp.b32 %0,1,0,p; }"
            : "=r"(done) : "r"(a), "r"(parity) : "memory");
    }
}
__device__ __forceinline__ void cp16(uint32_t dst, const float* src) {
    asm volatile("cp.async.cg.shared.global [%0], [%1], 16;" :: "r"(dst), "l"(src) : "memory");
}
__device__ __forceinline__ void cp_commit() { asm volatile("cp.async.commit_group;" ::: "memory"); }
__device__ __forceinline__ void cp_wait0()  { asm volatile("cp.async.wait_group 0;"  ::: "memory"); }

__device__ __forceinline__ void mma8(float* c, const uint4& a, const uint2& b) {
    asm volatile(
        "mma.sync.aligned.m16n8k8.row.col.f32.tf32.tf32.f32 "
        "{%0,%1,%2,%3}, {%4,%5,%6,%7}, {%8,%9}, {%0,%1,%2,%3};"
        : "+f"(c[0]), "+f"(c[1]), "+f"(c[2]), "+f"(c[3])
        : "r"(a.x), "r"(a.y), "r"(a.z), "r"(a.w), "r"(b.x), "r"(b.y));
}

// ============ split kernels: tf32 hi/lo + fragment-layout pack ============
// A frag layout (per 128-row block): [ks(16)][maCTA(8)][lane(32)][reg(4)]  (64KB/blk)
__global__ void split_x(const float* __restrict__ x, int n4)
{
    int i = blockIdx.x * 256 + threadIdx.x;
    if (i >= n4) return;
    int m = i >> 5, q = i & 31, k0 = q * 4;
    float4 v = reinterpret_cast<const float4*>(x)[i];
    float vv[4] = {v.x, v.y, v.z, v.w};
    int blk = m >> 7, mloc = m & 127, ma = mloc >> 4, mrow = mloc & 15;
    int lane_m = (mrow & 7) * 4, regm = mrow >> 3;
#pragma unroll
    for (int j = 0; j < 4; j++) {
        int k = k0 + j;
        int ks = k >> 3, kk = k & 7;
        int lane = lane_m + (kk & 3);
        int reg  = ((kk >> 2) << 1) | regm;
        size_t idx = ((((size_t)blk * 16 + ks) * 8 + ma) * 32 + lane) * 4 + reg;
        uint32_t hb; asm("cvt.rna.tf32.f32 %0, %1;" : "=r"(hb) : "f"(vv[j]));
        float h = __uint_as_float(hb);
        float l = vv[j] - h;
        uint32_t lb; asm("cvt.rna.tf32.f32 %0, %1;" : "=r"(lb) : "f"(l));
        g_xh[idx] = h;
        g_xl[idx] = __uint_as_float(lb);
    }
}

// B frag layout: [t][kc(4)][ks(4)][na(16)][lane(32)][reg(2)]  (16KB per (t,kc) chunk)
__global__ void split_c(const float* __restrict__ codes, int n4)
{
    int i = blockIdx.x * 256 + threadIdx.x;
    if (i >= n4) return;
    int n = i >> 5, q = i & 31, k0 = q * 4;
    float4 v = reinterpret_cast<const float4*>(codes)[i];
    float vv[4] = {v.x, v.y, v.z, v.w};
    int t = n >> 7, nloc = n & 127, na = nloc >> 3;
    int lane_n = (nloc & 7) * 4;
#pragma unroll
    for (int j = 0; j < 4; j++) {
        int k = k0 + j;
        int kc = k >> 5, ks = (k >> 3) & 3;
        int lane = lane_n + (k & 3);
        int reg  = (k >> 2) & 1;
        size_t idx = ((((size_t)(t * 4 + kc) * 4 + ks) * 16 + na) * 32 + lane) * 2 + reg;
        uint32_t hb; asm("cvt.rna.tf32.f32 %0, %1;" : "=r"(hb) : "f"(vv[j]));
        float h = __uint_as_float(hb);
        float l = vv[j] - h;
        uint32_t lb; asm("cvt.rna.tf32.f32 %0, %1;" : "=r"(lb) : "f"(l));
        g_ch[idx] = h;
        g_cl[idx] = __uint_as_float(lb);
    }
}

__global__ void cnorm_kernel(const float* __restrict__ codes, int C)
{
    int j = blockIdx.x * 8 + (threadIdx.x >> 5);
    int lane = threadIdx.x & 31;
    if (j >= C) return;
    float4 v = reinterpret_cast<const float4*>(codes + (size_t)j * DDIM)[lane];
    float s = v.x * v.x + v.y * v.y + v.z * v.z + v.w * v.w;
#pragma unroll
    for (int o = 16; o; o >>= 1) s += __shfl_xor_sync(0xffffffffu, s, o);
    if (lane == 0) g_cnorm[j] = s;
}

// ============ main kernel ============
// 8 warps: 0-3 math (2x2 warp grid, 64x64 tiles), 4-7 producers (one slot each).
__global__ __launch_bounds__(256, 1)
void vq_mma(const float* __restrict__ x, const float* __restrict__ codes,
            float* __restrict__ out_q, float* __restrict__ out_idx,
            int C, int write_idx)
{
    extern __shared__ char smem[];
    const uint32_t sb = smem_u32(smem);
    const int tid = threadIdx.x, wid = tid >> 5, lane = tid & 31;
    const int row0 = blockIdx.x * BM;
    const int nt = C >> 7;

    if (tid == 0) {
#pragma unroll
        for (int s = 0; s < 4; s++) {
            mbar_init(sb + MB_OFF + s * 8, 32);       // full: 32 producer-lane arrives
            mbar_init(sb + MB_OFF + 32 + s * 8, 4);   // empty: 4 math-warp arrives
        }
    }

    // Resident A copy (frag-packed, contiguous): 2 x 64KB via cp.async.
    {
        const float* srch = g_xh + (size_t)blockIdx.x * 16384;
        const float* srcl = g_xl + (size_t)blockIdx.x * 16384;
        for (int i = tid; i < 4096; i += 256) {
            cp16(sb + AH_OFF + i * 16, srch + i * 4);
            cp16(sb + AL_OFF + i * 16, srcl + i * 4);
        }
        cp_commit(); cp_wait0();
    }
    __syncthreads();

    if (wid < 4) {
        // ---------------- math warps ----------------
        const int wm = wid >> 1, wn = wid & 1;
        float acc[4][8][4];
#pragma unroll
        for (int a = 0; a < 4; a++)
#pragma unroll
            for (int b = 0; b < 8; b++)
#pragma unroll
                for (int r = 0; r < 4; r++) acc[a][b][r] = 0.0f;
        float bestv[8]; int besti[8];
#pragma unroll
        for (int s = 0; s < 8; s++) { bestv[s] = CUDART_INF_F; besti[s] = 0; }
        uint32_t pf[4] = {0, 0, 0, 0};

        for (int t = 0; t < nt; t++) {
            // prefetch cnorm for this coltile (used ~6k cyc later)
            float cn[16];
            const int cb = t * 128 + wn * 64 + (lane & 3) * 2;
#pragma unroll
            for (int na = 0; na < 8; na++) {
                cn[na * 2]     = __ldg(&g_cnorm[cb + na * 8]);
                cn[na * 2 + 1] = __ldg(&g_cnorm[cb + na * 8 + 1]);
            }

#pragma unroll 1
            for (int kc = 0; kc < 4; kc++) {
                const int sch = (kc * 2) & 3, scl = sch + 1;
                const uint32_t bch = (uint32_t)(SLOT_OFF + (sch << 14));
                const uint32_t bcl = (uint32_t)(SLOT_OFF + (scl << 14));

                mbar_wait(sb + MB_OFF + sch * 8, pf[sch]); pf[sch] ^= 1;
#pragma unroll
                for (int pass = 0; pass < 2; pass++) {          // hh then lh (both use ch chunk)
                    const uint32_t abase = pass ? AL_OFF : AH_OFF;
#pragma unroll
                    for (int ks = 0; ks < 4; ks++) {
                        const int ksg = kc * 4 + ks;
                        uint4 af[4]; uint2 bf[8];
#pragma unroll
                        for (int ma = 0; ma < 4; ma++)
                            af[ma] = *reinterpret_cast<const uint4*>(
                                smem + abase + (((ksg * 8) + wm * 4 + ma) * 32 + lane) * 16);
#pragma unroll
                        for (int na = 0; na < 8; na++)
                            bf[na] = *reinterpret_cast<const uint2*>(
                                smem + bch + (((ks * 16) + wn * 8 + na) * 32 + lane) * 8);
#pragma unroll
                        for (int ma = 0; ma < 4; ma++)
#pragma unroll
                            for (int na = 0; na < 8; na++)
                                mma8(acc[ma][na], af[ma], bf[na]);
                    }
                }
                if (lane == 0) mbar_arrive(sb + MB_OFF + 32 + sch * 8);

                mbar_wait(sb + MB_OFF + scl * 8, pf[scl]); pf[scl] ^= 1;
#pragma unroll
                for (int ks = 0; ks < 4; ks++) {                // hl (xh * cl)
                    const int ksg = kc * 4 + ks;
                    uint4 af[4]; uint2 bf[8];
#pragma unroll
                    for (int ma = 0; ma < 4; ma++)
                        af[ma] = *reinterpret_cast<const uint4*>(
                            smem + AH_OFF + (((ksg * 8) + wm * 4 + ma) * 32 + lane) * 16);
#pragma unroll
                    for (int na = 0; na < 8; na++)
                        bf[na] = *reinterpret_cast<const uint2*>(
                            smem + bcl + (((ks * 16) + wn * 8 + na) * 32 + lane) * 8);
#pragma unroll
                    for (int ma = 0; ma < 4; ma++)
#pragma unroll
                        for (int na = 0; na < 8; na++)
                            mma8(acc[ma][na], af[ma], bf[na]);
                }
                if (lane == 0) mbar_arrive(sb + MB_OFF + 32 + scl * 8);
            }

            // epilogue: key = ||c||^2 - 2 x.c, online argmin, reset accs
#pragma unroll
            for (int ma = 0; ma < 4; ma++) {
                const int slo = ma * 2, shi = ma * 2 + 1;
#pragma unroll
                for (int na = 0; na < 8; na++) {
                    const int c0 = t * 128 + wn * 64 + na * 8 + (lane & 3) * 2;
                    float k00 = fmaf(-2.0f, acc[ma][na][0], cn[na * 2]);
                    float k01 = fmaf(-2.0f, acc[ma][na][1], cn[na * 2 + 1]);
                    float k10 = fmaf(-2.0f, acc[ma][na][2], cn[na * 2]);
                    float k11 = fmaf(-2.0f, acc[ma][na][3], cn[na * 2 + 1]);
                    if (k00 < bestv[slo]) { bestv[slo] = k00; besti[slo] = c0; }
                    if (k01 < bestv[slo]) { bestv[slo] = k01; besti[slo] = c0 + 1; }
                    if (k10 < bestv[shi]) { bestv[shi] = k10; besti[shi] = c0; }
                    if (k11 < bestv[shi]) { bestv[shi] = k11; besti[shi] = c0 + 1; }
                    acc[ma][na][0] = 0.0f; acc[ma][na][1] = 0.0f;
                    acc[ma][na][2] = 0.0f; acc[ma][na][3] = 0.0f;
                }
            }
        }

        // reduce across the 4 lanes sharing each row (lane&3 group); first-index ties
#pragma unroll
        for (int s = 0; s < 8; s++) {
            float v = bestv[s]; int bi = besti[s];
#pragma unroll
            for (int o = 1; o <= 2; o <<= 1) {
                float vo = __shfl_xor_sync(0xffffffffu, v, o);
                int   io = __shfl_xor_sync(0xffffffffu, bi, o);
                if (vo < v || (vo == v && io < bi)) { v = vo; bi = io; }
            }
            if ((lane & 3) == 0) {
                int row = wm * 64 + (s >> 1) * 16 + (s & 1) * 8 + (lane >> 2);
                reinterpret_cast<float*>(smem + BV_OFF)[wn * 128 + row] = v;
                reinterpret_cast<int*>(smem + BI_OFF)[wn * 128 + row]   = bi;
            }
        }
    } else {
        // ---------------- producer warps (one slot each) ----------------
        const int pw = wid - 4;
        const uint32_t dst = sb + SLOT_OFF + (pw << 14);
        uint32_t pe = 0;
        const int nchunks = nt * 8;
        for (int c = pw; c < nchunks; c += 4) {
            if (c >= 4) { mbar_wait(sb + MB_OFF + 32 + pw * 8, pe); pe ^= 1; }
            const int t = c >> 3, r = c & 7, kc = r >> 1;
            const float* src = ((r & 1) ? g_cl : g_ch) + ((size_t)(t * 4 + kc) << 12);
#pragma unroll
            for (int i = 0; i < 32; i++)
                cp16(dst + (uint32_t)((i * 32 + lane) << 4), src + ((i * 32 + lane) << 2));
            cp_commit(); cp_wait0();
            mbar_arrive(sb + MB_OFF + pw * 8);   // all 32 lanes -> count 32
        }
    }

    __syncthreads();

    // combine warp-col halves, gather codes, loss (all 256 threads, 16 per row)
    float thr_loss = 0.0f;
    {
        const int txg = tid & 15, grp = tid >> 4;
        const float* bv = reinterpret_cast<const float*>(smem + BV_OFF);
        const int*   bixs = reinterpret_cast<const int*>(smem + BI_OFF);
        for (int row = grp; row < BM; row += 16) {
            float v0 = bv[row], v1 = bv[128 + row];
            int i0 = bixs[row], i1 = bixs[128 + row];
            int bi = (v1 < v0 || (v1 == v0 && i1 < i0)) ? i1 : i0;
            int grow = row0 + row;
            if (txg == 0 && write_idx) out_idx[grow] = (float)bi;
            const float4* cq = reinterpret_cast<const float4*>(codes + (size_t)bi * DDIM + txg * 8);
            float4 q0 = cq[0], q1 = cq[1];
            float4* od = reinterpret_cast<float4*>(out_q + (size_t)grow * DDIM + txg * 8);
            od[0] = q0; od[1] = q1;
            const float4* xp = reinterpret_cast<const float4*>(x + (size_t)grow * DDIM + txg * 8);
            float4 x0 = xp[0], x1 = xp[1];
            float d;
            d = x0.x - q0.x; thr_loss = fmaf(d, d, thr_loss);
            d = x0.y - q0.y; thr_loss = fmaf(d, d, thr_loss);
            d = x0.z - q0.z; thr_loss = fmaf(d, d, thr_loss);
            d = x0.w - q0.w; thr_loss = fmaf(d, d, thr_loss);
            d = x1.x - q1.x; thr_loss = fmaf(d, d, thr_loss);
            d = x1.y - q1.y; thr_loss = fmaf(d, d, thr_loss);
            d = x1.z - q1.z; thr_loss = fmaf(d, d, thr_loss);
            d = x1.w - q1.w; thr_loss = fmaf(d, d, thr_loss);
        }
    }
#pragma unroll
    for (int o = 16; o; o >>= 1) thr_loss += __shfl_xor_sync(0xffffffffu, thr_loss, o);
    if (lane == 0) reinterpret_cast<float*>(smem + RED_OFF)[wid] = thr_loss;
    __syncthreads();
    if (tid == 0) {
        float sum = 0.0f;
#pragma unroll
        for (int w = 0; w < 8; w++) sum += reinterpret_cast<const float*>(smem + RED_OFF)[w];
        g_block_loss[blockIdx.x] = sum;
    }
}

// ---- deterministic fixed-order final loss reduction ----
__global__ void finalize_kernel(float* __restrict__ out_loss, int nblocks, float invB)
{
    __shared__ float red[256];
    float s = 0.0f;
    for (int i = threadIdx.x; i < nblocks; i += 256) s += g_block_loss[i];
    red[threadIdx.x] = s;
    __syncthreads();
    for (int o = 128; o; o >>= 1) {
        if (threadIdx.x < o) red[threadIdx.x] += red[threadIdx.x + o];
        __syncthreads();
    }
    if (threadIdx.x == 0) *out_loss = 1.25f * red[0] * invB;  // (1 + BETA) * mean ||x-q||^2
}

extern "C" void kernel_launch(void* const* d_in, const int* in_sizes, int n_in,
                              void* d_out, int out_size)
{
    const float* x     = (const float*)d_in[0];
    const float* codes = (const float*)d_in[1];
    const int B = in_sizes[0] / DDIM;
    const int C = in_sizes[1] / DDIM;

    float* out      = (float*)d_out;
    float* out_q    = out;
    float* out_idx  = out + (size_t)B * DDIM;
    float* out_loss = out + (size_t)B * DDIM + B;

    const long long need_idx  = (long long)B * DDIM + B;
    const long long need_loss = need_idx + 1;
    const int write_idx  = ((long long)out_size >= need_idx)  ? 1 : 0;
    const int write_loss = ((long long)out_size >= need_loss) ? 1 : 0;

    const int n4x = B * DDIM / 4, n4c = C * DDIM / 4;
    split_x<<<(n4x + 255) / 256, 256>>>(x, n4x);
    split_c<<<(n4c + 255) / 256, 256>>>(codes, n4c);
    cnorm_kernel<<<(C + 7) / 8, 256>>>(codes, C);

    (void)cudaFuncSetAttribute(vq_mma, cudaFuncAttributeMaxDynamicSharedMemorySize, SMEM_MAIN);
    vq_mma<<<B / BM, 256, SMEM_MAIN>>>(x, codes, out_q, out_idx, C, write_idx);

    if (write_loss)
        finalize_kernel<<<1, 256>>>(out_loss, B / BM, 1.0f / (float)B);
}

// round 5
// speedup vs baseline: 1.8423x; 1.0828x over previous
#include <cuda_runtime.h>
#include <math_constants.h>
#include <cstdint>

// Quantizer_33036888441545 — VQ argmin + gather + loss via legacy mma.sync tf32 (3xTF32 split).
// R5: 8 math warps (2x4 grid, 64x32 tiles) + 4 producer warps.

#define DDIM 128
#define BM   128
#define MAXB 65536
#define MAXC 4096

__device__ float g_xh[MAXB * DDIM];
__device__ float g_xl[MAXB * DDIM];
__device__ float g_ch[MAXC * DDIM];
__device__ float g_cl[MAXC * DDIM];
__device__ float g_cnorm[MAXC];
__device__ float g_block_loss[MAXB / BM];

// ---- smem map (bytes) ----
#define AH_OFF   0         // 64KB  A-hi frags, resident
#define AL_OFF   65536     // 64KB  A-lo frags, resident
#define SLOT_OFF 131072    // 4 x 16KB B-chunk ring
#define MB_OFF   196608    // full[4] @ +0, empty[4] @ +32
#define BV_OFF   196672    // float bestv[4][128]
#define BI_OFF   198720    // int   besti[4][128]
#define RED_OFF  200768    // float red[12]
#define SMEM_MAIN 200832

// ============ helpers ============
__device__ __forceinline__ uint32_t smem_u32(const void* p) {
    uint32_t a;
    asm("{ .reg .u64 t; cvta.to.shared.u64 t, %1; cvt.u32.u64 %0, t; }" : "=r"(a) : "l"(p));
    return a;
}
__device__ __forceinline__ void mbar_init(uint32_t a, uint32_t cnt) {
    asm volatile("mbarrier.init.shared.b64 [%0], %1;" :: "r"(a), "r"(cnt) : "memory");
}
__device__ __forceinline__ void mbar_arrive(uint32_t a) {
    asm volatile("mbarrier.arrive.shared.b64 _, [%0];" :: "r"(a) : "memory");
}
__device__ __forceinline__ void mbar_wait(uint32_t a, uint32_t parity) {
    uint32_t done = 0;
    while (!done) {
        asm volatile(
            "{ .reg .pred p; mbarrier.try_wait.parity.acquire.cta.shared::cta.b64 p, [%1], %2, 0x989680; selp.b32 %0,1,0,p; }"
            : "=r"(done) : "r"(a), "r"(parity) : "memory");
    }
}
__device__ __forceinline__ void cp16(uint32_t dst, const float* src) {
    asm volatile("cp.async.cg.shared.global [%0], [%1], 16;" :: "r"(dst), "l"(src) : "memory");
}
__device__ __forceinline__ void cp_commit() { asm volatile("cp.async.commit_group;" ::: "memory"); }
__device__ __forceinline__ void cp_wait0()  { asm volatile("cp.async.wait_group 0;"  ::: "memory"); }

__device__ __forceinline__ void mma8(float* c, const uint4& a, const uint2& b) {
    asm volatile(
        "mma.sync.aligned.m16n8k8.row.col.f32.tf32.tf32.f32 "
        "{%0,%1,%2,%3}, {%4,%5,%6,%7}, {%8,%9}, {%0,%1,%2,%3};"
        : "+f"(c[0]), "+f"(c[1]), "+f"(c[2]), "+f"(c[3])
        : "r"(a.x), "r"(a.y), "r"(a.z), "r"(a.w), "r"(b.x), "r"(b.y));
}

// ============ split kernels (unchanged from R4, verified) ============
__global__ void split_x(const float* __restrict__ x, int n4)
{
    int i = blockIdx.x * 256 + threadIdx.x;
    if (i >= n4) return;
    int m = i >> 5, q = i & 31, k0 = q * 4;
    float4 v = reinterpret_cast<const float4*>(x)[i];
    float vv[4] = {v.x, v.y, v.z, v.w};
    int blk = m >> 7, mloc = m & 127, ma = mloc >> 4, mrow = mloc & 15;
    int lane_m = (mrow & 7) * 4, regm = mrow >> 3;
#pragma unroll
    for (int j = 0; j < 4; j++) {
        int k = k0 + j;
        int ks = k >> 3, kk = k & 7;
        int lane = lane_m + (kk & 3);
        int reg  = ((kk >> 2) << 1) | regm;
        size_t idx = ((((size_t)blk * 16 + ks) * 8 + ma) * 32 + lane) * 4 + reg;
        uint32_t hb; asm("cvt.rna.tf32.f32 %0, %1;" : "=r"(hb) : "f"(vv[j]));
        float h = __uint_as_float(hb);
        float l = vv[j] - h;
        uint32_t lb; asm("cvt.rna.tf32.f32 %0, %1;" : "=r"(lb) : "f"(l));
        g_xh[idx] = h;
        g_xl[idx] = __uint_as_float(lb);
    }
}

__global__ void split_c(const float* __restrict__ codes, int n4)
{
    int i = blockIdx.x * 256 + threadIdx.x;
    if (i >= n4) return;
    int n = i >> 5, q = i & 31, k0 = q * 4;
    float4 v = reinterpret_cast<const float4*>(codes)[i];
    float vv[4] = {v.x, v.y, v.z, v.w};
    int t = n >> 7, nloc = n & 127, na = nloc >> 3;
    int lane_n = (nloc & 7) * 4;
#pragma unroll
    for (int j = 0; j < 4; j++) {
        int k = k0 + j;
        int kc = k >> 5, ks = (k >> 3) & 3;
        int lane = lane_n + (k & 3);
        int reg  = (k >> 2) & 1;
        size_t idx = ((((size_t)(t * 4 + kc) * 4 + ks) * 16 + na) * 32 + lane) * 2 + reg;
        uint32_t hb; asm("cvt.rna.tf32.f32 %0, %1;" : "=r"(hb) : "f"(vv[j]));
        float h = __uint_as_float(hb);
        float l = vv[j] - h;
        uint32_t lb; asm("cvt.rna.tf32.f32 %0, %1;" : "=r"(lb) : "f"(l));
        g_ch[idx] = h;
        g_cl[idx] = __uint_as_float(lb);
    }
}

__global__ void cnorm_kernel(const float* __restrict__ codes, int C)
{
    int j = blockIdx.x * 8 + (threadIdx.x >> 5);
    int lane = threadIdx.x & 31;
    if (j >= C) return;
    float4 v = reinterpret_cast<const float4*>(codes + (size_t)j * DDIM)[lane];
    float s = v.x * v.x + v.y * v.y + v.z * v.z + v.w * v.w;
#pragma unroll
    for (int o = 16; o; o >>= 1) s += __shfl_xor_sync(0xffffffffu, s, o);
    if (lane == 0) g_cnorm[j] = s;
}

// ============ main kernel ============
// 12 warps: 0-7 math (2x4 warp grid, 64x32 tiles), 8-11 producers (one ring slot each).
__global__ __launch_bounds__(384, 1)
void vq_mma(const float* __restrict__ x, const float* __restrict__ codes,
            float* __restrict__ out_q, float* __restrict__ out_idx,
            int C, int write_idx)
{
    extern __shared__ char smem[];
    const uint32_t sb = smem_u32(smem);
    const int tid = threadIdx.x, wid = tid >> 5, lane = tid & 31;
    const int row0 = blockIdx.x * BM;
    const int nt = C >> 7;

    if (tid == 0) {
#pragma unroll
        for (int s = 0; s < 4; s++) {
            mbar_init(sb + MB_OFF + s * 8, 32);       // full: 32 producer-lane arrives
            mbar_init(sb + MB_OFF + 32 + s * 8, 8);   // empty: 8 math-warp arrives
        }
    }

    // Resident A copy (frag-packed, contiguous): 2 x 64KB via cp.async.
    {
        const float* srch = g_xh + (size_t)blockIdx.x * 16384;
        const float* srcl = g_xl + (size_t)blockIdx.x * 16384;
        for (int i = tid; i < 4096; i += 384) {
            cp16(sb + AH_OFF + i * 16, srch + i * 4);
            cp16(sb + AL_OFF + i * 16, srcl + i * 4);
        }
        cp_commit(); cp_wait0();
    }
    __syncthreads();

    if (wid < 8) {
        // ---------------- math warps: 64 rows (wm) x 32 cols (wn) ----------------
        const int wm = wid >> 2, wn = wid & 3;
        float acc[4][4][4];
#pragma unroll
        for (int a = 0; a < 4; a++)
#pragma unroll
            for (int b = 0; b < 4; b++)
#pragma unroll
                for (int r = 0; r < 4; r++) acc[a][b][r] = 0.0f;
        float bestv[8]; int besti[8];
#pragma unroll
        for (int s = 0; s < 8; s++) { bestv[s] = CUDART_INF_F; besti[s] = 0; }
        uint32_t pf[4] = {0, 0, 0, 0};

        for (int t = 0; t < nt; t++) {
            float cn[8];
            const int cb = t * 128 + wn * 32 + (lane & 3) * 2;
#pragma unroll
            for (int na = 0; na < 4; na++) {
                cn[na * 2]     = __ldg(&g_cnorm[cb + na * 8]);
                cn[na * 2 + 1] = __ldg(&g_cnorm[cb + na * 8 + 1]);
            }

#pragma unroll 1
            for (int kc = 0; kc < 4; kc++) {
                const int sch = (kc * 2) & 3, scl = sch + 1;
                const uint32_t bch = (uint32_t)(SLOT_OFF + (sch << 14));
                const uint32_t bcl = (uint32_t)(SLOT_OFF + (scl << 14));

                mbar_wait(sb + MB_OFF + sch * 8, pf[sch]); pf[sch] ^= 1;
#pragma unroll
                for (int pass = 0; pass < 2; pass++) {          // hh then lh (both use ch chunk)
                    const uint32_t abase = pass ? AL_OFF : AH_OFF;
#pragma unroll
                    for (int ks = 0; ks < 4; ks++) {
                        const int ksg = kc * 4 + ks;
                        uint4 af[4]; uint2 bf[4];
#pragma unroll
                        for (int ma = 0; ma < 4; ma++)
                            af[ma] = *reinterpret_cast<const uint4*>(
                                smem + abase + (((ksg * 8) + wm * 4 + ma) * 32 + lane) * 16);
#pragma unroll
                        for (int na = 0; na < 4; na++)
                            bf[na] = *reinterpret_cast<const uint2*>(
                                smem + bch + (((ks * 16) + wn * 4 + na) * 32 + lane) * 8);
#pragma unroll
                        for (int ma = 0; ma < 4; ma++)
#pragma unroll
                            for (int na = 0; na < 4; na++)
                                mma8(acc[ma][na], af[ma], bf[na]);
                    }
                }
                if (lane == 0) mbar_arrive(sb + MB_OFF + 32 + sch * 8);

                mbar_wait(sb + MB_OFF + scl * 8, pf[scl]); pf[scl] ^= 1;
#pragma unroll
                for (int ks = 0; ks < 4; ks++) {                // hl (xh * cl)
                    const int ksg = kc * 4 + ks;
                    uint4 af[4]; uint2 bf[4];
#pragma unroll
                    for (int ma = 0; ma < 4; ma++)
                        af[ma] = *reinterpret_cast<const uint4*>(
                            smem + AH_OFF + (((ksg * 8) + wm * 4 + ma) * 32 + lane) * 16);
#pragma unroll
                    for (int na = 0; na < 4; na++)
                        bf[na] = *reinterpret_cast<const uint2*>(
                            smem + bcl + (((ks * 16) + wn * 4 + na) * 32 + lane) * 8);
#pragma unroll
                    for (int ma = 0; ma < 4; ma++)
#pragma unroll
                        for (int na = 0; na < 4; na++)
                            mma8(acc[ma][na], af[ma], bf[na]);
                }
                if (lane == 0) mbar_arrive(sb + MB_OFF + 32 + scl * 8);
            }

            // epilogue: key = ||c||^2 - 2 x.c, online argmin, reset accs
#pragma unroll
            for (int ma = 0; ma < 4; ma++) {
                const int slo = ma * 2, shi = ma * 2 + 1;
#pragma unroll
                for (int na = 0; na < 4; na++) {
                    const int c0 = t * 128 + wn * 32 + na * 8 + (lane & 3) * 2;
                    float k00 = fmaf(-2.0f, acc[ma][na][0], cn[na * 2]);
                    float k01 = fmaf(-2.0f, acc[ma][na][1], cn[na * 2 + 1]);
                    float k10 = fmaf(-2.0f, acc[ma][na][2], cn[na * 2]);
                    float k11 = fmaf(-2.0f, acc[ma][na][3], cn[na * 2 + 1]);
                    if (k00 < bestv[slo]) { bestv[slo] = k00; besti[slo] = c0; }
                    if (k01 < bestv[slo]) { bestv[slo] = k01; besti[slo] = c0 + 1; }
                    if (k10 < bestv[shi]) { bestv[shi] = k10; besti[shi] = c0; }
                    if (k11 < bestv[shi]) { bestv[shi] = k11; besti[shi] = c0 + 1; }
                    acc[ma][na][0] = 0.0f; acc[ma][na][1] = 0.0f;
                    acc[ma][na][2] = 0.0f; acc[ma][na][3] = 0.0f;
                }
            }
        }

        // reduce across the 4 lanes sharing each row; first-index ties
#pragma unroll
        for (int s = 0; s < 8; s++) {
            float v = bestv[s]; int bi = besti[s];
#pragma unroll
            for (int o = 1; o <= 2; o <<= 1) {
                float vo = __shfl_xor_sync(0xffffffffu, v, o);
                int   io = __shfl_xor_sync(0xffffffffu, bi, o);
                if (vo < v || (vo == v && io < bi)) { v = vo; bi = io; }
            }
            if ((lane & 3) == 0) {
                int row = wm * 64 + (s >> 1) * 16 + (s & 1) * 8 + (lane >> 2);
                reinterpret_cast<float*>(smem + BV_OFF)[wn * 128 + row] = v;
                reinterpret_cast<int*>(smem + BI_OFF)[wn * 128 + row]   = bi;
            }
        }
    } else {
        // ---------------- producer warps (one slot each) ----------------
        const int pw = wid - 8;
        const uint32_t dst = sb + SLOT_OFF + (pw << 14);
        uint32_t pe = 0;
        const int nchunks = nt * 8;
        for (int c = pw; c < nchunks; c += 4) {
            if (c >= 4) { mbar_wait(sb + MB_OFF + 32 + pw * 8, pe); pe ^= 1; }
            const int t = c >> 3, r = c & 7, kc = r >> 1;
            const float* src = ((r & 1) ? g_cl : g_ch) + ((size_t)(t * 4 + kc) << 12);
#pragma unroll
            for (int i = 0; i < 32; i++)
                cp16(dst + (uint32_t)((i * 32 + lane) << 4), src + ((i * 32 + lane) << 2));
            cp_commit(); cp_wait0();
            mbar_arrive(sb + MB_OFF + pw * 8);   // all 32 lanes -> count 32
        }
    }

    __syncthreads();

    // combine 4 warp-col stripes per row, gather codes, loss (384 threads, 16 per row)
    float thr_loss = 0.0f;
    {
        const int txg = tid & 15, grp = tid >> 4;
        const float* bv = reinterpret_cast<const float*>(smem + BV_OFF);
        const int*   bixs = reinterpret_cast<const int*>(smem + BI_OFF);
        for (int row = grp; row < BM; row += 24) {
            float v = bv[row]; int bi = bixs[row];
#pragma unroll
            for (int wnn = 1; wnn < 4; wnn++) {
                float vo = bv[wnn * 128 + row];
                int   io = bixs[wnn * 128 + row];
                if (vo < v || (vo == v && io < bi)) { v = vo; bi = io; }
            }
            int grow = row0 + row;
            if (txg == 0 && write_idx) out_idx[grow] = (float)bi;
            const float4* cq = reinterpret_cast<const float4*>(codes + (size_t)bi * DDIM + txg * 8);
            float4 q0 = cq[0], q1 = cq[1];
            float4* od = reinterpret_cast<float4*>(out_q + (size_t)grow * DDIM + txg * 8);
            od[0] = q0; od[1] = q1;
            const float4* xp = reinterpret_cast<const float4*>(x + (size_t)grow * DDIM + txg * 8);
            float4 x0 = xp[0], x1 = xp[1];
            float d;
            d = x0.x - q0.x; thr_loss = fmaf(d, d, thr_loss);
            d = x0.y - q0.y; thr_loss = fmaf(d, d, thr_loss);
            d = x0.z - q0.z; thr_loss = fmaf(d, d, thr_loss);
            d = x0.w - q0.w; thr_loss = fmaf(d, d, thr_loss);
            d = x1.x - q1.x; thr_loss = fmaf(d, d, thr_loss);
            d = x1.y - q1.y; thr_loss = fmaf(d, d, thr_loss);
            d = x1.z - q1.z; thr_loss = fmaf(d, d, thr_loss);
            d = x1.w - q1.w; thr_loss = fmaf(d, d, thr_loss);
        }
    }
#pragma unroll
    for (int o = 16; o; o >>= 1) thr_loss += __shfl_xor_sync(0xffffffffu, thr_loss, o);
    if (lane == 0) reinterpret_cast<float*>(smem + RED_OFF)[wid] = thr_loss;
    __syncthreads();
    if (tid == 0) {
        float sum = 0.0f;
#pragma unroll
        for (int w = 0; w < 12; w++) sum += reinterpret_cast<const float*>(smem + RED_OFF)[w];
        g_block_loss[blockIdx.x] = sum;
    }
}

// ---- deterministic fixed-order final loss reduction ----
__global__ void finalize_kernel(float* __restrict__ out_loss, int nblocks, float invB)
{
    __shared__ float red[256];
    float s = 0.0f;
    for (int i = threadIdx.x; i < nblocks; i += 256) s += g_block_loss[i];
    red[threadIdx.x] = s;
    __syncthreads();
    for (int o = 128; o; o >>= 1) {
        if (threadIdx.x < o) red[threadIdx.x] += red[threadIdx.x + o];
        __syncthreads();
    }
    if (threadIdx.x == 0) *out_loss = 1.25f * red[0] * invB;  // (1 + BETA) * mean ||x-q||^2
}

extern "C" void kernel_launch(void* const* d_in, const int* in_sizes, int n_in,
                              void* d_out, int out_size)
{
    const float* x     = (const float*)d_in[0];
    const float* codes = (const float*)d_in[1];
    const int B = in_sizes[0] / DDIM;
    const int C = in_sizes[1] / DDIM;

    float* out      = (float*)d_out;
    float* out_q    = out;
    float* out_idx  = out + (size_t)B * DDIM;
    float* out_loss = out + (size_t)B * DDIM + B;

    const long long need_idx  = (long long)B * DDIM + B;
    const long long need_loss = need_idx + 1;
    const int write_idx  = ((long long)out_size >= need_idx)  ? 1 : 0;
    const int write_loss = ((long long)out_size >= need_loss) ? 1 : 0;

    const int n4x = B * DDIM / 4, n4c = C * DDIM / 4;
    split_x<<<(n4x + 255) / 256, 256>>>(x, n4x);
    split_c<<<(n4c + 255) / 256, 256>>>(codes, n4c);
    cnorm_kernel<<<(C + 7) / 8, 256>>>(codes, C);

    (void)cudaFuncSetAttribute(vq_mma, cudaFuncAttributeMaxDynamicSharedMemorySize, SMEM_MAIN);
    vq_mma<<<B / BM, 384, SMEM_MAIN>>>(x, codes, out_q, out_idx, C, write_idx);

    if (write_loss)
        finalize_kernel<<<1, 256>>>(out_loss, B / BM, 1.0f / (float)B);
}

// round 6
// speedup vs baseline: 1.9625x; 1.0653x over previous
#include <cuda_runtime.h>
#include <math_constants.h>
#include <cstdint>

// Quantizer_33036888441545 — VQ argmin + gather + loss via mma.sync tf32 (3xTF32 split).
// R6: BM=64, 192 threads (4 math warps 32x64 + 2 producers), occupancy 2.

#define DDIM 128
#define BM   64
#define TPB  192
#define MAXB 65536
#define MAXC 4096

__device__ float g_xh[MAXB * DDIM];
__device__ float g_xl[MAXB * DDIM];
__device__ float g_ch[MAXC * DDIM];
__device__ float g_cl[MAXC * DDIM];
__device__ float g_cnorm[MAXC];
__device__ float g_block_loss[MAXB / BM];

// ---- smem map (bytes) ----
#define AH_OFF   0          // 32KB A-hi frags (64 rows), resident
#define AL_OFF   32768      // 32KB A-lo frags, resident
#define SLOT_OFF 65536      // 2 x 16KB B ring (slot0 = ch, slot1 = cl)
#define MB_OFF   98304      // full[2] @ +0,+8 ; empty[2] @ +16,+24
#define BV_OFF   98336      // float bv[2][64]
#define BI_OFF   98848      // int   bi[2][64]
#define RED_OFF  99360      // float red[6]
#define SMEM_MAIN 99392

// ============ helpers ============
__device__ __forceinline__ uint32_t smem_u32(const void* p) {
    uint32_t a;
    asm("{ .reg .u64 t; cvta.to.shared.u64 t, %1; cvt.u32.u64 %0, t; }" : "=r"(a) : "l"(p));
    return a;
}
__device__ __forceinline__ void mbar_init(uint32_t a, uint32_t cnt) {
    asm volatile("mbarrier.init.shared.b64 [%0], %1;" :: "r"(a), "r"(cnt) : "memory");
}
__device__ __forceinline__ void mbar_arrive(uint32_t a) {
    asm volatile("mbarrier.arrive.shared.b64 _, [%0];" :: "r"(a) : "memory");
}
__device__ __forceinline__ void mbar_wait(uint32_t a, uint32_t parity) {
    uint32_t done = 0;
    while (!done) {
        asm volatile(
            "{ .reg .pred p; mbarrier.try_wait.parity.acquire.cta.shared::cta.b64 p, [%1], %2, 0x989680; selp.b32 %0,1,0,p; }"
            : "=r"(done) : "r"(a), "r"(parity) : "memory");
    }
}
__device__ __forceinline__ void cp16(uint32_t dst, const float* src) {
    asm volatile("cp.async.cg.shared.global [%0], [%1], 16;" :: "r"(dst), "l"(src) : "memory");
}
__device__ __forceinline__ void cp_commit() { asm volatile("cp.async.commit_group;" ::: "memory"); }
__device__ __forceinline__ void cp_wait0()  { asm volatile("cp.async.wait_group 0;"  ::: "memory"); }

__device__ __forceinline__ void mma8(float* c, const uint4& a, const uint2& b) {
    asm volatile(
        "mma.sync.aligned.m16n8k8.row.col.f32.tf32.tf32.f32 "
        "{%0,%1,%2,%3}, {%4,%5,%6,%7}, {%8,%9}, {%0,%1,%2,%3};"
        : "+f"(c[0]), "+f"(c[1]), "+f"(c[2]), "+f"(c[3])
        : "r"(a.x), "r"(a.y), "r"(a.z), "r"(a.w), "r"(b.x), "r"(b.y));
}

// ============ split kernels ============
// A frag layout (per 64-row block): [blk][ks(16)][ma(4)][lane(32)][reg(4)]  (32KB/blk/split)
__global__ void split_x(const float* __restrict__ x, int n4)
{
    int i = blockIdx.x * 256 + threadIdx.x;
    if (i >= n4) return;
    int m = i >> 5, q = i & 31, k0 = q * 4;
    float4 v = reinterpret_cast<const float4*>(x)[i];
    float vv[4] = {v.x, v.y, v.z, v.w};
    int blk = m >> 6, mloc = m & 63, ma = mloc >> 4, mrow = mloc & 15;
    int lane_m = (mrow & 7) * 4, regm = mrow >> 3;
#pragma unroll
    for (int j = 0; j < 4; j++) {
        int k = k0 + j;
        int ks = k >> 3, kk = k & 7;
        int lane = lane_m + (kk & 3);
        int reg  = ((kk >> 2) << 1) | regm;
        size_t idx = ((((size_t)blk * 16 + ks) * 4 + ma) * 32 + lane) * 4 + reg;
        uint32_t hb; asm("cvt.rna.tf32.f32 %0, %1;" : "=r"(hb) : "f"(vv[j]));
        float h = __uint_as_float(hb);
        float l = vv[j] - h;
        uint32_t lb; asm("cvt.rna.tf32.f32 %0, %1;" : "=r"(lb) : "f"(l));
        g_xh[idx] = h;
        g_xl[idx] = __uint_as_float(lb);
    }
}

// B frag layout: [t][kc(4)][ks(4)][na(16)][lane(32)][reg(2)]  (16KB per (t,kc) chunk)  (unchanged)
__global__ void split_c(const float* __restrict__ codes, int n4)
{
    int i = blockIdx.x * 256 + threadIdx.x;
    if (i >= n4) return;
    int n = i >> 5, q = i & 31, k0 = q * 4;
    float4 v = reinterpret_cast<const float4*>(codes)[i];
    float vv[4] = {v.x, v.y, v.z, v.w};
    int t = n >> 7, nloc = n & 127, na = nloc >> 3;
    int lane_n = (nloc & 7) * 4;
#pragma unroll
    for (int j = 0; j < 4; j++) {
        int k = k0 + j;
        int kc = k >> 5, ks = (k >> 3) & 3;
        int lane = lane_n + (k & 3);
        int reg  = (k >> 2) & 1;
        size_t idx = ((((size_t)(t * 4 + kc) * 4 + ks) * 16 + na) * 32 + lane) * 2 + reg;
        uint32_t hb; asm("cvt.rna.tf32.f32 %0, %1;" : "=r"(hb) : "f"(vv[j]));
        float h = __uint_as_float(hb);
        float l = vv[j] - h;
        uint32_t lb; asm("cvt.rna.tf32.f32 %0, %1;" : "=r"(lb) : "f"(l));
        g_ch[idx] = h;
        g_cl[idx] = __uint_as_float(lb);
    }
}

__global__ void cnorm_kernel(const float* __restrict__ codes, int C)
{
    int j = blockIdx.x * 8 + (threadIdx.x >> 5);
    int lane = threadIdx.x & 31;
    if (j >= C) return;
    float4 v = reinterpret_cast<const float4*>(codes + (size_t)j * DDIM)[lane];
    float s = v.x * v.x + v.y * v.y + v.z * v.z + v.w * v.w;
#pragma unroll
    for (int o = 16; o; o >>= 1) s += __shfl_xor_sync(0xffffffffu, s, o);
    if (lane == 0) g_cnorm[j] = s;
}

// ============ main kernel ============
// 6 warps: 0-3 math (2x2 grid, 32x64 tiles), 4-5 producers (slot pw each).
__global__ __launch_bounds__(TPB, 2)
void vq_mma(const float* __restrict__ x, const float* __restrict__ codes,
            float* __restrict__ out_q, float* __restrict__ out_idx,
            int C, int write_idx)
{
    extern __shared__ char smem[];
    const uint32_t sb = smem_u32(smem);
    const int tid = threadIdx.x, wid = tid >> 5, lane = tid & 31;
    const int row0 = blockIdx.x * BM;
    const int nt = C >> 7;

    if (tid == 0) {
#pragma unroll
        for (int s = 0; s < 2; s++) {
            mbar_init(sb + MB_OFF + s * 8, 32);        // full: one producer warp (32 lanes)
            mbar_init(sb + MB_OFF + 16 + s * 8, 4);    // empty: 4 math warps
        }
    }

    // Resident A copy (frag-packed, contiguous): 2 x 32KB via cp.async.
    {
        const float* srch = g_xh + (size_t)blockIdx.x * 8192;
        const float* srcl = g_xl + (size_t)blockIdx.x * 8192;
        for (int i = tid; i < 2048; i += TPB) {
            cp16(sb + AH_OFF + i * 16, srch + i * 4);
            cp16(sb + AL_OFF + i * 16, srcl + i * 4);
        }
        cp_commit(); cp_wait0();
    }
    __syncthreads();

    if (wid < 4) {
        // ---------------- math warps: 32 rows (wm) x 64 cols (wn) ----------------
        const int wm = wid >> 1, wn = wid & 1;
        float acc[2][8][4];
#pragma unroll
        for (int a = 0; a < 2; a++)
#pragma unroll
            for (int b = 0; b < 8; b++)
#pragma unroll
                for (int r = 0; r < 4; r++) acc[a][b][r] = 0.0f;
        float bestv[4]; int besti[4];
#pragma unroll
        for (int s = 0; s < 4; s++) { bestv[s] = CUDART_INF_F; besti[s] = 0; }
        uint32_t pf0 = 0, pf1 = 0;

        for (int t = 0; t < nt; t++) {
            float cn[16];
            const int cb = t * 128 + wn * 64 + (lane & 3) * 2;
#pragma unroll
            for (int na = 0; na < 8; na++) {
                cn[na * 2]     = __ldg(&g_cnorm[cb + na * 8]);
                cn[na * 2 + 1] = __ldg(&g_cnorm[cb + na * 8 + 1]);
            }

#pragma unroll 1
            for (int kc = 0; kc < 4; kc++) {
                const uint32_t bch = (uint32_t)(SLOT_OFF);
                const uint32_t bcl = (uint32_t)(SLOT_OFF + 16384);

                mbar_wait(sb + MB_OFF + 0, pf0); pf0 ^= 1;
#pragma unroll
                for (int pass = 0; pass < 2; pass++) {          // hh then lh (both on ch)
                    const uint32_t abase = pass ? AL_OFF : AH_OFF;
#pragma unroll
                    for (int ks = 0; ks < 4; ks++) {
                        const int ksg = kc * 4 + ks;
                        uint4 af[2]; uint2 bf[8];
#pragma unroll
                        for (int ma = 0; ma < 2; ma++)
                            af[ma] = *reinterpret_cast<const uint4*>(
                                smem + abase + (((ksg * 4) + wm * 2 + ma) * 32 + lane) * 16);
#pragma unroll
                        for (int na = 0; na < 8; na++)
                            bf[na] = *reinterpret_cast<const uint2*>(
                                smem + bch + (((ks * 16) + wn * 8 + na) * 32 + lane) * 8);
#pragma unroll
                        for (int ma = 0; ma < 2; ma++)
#pragma unroll
                            for (int na = 0; na < 8; na++)
                                mma8(acc[ma][na], af[ma], bf[na]);
                    }
                }
                if (lane == 0) mbar_arrive(sb + MB_OFF + 16);

                mbar_wait(sb + MB_OFF + 8, pf1); pf1 ^= 1;
#pragma unroll
                for (int ks = 0; ks < 4; ks++) {                // hl (xh * cl)
                    const int ksg = kc * 4 + ks;
                    uint4 af[2]; uint2 bf[8];
#pragma unroll
                    for (int ma = 0; ma < 2; ma++)
                        af[ma] = *reinterpret_cast<const uint4*>(
                            smem + AH_OFF + (((ksg * 4) + wm * 2 + ma) * 32 + lane) * 16);
#pragma unroll
                    for (int na = 0; na < 8; na++)
                        bf[na] = *reinterpret_cast<const uint2*>(
                            smem + bcl + (((ks * 16) + wn * 8 + na) * 32 + lane) * 8);
#pragma unroll
                    for (int ma = 0; ma < 2; ma++)
#pragma unroll
                        for (int na = 0; na < 8; na++)
                            mma8(acc[ma][na], af[ma], bf[na]);
                }
                if (lane == 0) mbar_arrive(sb + MB_OFF + 24);
            }

            // epilogue: key = ||c||^2 - 2 x.c, online argmin, reset accs
#pragma unroll
            for (int ma = 0; ma < 2; ma++) {
                const int slo = ma * 2, shi = ma * 2 + 1;
#pragma unroll
                for (int na = 0; na < 8; na++) {
                    const int c0 = t * 128 + wn * 64 + na * 8 + (lane & 3) * 2;
                    float k00 = fmaf(-2.0f, acc[ma][na][0], cn[na * 2]);
                    float k01 = fmaf(-2.0f, acc[ma][na][1], cn[na * 2 + 1]);
                    float k10 = fmaf(-2.0f, acc[ma][na][2], cn[na * 2]);
                    float k11 = fmaf(-2.0f, acc[ma][na][3], cn[na * 2 + 1]);
                    if (k00 < bestv[slo]) { bestv[slo] = k00; besti[slo] = c0; }
                    if (k01 < bestv[slo]) { bestv[slo] = k01; besti[slo] = c0 + 1; }
                    if (k10 < bestv[shi]) { bestv[shi] = k10; besti[shi] = c0; }
                    if (k11 < bestv[shi]) { bestv[shi] = k11; besti[shi] = c0 + 1; }
                    acc[ma][na][0] = 0.0f; acc[ma][na][1] = 0.0f;
                    acc[ma][na][2] = 0.0f; acc[ma][na][3] = 0.0f;
                }
            }
        }

        // reduce across the 4 lanes sharing each row; first-index ties
#pragma unroll
        for (int s = 0; s < 4; s++) {
            float v = bestv[s]; int bi = besti[s];
#pragma unroll
            for (int o = 1; o <= 2; o <<= 1) {
                float vo = __shfl_xor_sync(0xffffffffu, v, o);
                int   io = __shfl_xor_sync(0xffffffffu, bi, o);
                if (vo < v || (vo == v && io < bi)) { v = vo; bi = io; }
            }
            if ((lane & 3) == 0) {
                int row = wm * 32 + (s >> 1) * 16 + (s & 1) * 8 + (lane >> 2);
                reinterpret_cast<float*>(smem + BV_OFF)[wn * 64 + row] = v;
                reinterpret_cast<int*>(smem + BI_OFF)[wn * 64 + row]   = bi;
            }
        }
    } else {
        // ---------------- producer warps: pw owns ring slot pw ----------------
        const int pw = wid - 4;
        const uint32_t dst = sb + SLOT_OFF + (pw << 14);
        uint32_t pe = 0;
        const int nchunks = nt * 8;
        for (int c = pw; c < nchunks; c += 2) {
            if (c >= 2) { mbar_wait(sb + MB_OFF + 16 + pw * 8, pe); pe ^= 1; }
            const int t = c >> 3, r = c & 7, kc = r >> 1;
            const float* src = ((r & 1) ? g_cl : g_ch) + ((size_t)(t * 4 + kc) << 12);
#pragma unroll
            for (int i = 0; i < 32; i++)
                cp16(dst + (uint32_t)((i * 32 + lane) << 4), src + ((i * 32 + lane) << 2));
            cp_commit(); cp_wait0();
            mbar_arrive(sb + MB_OFF + pw * 8);   // 32 lane arrives -> count 32
        }
    }

    __syncthreads();

    // combine 2 warp-col stripes per row, gather codes, loss (192 threads, 16 per row)
    float thr_loss = 0.0f;
    {
        const int txg = tid & 15, grp = tid >> 4;            // 12 groups
        const float* bv = reinterpret_cast<const float*>(smem + BV_OFF);
        const int*   bixs = reinterpret_cast<const int*>(smem + BI_OFF);
        for (int row = grp; row < BM; row += 12) {
            float v0 = bv[row], v1 = bv[64 + row];
            int i0 = bixs[row], i1 = bixs[64 + row];
            int bi = (v1 < v0 || (v1 == v0 && i1 < i0)) ? i1 : i0;
            int grow = row0 + row;
            if (txg == 0 && write_idx) out_idx[grow] = (float)bi;
            const float4* cq = reinterpret_cast<const float4*>(codes + (size_t)bi * DDIM + txg * 8);
            float4 q0 = cq[0], q1 = cq[1];
            float4* od = reinterpret_cast<float4*>(out_q + (size_t)grow * DDIM + txg * 8);
            od[0] = q0; od[1] = q1;
            const float4* xp = reinterpret_cast<const float4*>(x + (size_t)grow * DDIM + txg * 8);
            float4 x0 = xp[0], x1 = xp[1];
            float d;
            d = x0.x - q0.x; thr_loss = fmaf(d, d, thr_loss);
            d = x0.y - q0.y; thr_loss = fmaf(d, d, thr_loss);
            d = x0.z - q0.z; thr_loss = fmaf(d, d, thr_loss);
            d = x0.w - q0.w; thr_loss = fmaf(d, d, thr_loss);
            d = x1.x - q1.x; thr_loss = fmaf(d, d, thr_loss);
            d = x1.y - q1.y; thr_loss = fmaf(d, d, thr_loss);
            d = x1.z - q1.z; thr_loss = fmaf(d, d, thr_loss);
            d = x1.w - q1.w; thr_loss = fmaf(d, d, thr_loss);
        }
    }
#pragma unroll
    for (int o = 16; o; o >>= 1) thr_loss += __shfl_xor_sync(0xffffffffu, thr_loss, o);
    if (lane == 0) reinterpret_cast<float*>(smem + RED_OFF)[wid] = thr_loss;
    __syncthreads();
    if (tid == 0) {
        float sum = 0.0f;
#pragma unroll
        for (int w = 0; w < TPB / 32; w++) sum += reinterpret_cast<const float*>(smem + RED_OFF)[w];
        g_block_loss[blockIdx.x] = sum;
    }
}

// ---- deterministic fixed-order final loss reduction ----
__global__ void finalize_kernel(float* __restrict__ out_loss, int nblocks, float invB)
{
    __shared__ float red[256];
    float s = 0.0f;
    for (int i = threadIdx.x; i < nblocks; i += 256) s += g_block_loss[i];
    red[threadIdx.x] = s;
    __syncthreads();
    for (int o = 128; o; o >>= 1) {
        if (threadIdx.x < o) red[threadIdx.x] += red[threadIdx.x + o];
        __syncthreads();
    }
    if (threadIdx.x == 0) *out_loss = 1.25f * red[0] * invB;  // (1 + BETA) * mean ||x-q||^2
}

extern "C" void kernel_launch(void* const* d_in, const int* in_sizes, int n_in,
                              void* d_out, int out_size)
{
    const float* x     = (const float*)d_in[0];
    const float* codes = (const float*)d_in[1];
    const int B = in_sizes[0] / DDIM;
    const int C = in_sizes[1] / DDIM;

    float* out      = (float*)d_out;
    float* out_q    = out;
    float* out_idx  = out + (size_t)B * DDIM;
    float* out_loss = out + (size_t)B * DDIM + B;

    const long long need_idx  = (long long)B * DDIM + B;
    const long long need_loss = need_idx + 1;
    const int write_idx  = ((long long)out_size >= need_idx)  ? 1 : 0;
    const int write_loss = ((long long)out_size >= need_loss) ? 1 : 0;

    const int n4x = B * DDIM / 4, n4c = C * DDIM / 4;
    split_x<<<(n4x + 255) / 256, 256>>>(x, n4x);
    split_c<<<(n4c + 255) / 256, 256>>>(codes, n4c);
    cnorm_kernel<<<(C + 7) / 8, 256>>>(codes, C);

    (void)cudaFuncSetAttribute(vq_mma, cudaFuncAttributeMaxDynamicSharedMemorySize, SMEM_MAIN);
    vq_mma<<<B / BM, TPB, SMEM_MAIN>>>(x, codes, out_q, out_idx, C, write_idx);

    if (write_loss)
        finalize_kernel<<<1, 256>>>(out_loss, B / BM, 1.0f / (float)B);
}

// round 7
// speedup vs baseline: 3.4481x; 1.7570x over previous
#include <cuda_runtime.h>
#include <cuda_fp16.h>
#include <math_constants.h>
#include <cstdint>

// Quantizer_33036888441545 — VQ argmin + gather + loss via mma.sync fp16 (3x split, fp32 acc).
// R7: m16n8k16 f16 HMMA (2x tf32 rate). BM=64, 192 thr (4 math warps 32x64 + 2 producers), occ 2.

#define DDIM 128
#define BM   64
#define TPB  192
#define MAXB 65536
#define MAXC 4096

__device__ __half g_xh[MAXB * DDIM];
__device__ __half g_xl[MAXB * DDIM];
__device__ __half g_ch[MAXC * DDIM];
__device__ __half g_cl[MAXC * DDIM];
__device__ float  g_cnorm[MAXC];
__device__ float  g_block_loss[MAXB / BM];

// ---- smem map (bytes) ----
#define AH_OFF   0          // 16KB A-hi frags (64 rows), resident
#define AL_OFF   16384      // 16KB A-lo frags, resident
#define SLOT_OFF 32768      // 4 x 8KB B ring (slots 0,2 = ch ; 1,3 = cl)
#define MB_OFF   65536      // full[4] @ +0..24 ; empty[4] @ +32..56
#define BV_OFF   65600      // float bv[2][64]
#define BI_OFF   66112      // int   bi[2][64]
#define RED_OFF  66624      // float red[6]
#define SMEM_MAIN 66688

// ============ helpers ============
__device__ __forceinline__ uint32_t smem_u32(const void* p) {
    uint32_t a;
    asm("{ .reg .u64 t; cvta.to.shared.u64 t, %1; cvt.u32.u64 %0, t; }" : "=r"(a) : "l"(p));
    return a;
}
__device__ __forceinline__ void mbar_init(uint32_t a, uint32_t cnt) {
    asm volatile("mbarrier.init.shared.b64 [%0], %1;" :: "r"(a), "r"(cnt) : "memory");
}
__device__ __forceinline__ void mbar_arrive(uint32_t a) {
    asm volatile("mbarrier.arrive.shared.b64 _, [%0];" :: "r"(a) : "memory");
}
__device__ __forceinline__ void mbar_wait(uint32_t a, uint32_t parity) {
    uint32_t done = 0;
    while (!done) {
        asm volatile(
            "{ .reg .pred p; mbarrier.try_wait.parity.acquire.cta.shared::cta.b64 p, [%1], %2, 0x989680; selp.b32 %0,1,0,p; }"
            : "=r"(done) : "r"(a), "r"(parity) : "memory");
    }
}
__device__ __forceinline__ void cp16(uint32_t dst, const float* src) {
    asm volatile("cp.async.cg.shared.global [%0], [%1], 16;" :: "r"(dst), "l"(src) : "memory");
}
__device__ __forceinline__ void cp_commit() { asm volatile("cp.async.commit_group;" ::: "memory"); }
__device__ __forceinline__ void cp_wait0()  { asm volatile("cp.async.wait_group 0;"  ::: "memory"); }

// m16n8k16 fp16 MMA, fp32 accumulate
__device__ __forceinline__ void mma16(float* c, const uint4& a, const uint2& b) {
    asm volatile(
        "mma.sync.aligned.m16n8k16.row.col.f32.f16.f16.f32 "
        "{%0,%1,%2,%3}, {%4,%5,%6,%7}, {%8,%9}, {%0,%1,%2,%3};"
        : "+f"(c[0]), "+f"(c[1]), "+f"(c[2]), "+f"(c[3])
        : "r"(a.x), "r"(a.y), "r"(a.z), "r"(a.w), "r"(b.x), "r"(b.y));
}

// ============ split kernels: fp16 hi/lo + fragment-layout pack ============
// A frag layout (per 64-row block): [blk][ks(8)][ma(4)][lane(32)][reg(4)][klo(2)] halves
__global__ void split_x(const float* __restrict__ x, int n4)
{
    int i = blockIdx.x * 256 + threadIdx.x;
    if (i >= n4) return;
    int m = i >> 5, q = i & 31, k0 = q * 4;
    float4 v = reinterpret_cast<const float4*>(x)[i];
    float vv[4] = {v.x, v.y, v.z, v.w};
    int blk = m >> 6, mloc = m & 63, ma = mloc >> 4, r = mloc & 15;
#pragma unroll
    for (int j = 0; j < 4; j++) {
        int k = k0 + j;
        int ks = k >> 4, kk = k & 15;
        int lane = (r & 7) * 4 + ((kk & 7) >> 1);
        int reg  = ((kk >> 3) << 1) | (r >> 3);
        int klo  = kk & 1;
        size_t idx = (((((size_t)blk * 8 + ks) * 4 + ma) * 32 + lane) * 4 + reg) * 2 + klo;
        __half h = __float2half_rn(vv[j]);
        __half l = __float2half_rn(vv[j] - __half2float(h));
        g_xh[idx] = h;
        g_xl[idx] = l;
    }
}

// B frag layout: [t][kc(4)][ks2(2)][na(16)][lane(32)][reg(2)][klo(2)] halves (8KB per (t,kc) chunk)
__global__ void split_c(const float* __restrict__ codes, int n4)
{
    int i = blockIdx.x * 256 + threadIdx.x;
    if (i >= n4) return;
    int n = i >> 5, q = i & 31, k0 = q * 4;
    float4 v = reinterpret_cast<const float4*>(codes)[i];
    float vv[4] = {v.x, v.y, v.z, v.w};
    int t = n >> 7, nloc = n & 127, na = nloc >> 3;
#pragma unroll
    for (int j = 0; j < 4; j++) {
        int k = k0 + j;
        int kc = k >> 5, ks2 = (k >> 4) & 1, kk = k & 15;
        int lane = (nloc & 7) * 4 + ((kk & 7) >> 1);
        int reg  = kk >> 3;
        int klo  = kk & 1;
        size_t idx = ((((((size_t)t * 4 + kc) * 2 + ks2) * 16 + na) * 32 + lane) * 2 + reg) * 2 + klo;
        __half h = __float2half_rn(vv[j]);
        __half l = __float2half_rn(vv[j] - __half2float(h));
        g_ch[idx] = h;
        g_cl[idx] = l;
    }
}

__global__ void cnorm_kernel(const float* __restrict__ codes, int C)
{
    int j = blockIdx.x * 8 + (threadIdx.x >> 5);
    int lane = threadIdx.x & 31;
    if (j >= C) return;
    float4 v = reinterpret_cast<const float4*>(codes + (size_t)j * DDIM)[lane];
    float s = v.x * v.x + v.y * v.y + v.z * v.z + v.w * v.w;
#pragma unroll
    for (int o = 16; o; o >>= 1) s += __shfl_xor_sync(0xffffffffu, s, o);
    if (lane == 0) g_cnorm[j] = s;
}

// ============ main kernel ============
// 6 warps: 0-3 math (2x2 grid, 32x64 tiles), 4-5 producers (pw=0 -> ch slots {0,2}, pw=1 -> cl {1,3}).
__global__ __launch_bounds__(TPB, 2)
void vq_mma(const float* __restrict__ x, const float* __restrict__ codes,
            float* __restrict__ out_q, float* __restrict__ out_idx,
            int C, int write_idx)
{
    extern __shared__ char smem[];
    const uint32_t sb = smem_u32(smem);
    const int tid = threadIdx.x, wid = tid >> 5, lane = tid & 31;
    const int row0 = blockIdx.x * BM;
    const int nt = C >> 7;

    if (tid == 0) {
#pragma unroll
        for (int s = 0; s < 4; s++) {
            mbar_init(sb + MB_OFF + s * 8, 32);        // full: one producer warp (32 lanes)
            mbar_init(sb + MB_OFF + 32 + s * 8, 4);    // empty: 4 math warps
        }
    }

    // Resident A copy (frag-packed, contiguous): 2 x 16KB via cp.async.
    {
        const float* srch = reinterpret_cast<const float*>(g_xh) + (size_t)blockIdx.x * 4096;
        const float* srcl = reinterpret_cast<const float*>(g_xl) + (size_t)blockIdx.x * 4096;
        for (int i = tid; i < 1024; i += TPB) {
            cp16(sb + AH_OFF + i * 16, srch + i * 4);
            cp16(sb + AL_OFF + i * 16, srcl + i * 4);
        }
        cp_commit(); cp_wait0();
    }
    __syncthreads();

    if (wid < 4) {
        // ---------------- math warps: 32 rows (wm) x 64 cols (wn) ----------------
        const int wm = wid >> 1, wn = wid & 1;
        float acc[2][8][4];
#pragma unroll
        for (int a = 0; a < 2; a++)
#pragma unroll
            for (int b = 0; b < 8; b++)
#pragma unroll
                for (int r = 0; r < 4; r++) acc[a][b][r] = 0.0f;
        float bestv[4]; int besti[4];
#pragma unroll
        for (int s = 0; s < 4; s++) { bestv[s] = CUDART_INF_F; besti[s] = 0; }
        uint32_t pf[4] = {0, 0, 0, 0};

        for (int t = 0; t < nt; t++) {
            float cn[16];
            const int cb = t * 128 + wn * 64 + (lane & 3) * 2;
#pragma unroll
            for (int na = 0; na < 8; na++) {
                cn[na * 2]     = __ldg(&g_cnorm[cb + na * 8]);
                cn[na * 2 + 1] = __ldg(&g_cnorm[cb + na * 8 + 1]);
            }

#pragma unroll 1
            for (int kc = 0; kc < 4; kc++) {
                const int sch = (kc * 2) & 3, scl = sch + 1;
                const uint32_t bch = (uint32_t)(SLOT_OFF + (sch << 13));
                const uint32_t bcl = (uint32_t)(SLOT_OFF + (scl << 13));

                mbar_wait(sb + MB_OFF + sch * 8, pf[sch]); pf[sch] ^= 1;
#pragma unroll
                for (int pass = 0; pass < 2; pass++) {          // hh then lh (both on ch)
                    const uint32_t abase = pass ? AL_OFF : AH_OFF;
#pragma unroll
                    for (int ks2 = 0; ks2 < 2; ks2++) {
                        const int ks = kc * 2 + ks2;
                        uint4 af[2]; uint2 bf[8];
#pragma unroll
                        for (int ma = 0; ma < 2; ma++)
                            af[ma] = *reinterpret_cast<const uint4*>(
                                smem + abase + (((ks * 4) + wm * 2 + ma) * 32 + lane) * 16);
#pragma unroll
                        for (int na = 0; na < 8; na++)
                            bf[na] = *reinterpret_cast<const uint2*>(
                                smem + bch + (((ks2 * 16) + wn * 8 + na) * 32 + lane) * 8);
#pragma unroll
                        for (int ma = 0; ma < 2; ma++)
#pragma unroll
                            for (int na = 0; na < 8; na++)
                                mma16(acc[ma][na], af[ma], bf[na]);
                    }
                }
                if (lane == 0) mbar_arrive(sb + MB_OFF + 32 + sch * 8);

                mbar_wait(sb + MB_OFF + scl * 8, pf[scl]); pf[scl] ^= 1;
#pragma unroll
                for (int ks2 = 0; ks2 < 2; ks2++) {             // hl (xh * cl)
                    const int ks = kc * 2 + ks2;
                    uint4 af[2]; uint2 bf[8];
#pragma unroll
                    for (int ma = 0; ma < 2; ma++)
                        af[ma] = *reinterpret_cast<const uint4*>(
                            smem + AH_OFF + (((ks * 4) + wm * 2 + ma) * 32 + lane) * 16);
#pragma unroll
                    for (int na = 0; na < 8; na++)
                        bf[na] = *reinterpret_cast<const uint2*>(
                            smem + bcl + (((ks2 * 16) + wn * 8 + na) * 32 + lane) * 8);
#pragma unroll
                    for (int ma = 0; ma < 2; ma++)
#pragma unroll
                        for (int na = 0; na < 8; na++)
                            mma16(acc[ma][na], af[ma], bf[na]);
                }
                if (lane == 0) mbar_arrive(sb + MB_OFF + 32 + scl * 8);
            }

            // epilogue: key = ||c||^2 - 2 x.c, online argmin, reset accs
#pragma unroll
            for (int ma = 0; ma < 2; ma++) {
                const int slo = ma * 2, shi = ma * 2 + 1;
#pragma unroll
                for (int na = 0; na < 8; na++) {
                    const int c0 = t * 128 + wn * 64 + na * 8 + (lane & 3) * 2;
                    float k00 = fmaf(-2.0f, acc[ma][na][0], cn[na * 2]);
                    float k01 = fmaf(-2.0f, acc[ma][na][1], cn[na * 2 + 1]);
                    float k10 = fmaf(-2.0f, acc[ma][na][2], cn[na * 2]);
                    float k11 = fmaf(-2.0f, acc[ma][na][3], cn[na * 2 + 1]);
                    if (k00 < bestv[slo]) { bestv[slo] = k00; besti[slo] = c0; }
                    if (k01 < bestv[slo]) { bestv[slo] = k01; besti[slo] = c0 + 1; }
                    if (k10 < bestv[shi]) { bestv[shi] = k10; besti[shi] = c0; }
                    if (k11 < bestv[shi]) { bestv[shi] = k11; besti[shi] = c0 + 1; }
                    acc[ma][na][0] = 0.0f; acc[ma][na][1] = 0.0f;
                    acc[ma][na][2] = 0.0f; acc[ma][na][3] = 0.0f;
                }
            }
        }

        // reduce across the 4 lanes sharing each row; first-index ties
#pragma unroll
        for (int s = 0; s < 4; s++) {
            float v = bestv[s]; int bi = besti[s];
#pragma unroll
            for (int o = 1; o <= 2; o <<= 1) {
                float vo = __shfl_xor_sync(0xffffffffu, v, o);
                int   io = __shfl_xor_sync(0xffffffffu, bi, o);
                if (vo < v || (vo == v && io < bi)) { v = vo; bi = io; }
            }
            if ((lane & 3) == 0) {
                int row = wm * 32 + (s >> 1) * 16 + (s & 1) * 8 + (lane >> 2);
                reinterpret_cast<float*>(smem + BV_OFF)[wn * 64 + row] = v;
                reinterpret_cast<int*>(smem + BI_OFF)[wn * 64 + row]   = bi;
            }
        }
    } else {
        // ---------------- producer warps ----------------
        const int pw = wid - 4;
        uint32_t pe[2] = {0, 0};
        const int nchunks = nt * 8;
        for (int c = pw; c < nchunks; c += 2) {
            const int slot = c & 3;
            if (c >= 4) { mbar_wait(sb + MB_OFF + 32 + slot * 8, pe[slot >> 1]); pe[slot >> 1] ^= 1; }
            const int t = c >> 3, r = c & 7, kc = r >> 1;
            const float* src = reinterpret_cast<const float*>((r & 1) ? g_cl : g_ch)
                             + ((size_t)(t * 4 + kc) << 11);
            const uint32_t dst = sb + SLOT_OFF + (slot << 13);
#pragma unroll
            for (int i = 0; i < 16; i++)
                cp16(dst + (uint32_t)((i * 32 + lane) << 4), src + ((i * 32 + lane) << 2));
            cp_commit(); cp_wait0();
            mbar_arrive(sb + MB_OFF + slot * 8);   // 32 lane arrives -> count 32
        }
    }

    __syncthreads();

    // combine 2 warp-col stripes per row, gather codes, loss (192 threads, 16 per row)
    float thr_loss = 0.0f;
    {
        const int txg = tid & 15, grp = tid >> 4;            // 12 groups
        const float* bv = reinterpret_cast<const float*>(smem + BV_OFF);
        const int*   bixs = reinterpret_cast<const int*>(smem + BI_OFF);
        for (int row = grp; row < BM; row += 12) {
            float v0 = bv[row], v1 = bv[64 + row];
            int i0 = bixs[row], i1 = bixs[64 + row];
            int bi = (v1 < v0 || (v1 == v0 && i1 < i0)) ? i1 : i0;
            int grow = row0 + row;
            if (txg == 0 && write_idx) out_idx[grow] = (float)bi;
            const float4* cq = reinterpret_cast<const float4*>(codes + (size_t)bi * DDIM + txg * 8);
            float4 q0 = cq[0], q1 = cq[1];
            float4* od = reinterpret_cast<float4*>(out_q + (size_t)grow * DDIM + txg * 8);
            od[0] = q0; od[1] = q1;
            const float4* xp = reinterpret_cast<const float4*>(x + (size_t)grow * DDIM + txg * 8);
            float4 x0 = xp[0], x1 = xp[1];
            float d;
            d = x0.x - q0.x; thr_loss = fmaf(d, d, thr_loss);
            d = x0.y - q0.y; thr_loss = fmaf(d, d, thr_loss);
            d = x0.z - q0.z; thr_loss = fmaf(d, d, thr_loss);
            d = x0.w - q0.w; thr_loss = fmaf(d, d, thr_loss);
            d = x1.x - q1.x; thr_loss = fmaf(d, d, thr_loss);
            d = x1.y - q1.y; thr_loss = fmaf(d, d, thr_loss);
            d = x1.z - q1.z; thr_loss = fmaf(d, d, thr_loss);
            d = x1.w - q1.w; thr_loss = fmaf(d, d, thr_loss);
        }
    }
#pragma unroll
    for (int o = 16; o; o >>= 1) thr_loss += __shfl_xor_sync(0xffffffffu, thr_loss, o);
    if (lane == 0) reinterpret_cast<float*>(smem + RED_OFF)[wid] = thr_loss;
    __syncthreads();
    if (tid == 0) {
        float sum = 0.0f;
#pragma unroll
        for (int w = 0; w < TPB / 32; w++) sum += reinterpret_cast<const float*>(smem + RED_OFF)[w];
        g_block_loss[blockIdx.x] = sum;
    }
}

// ---- deterministic fixed-order final loss reduction ----
__global__ void finalize_kernel(float* __restrict__ out_loss, int nblocks, float invB)
{
    __shared__ float red[256];
    float s = 0.0f;
    for (int i = threadIdx.x; i < nblocks; i += 256) s += g_block_loss[i];
    red[threadIdx.x] = s;
    __syncthreads();
    for (int o = 128; o; o >>= 1) {
        if (threadIdx.x < o) red[threadIdx.x] += red[threadIdx.x + o];
        __syncthreads();
    }
    if (threadIdx.x == 0) *out_loss = 1.25f * red[0] * invB;  // (1 + BETA) * mean ||x-q||^2
}

extern "C" void kernel_launch(void* const* d_in, const int* in_sizes, int n_in,
                              void* d_out, int out_size)
{
    const float* x     = (const float*)d_in[0];
    const float* codes = (const float*)d_in[1];
    const int B = in_sizes[0] / DDIM;
    const int C = in_sizes[1] / DDIM;

    float* out      = (float*)d_out;
    float* out_q    = out;
    float* out_idx  = out + (size_t)B * DDIM;
    float* out_loss = out + (size_t)B * DDIM + B;

    const long long need_idx  = (long long)B * DDIM + B;
    const long long need_loss = need_idx + 1;
    const int write_idx  = ((long long)out_size >= need_idx)  ? 1 : 0;
    const int write_loss = ((long long)out_size >= need_loss) ? 1 : 0;

    const int n4x = B * DDIM / 4, n4c = C * DDIM / 4;
    split_x<<<(n4x + 255) / 256, 256>>>(x, n4x);
    split_c<<<(n4c + 255) / 256, 256>>>(codes, n4c);
    cnorm_kernel<<<(C + 7) / 8, 256>>>(codes, C);

    (void)cudaFuncSetAttribute(vq_mma, cudaFuncAttributeMaxDynamicSharedMemorySize, SMEM_MAIN);
    vq_mma<<<B / BM, TPB, SMEM_MAIN>>>(x, codes, out_q, out_idx, C, write_idx);

    if (write_loss)
        finalize_kernel<<<1, 256>>>(out_loss, B / BM, 1.0f / (float)B);
}

// round 8
// speedup vs baseline: 5.0495x; 1.4644x over previous
#include <cuda_runtime.h>
#include <cuda_fp16.h>
#include <math_constants.h>
#include <cstdint>

// Quantizer_33036888441545 — VQ argmin via hh-screen + exact 3xfp16 refine.
// x: [65536,128] f32, codes: [4096,128] f32. out: q[B*128], idx[B], loss[1].

#define DDIM 128
#define BM   64
#define TPB  192
#define MAXB 65536
#define MAXC 4096

__device__ __half    g_xh[MAXB * DDIM];
__device__ __half    g_xl[MAXB * DDIM];
__device__ __half    g_ch[MAXC * DDIM];
__device__ __half    g_cl[MAXC * DDIM];
__device__ float     g_cnorm[MAXC];
__device__ float     g_xhn[MAXB];
__device__ float     g_xln[MAXB];
__device__ unsigned  g_clmax;
__device__ unsigned  g_chmax;
__device__ int       g_idx[MAXB];
__device__ int       g_undec[MAXB];
__device__ int       g_count;
__device__ float     g_block_loss[1024];

// ---- pass1 smem map ----
#define P1_AH    0          // 16KB A-hi frags
#define P1_SLOT  16384      // 4 x 8KB ch ring
#define P1_MB    49152      // full[4] @+0..31, empty[4] @+32..63
#define P1_M1    49216      // float [2][64]
#define P1_M2    49728
#define P1_I1    50240
#define SMEM_P1  50752

// ---- refine smem map ----
#define RF_AH    0
#define RF_AL    16384
#define RF_SLOT  32768      // 4 x 8KB ring (ch/cl)
#define RF_MB    65536
#define RF_BV    65600      // float [2][64]
#define RF_BI    66112
#define RF_LIST  66624      // int [64]
#define SMEM_RF  66880

// ============ helpers ============
__device__ __forceinline__ uint32_t smem_u32(const void* p) {
    uint32_t a;
    asm("{ .reg .u64 t; cvta.to.shared.u64 t, %1; cvt.u32.u64 %0, t; }" : "=r"(a) : "l"(p));
    return a;
}
__device__ __forceinline__ void mbar_init(uint32_t a, uint32_t cnt) {
    asm volatile("mbarrier.init.shared.b64 [%0], %1;" :: "r"(a), "r"(cnt) : "memory");
}
__device__ __forceinline__ void mbar_arrive(uint32_t a) {
    asm volatile("mbarrier.arrive.shared.b64 _, [%0];" :: "r"(a) : "memory");
}
__device__ __forceinline__ void mbar_wait(uint32_t a, uint32_t parity) {
    uint32_t done = 0;
    while (!done) {
        asm volatile(
            "{ .reg .pred p; mbarrier.try_wait.parity.acquire.cta.shared::cta.b64 p, [%1], %2, 0x989680; selp.b32 %0,1,0,p; }"
            : "=r"(done) : "r"(a), "r"(parity) : "memory");
    }
}
__device__ __forceinline__ void cp16(uint32_t dst, const float* src) {
    asm volatile("cp.async.cg.shared.global [%0], [%1], 16;" :: "r"(dst), "l"(src) : "memory");
}
__device__ __forceinline__ void cp_commit() { asm volatile("cp.async.commit_group;" ::: "memory"); }
__device__ __forceinline__ void cp_wait0()  { asm volatile("cp.async.wait_group 0;"  ::: "memory"); }

__device__ __forceinline__ void mma16(float* c, const uint4& a, const uint2& b) {
    asm volatile(
        "mma.sync.aligned.m16n8k16.row.col.f32.f16.f16.f32 "
        "{%0,%1,%2,%3}, {%4,%5,%6,%7}, {%8,%9}, {%0,%1,%2,%3};"
        : "+f"(c[0]), "+f"(c[1]), "+f"(c[2]), "+f"(c[3])
        : "r"(a.x), "r"(a.y), "r"(a.z), "r"(a.w), "r"(b.x), "r"(b.y));
}

// A-frag half2-unit index within a 64-row block, for row mloc (0..63), even k.
__device__ __forceinline__ int a_frag_h2(int mloc, int k) {
    int ks = k >> 4, kk = k & 15, ma = mloc >> 4, r = mloc & 15;
    int lane = (r & 7) * 4 + ((kk & 7) >> 1);
    int reg  = ((kk >> 3) << 1) | (r >> 3);
    return ((ks * 4 + ma) * 32 + lane) * 4 + reg;
}

// ============ split_x: one warp per row; frags + row norms; resets ============
__global__ void split_x(const float* __restrict__ x)
{
    if (blockIdx.x == 0 && threadIdx.x == 0) { g_count = 0; g_clmax = 0u; g_chmax = 0u; }
    int row  = blockIdx.x * 8 + (threadIdx.x >> 5);
    int lane = threadIdx.x & 31;
    float4 v = reinterpret_cast<const float4*>(x)[(size_t)row * 32 + lane];
    float vv[4] = {v.x, v.y, v.z, v.w};
    __half h[4]; float l[4];
    float hs = 0.0f, ls = 0.0f;
#pragma unroll
    for (int j = 0; j < 4; j++) {
        h[j] = __float2half_rn(vv[j]);
        float hf = __half2float(h[j]);
        l[j] = vv[j] - hf;
        hs = fmaf(hf, hf, hs);
        ls = fmaf(l[j], l[j], ls);
    }
    int blk = row >> 6, mloc = row & 63;
    __half2* xh2 = reinterpret_cast<__half2*>(g_xh) + (size_t)blk * 4096;
    __half2* xl2 = reinterpret_cast<__half2*>(g_xl) + (size_t)blk * 4096;
#pragma unroll
    for (int p = 0; p < 2; p++) {
        int k = lane * 4 + p * 2;
        int u = a_frag_h2(mloc, k);
        xh2[u] = __halves2half2(h[p * 2], h[p * 2 + 1]);
        xl2[u] = __halves2half2(__float2half_rn(l[p * 2]), __float2half_rn(l[p * 2 + 1]));
    }
#pragma unroll
    for (int o = 16; o; o >>= 1) {
        hs += __shfl_xor_sync(0xffffffffu, hs, o);
        ls += __shfl_xor_sync(0xffffffffu, ls, o);
    }
    if (lane == 0) { g_xhn[row] = sqrtf(hs); g_xln[row] = sqrtf(ls); }
}

// ============ split_c: one warp per code; frags + cnorm + max split-norms ============
__global__ void split_c(const float* __restrict__ codes)
{
    int n    = blockIdx.x * 8 + (threadIdx.x >> 5);
    int lane = threadIdx.x & 31;
    float4 v = reinterpret_cast<const float4*>(codes)[(size_t)n * 32 + lane];
    float vv[4] = {v.x, v.y, v.z, v.w};
    __half h[4]; float l[4];
    float cs = 0.0f, hs = 0.0f, ls = 0.0f;
#pragma unroll
    for (int j = 0; j < 4; j++) {
        h[j] = __float2half_rn(vv[j]);
        float hf = __half2float(h[j]);
        l[j] = vv[j] - hf;
        cs = fmaf(vv[j], vv[j], cs);
        hs = fmaf(hf, hf, hs);
        ls = fmaf(l[j], l[j], ls);
    }
    int t = n >> 7, nloc = n & 127, na = nloc >> 3;
    __half2* ch2 = reinterpret_cast<__half2*>(g_ch);
    __half2* cl2 = reinterpret_cast<__half2*>(g_cl);
#pragma unroll
    for (int p = 0; p < 2; p++) {
        int k = lane * 4 + p * 2;
        int kc = k >> 5, ks2 = (k >> 4) & 1, kk = k & 15;
        int lane_f = (nloc & 7) * 4 + ((kk & 7) >> 1);
        int reg    = kk >> 3;
        size_t u = ((((size_t)(t * 4 + kc) * 2 + ks2) * 16 + na) * 32 + lane_f) * 2 + reg;
        ch2[u] = __halves2half2(h[p * 2], h[p * 2 + 1]);
        cl2[u] = __halves2half2(__float2half_rn(l[p * 2]), __float2half_rn(l[p * 2 + 1]));
    }
#pragma unroll
    for (int o = 16; o; o >>= 1) {
        cs += __shfl_xor_sync(0xffffffffu, cs, o);
        hs += __shfl_xor_sync(0xffffffffu, hs, o);
        ls += __shfl_xor_sync(0xffffffffu, ls, o);
    }
    if (lane == 0) {
        g_cnorm[n] = cs;
        atomicMax(&g_chmax, __float_as_uint(sqrtf(hs)));
        atomicMax(&g_clmax, __float_as_uint(sqrtf(ls)));
    }
}

// ============ pass1: hh-only GEMM, min1/min2/idx per row, decide/append ============
__global__ __launch_bounds__(TPB, 2)
void vq_pass1(int C)
{
    extern __shared__ char smem[];
    const uint32_t sb = smem_u32(smem);
    const int tid = threadIdx.x, wid = tid >> 5, lane = tid & 31;
    const int row0 = blockIdx.x * BM;
    const int nt = C >> 7;

    if (tid == 0) {
#pragma unroll
        for (int s = 0; s < 4; s++) {
            mbar_init(sb + P1_MB + s * 8, 32);
            mbar_init(sb + P1_MB + 32 + s * 8, 4);
        }
    }
    {   // resident A-hi (16KB)
        const float* srch = reinterpret_cast<const float*>(g_xh) + (size_t)blockIdx.x * 4096;
        for (int i = tid; i < 1024; i += TPB) cp16(sb + P1_AH + i * 16, srch + i * 4);
        cp_commit(); cp_wait0();
    }
    __syncthreads();

    if (wid < 4) {
        const int wm = wid >> 1, wn = wid & 1;
        float acc[2][8][4];
#pragma unroll
        for (int a = 0; a < 2; a++)
#pragma unroll
            for (int b = 0; b < 8; b++)
#pragma unroll
                for (int r = 0; r < 4; r++) acc[a][b][r] = 0.0f;
        float m1[4], m2[4]; int i1[4];
#pragma unroll
        for (int s = 0; s < 4; s++) { m1[s] = CUDART_INF_F; m2[s] = CUDART_INF_F; i1[s] = 0; }
        uint32_t pf[4] = {0, 0, 0, 0};

        for (int t = 0; t < nt; t++) {
            float cn[16];
            const int cb = t * 128 + wn * 64 + (lane & 3) * 2;
#pragma unroll
            for (int na = 0; na < 8; na++) {
                cn[na * 2]     = __ldg(&g_cnorm[cb + na * 8]);
                cn[na * 2 + 1] = __ldg(&g_cnorm[cb + na * 8 + 1]);
            }
#pragma unroll 1
            for (int kc = 0; kc < 4; kc++) {
                const int slot = kc;                 // chunk index t*4+kc -> slot (t*4+kc)&3 == kc
                const uint32_t bch = (uint32_t)(P1_SLOT + (slot << 13));
                mbar_wait(sb + P1_MB + slot * 8, pf[slot]); pf[slot] ^= 1;
#pragma unroll
                for (int ks2 = 0; ks2 < 2; ks2++) {
                    const int ks = kc * 2 + ks2;
                    uint4 af[2]; uint2 bf[8];
#pragma unroll
                    for (int ma = 0; ma < 2; ma++)
                        af[ma] = *reinterpret_cast<const uint4*>(
                            smem + P1_AH + (((ks * 4) + wm * 2 + ma) * 32 + lane) * 16);
#pragma unroll
                    for (int na = 0; na < 8; na++)
                        bf[na] = *reinterpret_cast<const uint2*>(
                            smem + bch + (((ks2 * 16) + wn * 8 + na) * 32 + lane) * 8);
#pragma unroll
                    for (int ma = 0; ma < 2; ma++)
#pragma unroll
                        for (int na = 0; na < 8; na++)
                            mma16(acc[ma][na], af[ma], bf[na]);
                }
                if (lane == 0) mbar_arrive(sb + P1_MB + 32 + slot * 8);
            }
            // epilogue: min1/min2/idx per slot
#pragma unroll
            for (int ma = 0; ma < 2; ma++) {
                const int slo = ma * 2, shi = ma * 2 + 1;
#pragma unroll
                for (int na = 0; na < 8; na++) {
                    const int c0 = t * 128 + wn * 64 + na * 8 + (lane & 3) * 2;
                    float k00 = fmaf(-2.0f, acc[ma][na][0], cn[na * 2]);
                    float k01 = fmaf(-2.0f, acc[ma][na][1], cn[na * 2 + 1]);
                    float k10 = fmaf(-2.0f, acc[ma][na][2], cn[na * 2]);
                    float k11 = fmaf(-2.0f, acc[ma][na][3], cn[na * 2 + 1]);
                    {
                        bool p = k00 < m1[slo];
                        m2[slo] = p ? m1[slo] : fminf(m2[slo], k00);
                        i1[slo] = p ? c0 : i1[slo];
                        m1[slo] = p ? k00 : m1[slo];
                    }
                    {
                        bool p = k01 < m1[slo];
                        m2[slo] = p ? m1[slo] : fminf(m2[slo], k01);
                        i1[slo] = p ? (c0 + 1) : i1[slo];
                        m1[slo] = p ? k01 : m1[slo];
                    }
                    {
                        bool p = k10 < m1[shi];
                        m2[shi] = p ? m1[shi] : fminf(m2[shi], k10);
                        i1[shi] = p ? c0 : i1[shi];
                        m1[shi] = p ? k10 : m1[shi];
                    }
                    {
                        bool p = k11 < m1[shi];
                        m2[shi] = p ? m1[shi] : fminf(m2[shi], k11);
                        i1[shi] = p ? (c0 + 1) : i1[shi];
                        m1[shi] = p ? k11 : m1[shi];
                    }
                    acc[ma][na][0] = 0.0f; acc[ma][na][1] = 0.0f;
                    acc[ma][na][2] = 0.0f; acc[ma][na][3] = 0.0f;
                }
            }
        }
        // lane merge (4 lanes per row), then stash per stripe
#pragma unroll
        for (int s = 0; s < 4; s++) {
            float v1 = m1[s], v2 = m2[s]; int ii = i1[s];
#pragma unroll
            for (int o = 1; o <= 2; o <<= 1) {
                float a1 = __shfl_xor_sync(0xffffffffu, v1, o);
                float a2 = __shfl_xor_sync(0xffffffffu, v2, o);
                int   ai = __shfl_xor_sync(0xffffffffu, ii, o);
                bool bwin = (a1 < v1) || (a1 == v1 && ai < ii);
                float loser1 = bwin ? v1 : a1;
                v2 = fminf(fminf(v2, a2), loser1);
                v1 = bwin ? a1 : v1;
                ii = bwin ? ai : ii;
            }
            if ((lane & 3) == 0) {
                int row = wm * 32 + (s >> 1) * 16 + (s & 1) * 8 + (lane >> 2);
                reinterpret_cast<float*>(smem + P1_M1)[wn * 64 + row] = v1;
                reinterpret_cast<float*>(smem + P1_M2)[wn * 64 + row] = v2;
                reinterpret_cast<int*>(smem + P1_I1)[wn * 64 + row]   = ii;
            }
        }
    } else {
        // producers: 2 warps feed 4-slot ch ring
        const int pw = wid - 4;
        uint32_t pe[4] = {0, 0, 0, 0};
        const int nchunks = nt * 4;
        for (int c = pw; c < nchunks; c += 2) {
            const int slot = c & 3;
            if (c >= 4) { mbar_wait(sb + P1_MB + 32 + slot * 8, pe[slot]); pe[slot] ^= 1; }
            const float* src = reinterpret_cast<const float*>(g_ch) + ((size_t)c << 11);
            const uint32_t dst = sb + P1_SLOT + (slot << 13);
#pragma unroll
            for (int i = 0; i < 16; i++)
                cp16(dst + (uint32_t)((i * 32 + lane) << 4), src + ((i * 32 + lane) << 2));
            cp_commit(); cp_wait0();
            mbar_arrive(sb + P1_MB + slot * 8);
        }
    }
    __syncthreads();

    // decide / append (threads 0..63, one row each)
    if (tid < 64) {
        const float* sm1 = reinterpret_cast<const float*>(smem + P1_M1);
        const float* sm2 = reinterpret_cast<const float*>(smem + P1_M2);
        const int*   si1 = reinterpret_cast<const int*>(smem + P1_I1);
        float v1 = sm1[tid], v2 = sm2[tid]; int ii = si1[tid];
        float b1 = sm1[64 + tid], b2 = sm2[64 + tid]; int bi = si1[64 + tid];
        bool bwin = (b1 < v1) || (b1 == v1 && bi < ii);
        float loser1 = bwin ? v1 : b1;
        float m2f = fminf(fminf(v2, b2), loser1);
        float m1f = bwin ? b1 : v1;
        int   idx = bwin ? bi : ii;
        int grow = row0 + tid;
        g_idx[grow] = idx;
        float xhn = g_xhn[grow], xln = g_xln[grow];
        float clm = __uint_as_float(g_clmax), chm = __uint_as_float(g_chmax);
        float eb = xhn * clm + xln * chm + xln * clm;      // Cauchy-Schwarz core
        float thr = 5.0f * eb + 0.125f;                    // 2*(2*eb)*1.25 + slack
        if (!((m2f - m1f) > thr)) {
            int p = atomicAdd(&g_count, 1);
            g_undec[p] = grow;
        }
    }
}

// ============ refine: exact 3-pass over compacted undecided rows ============
__global__ __launch_bounds__(TPB, 2)
void vq_refine(const float* __restrict__ x, int C)
{
    const int cnt = *(volatile int*)&g_count;
    if ((int)blockIdx.x * 64 >= cnt) return;

    extern __shared__ char smem[];
    const uint32_t sb = smem_u32(smem);
    const int tid = threadIdx.x, wid = tid >> 5, lane = tid & 31;
    const int nt = C >> 7;

    if (tid == 0) {
#pragma unroll
        for (int s = 0; s < 4; s++) {
            mbar_init(sb + RF_MB + s * 8, 32);
            mbar_init(sb + RF_MB + 32 + s * 8, 4);
        }
    }
    // load row list + pack A frags from x
    int* list = reinterpret_cast<int*>(smem + RF_LIST);
    if (tid < 64) {
        int li = blockIdx.x * 64 + tid;
        int r = g_undec[(li < cnt) ? li : (cnt - 1)];
        list[tid] = r;
        const float4* xp = reinterpret_cast<const float4*>(x + (size_t)r * DDIM);
        __half2* ah = reinterpret_cast<__half2*>(smem + RF_AH);
        __half2* al = reinterpret_cast<__half2*>(smem + RF_AL);
#pragma unroll 4
        for (int q = 0; q < 32; q++) {
            float4 v = xp[q];
            float vv[4] = {v.x, v.y, v.z, v.w};
            __half h[4]; __half l[4];
#pragma unroll
            for (int j = 0; j < 4; j++) {
                h[j] = __float2half_rn(vv[j]);
                l[j] = __float2half_rn(vv[j] - __half2float(h[j]));
            }
#pragma unroll
            for (int p = 0; p < 2; p++) {
                int k = q * 4 + p * 2;
                int u = a_frag_h2(tid, k);
                ah[u] = __halves2half2(h[p * 2], h[p * 2 + 1]);
                al[u] = __halves2half2(l[p * 2], l[p * 2 + 1]);
            }
        }
    }
    __syncthreads();

    if (wid < 4) {
        const int wm = wid >> 1, wn = wid & 1;
        float acc[2][8][4];
#pragma unroll
        for (int a = 0; a < 2; a++)
#pragma unroll
            for (int b = 0; b < 8; b++)
#pragma unroll
                for (int r = 0; r < 4; r++) acc[a][b][r] = 0.0f;
        float bestv[4]; int besti[4];
#pragma unroll
        for (int s = 0; s < 4; s++) { bestv[s] = CUDART_INF_F; besti[s] = 0; }
        uint32_t pf[4] = {0, 0, 0, 0};

        for (int t = 0; t < nt; t++) {
            float cn[16];
            const int cb = t * 128 + wn * 64 + (lane & 3) * 2;
#pragma unroll
            for (int na = 0; na < 8; na++) {
                cn[na * 2]     = __ldg(&g_cnorm[cb + na * 8]);
                cn[na * 2 + 1] = __ldg(&g_cnorm[cb + na * 8 + 1]);
            }
#pragma unroll 1
            for (int kc = 0; kc < 4; kc++) {
                const int sch = (kc * 2) & 3, scl = sch + 1;
                const uint32_t bch = (uint32_t)(RF_SLOT + (sch << 13));
                const uint32_t bcl = (uint32_t)(RF_SLOT + (scl << 13));
                mbar_wait(sb + RF_MB + sch * 8, pf[sch]); pf[sch] ^= 1;
#pragma unroll
                for (int pass = 0; pass < 2; pass++) {
                    const uint32_t abase = pass ? RF_AL : RF_AH;
#pragma unroll
                    for (int ks2 = 0; ks2 < 2; ks2++) {
                        const int ks = kc * 2 + ks2;
                        uint4 af[2]; uint2 bf[8];
#pragma unroll
                        for (int ma = 0; ma < 2; ma++)
                            af[ma] = *reinterpret_cast<const uint4*>(
                                smem + abase + (((ks * 4) + wm * 2 + ma) * 32 + lane) * 16);
#pragma unroll
                        for (int na = 0; na < 8; na++)
                            bf[na] = *reinterpret_cast<const uint2*>(
                                smem + bch + (((ks2 * 16) + wn * 8 + na) * 32 + lane) * 8);
#pragma unroll
                        for (int ma = 0; ma < 2; ma++)
#pragma unroll
                            for (int na = 0; na < 8; na++)
                                mma16(acc[ma][na], af[ma], bf[na]);
                    }
                }
                if (lane == 0) mbar_arrive(sb + RF_MB + 32 + sch * 8);

                mbar_wait(sb + RF_MB + scl * 8, pf[scl]); pf[scl] ^= 1;
#pragma unroll
                for (int ks2 = 0; ks2 < 2; ks2++) {
                    const int ks = kc * 2 + ks2;
                    uint4 af[2]; uint2 bf[8];
#pragma unroll
                    for (int ma = 0; ma < 2; ma++)
                        af[ma] = *reinterpret_cast<const uint4*>(
                            smem + RF_AH + (((ks * 4) + wm * 2 + ma) * 32 + lane) * 16);
#pragma unroll
                    for (int na = 0; na < 8; na++)
                        bf[na] = *reinterpret_cast<const uint2*>(
                            smem + bcl + (((ks2 * 16) + wn * 8 + na) * 32 + lane) * 8);
#pragma unroll
                    for (int ma = 0; ma < 2; ma++)
#pragma unroll
                        for (int na = 0; na < 8; na++)
                            mma16(acc[ma][na], af[ma], bf[na]);
                }
                if (lane == 0) mbar_arrive(sb + RF_MB + 32 + scl * 8);
            }
#pragma unroll
            for (int ma = 0; ma < 2; ma++) {
                const int slo = ma * 2, shi = ma * 2 + 1;
#pragma unroll
                for (int na = 0; na < 8; na++) {
                    const int c0 = t * 128 + wn * 64 + na * 8 + (lane & 3) * 2;
                    float k00 = fmaf(-2.0f, acc[ma][na][0], cn[na * 2]);
                    float k01 = fmaf(-2.0f, acc[ma][na][1], cn[na * 2 + 1]);
                    float k10 = fmaf(-2.0f, acc[ma][na][2], cn[na * 2]);
                    float k11 = fmaf(-2.0f, acc[ma][na][3], cn[na * 2 + 1]);
                    if (k00 < bestv[slo]) { bestv[slo] = k00; besti[slo] = c0; }
                    if (k01 < bestv[slo]) { bestv[slo] = k01; besti[slo] = c0 + 1; }
                    if (k10 < bestv[shi]) { bestv[shi] = k10; besti[shi] = c0; }
                    if (k11 < bestv[shi]) { bestv[shi] = k11; besti[shi] = c0 + 1; }
                    acc[ma][na][0] = 0.0f; acc[ma][na][1] = 0.0f;
                    acc[ma][na][2] = 0.0f; acc[ma][na][3] = 0.0f;
                }
            }
        }
#pragma unroll
        for (int s = 0; s < 4; s++) {
            float v = bestv[s]; int bi = besti[s];
#pragma unroll
            for (int o = 1; o <= 2; o <<= 1) {
                float vo = __shfl_xor_sync(0xffffffffu, v, o);
                int   io = __shfl_xor_sync(0xffffffffu, bi, o);
                if (vo < v || (vo == v && io < bi)) { v = vo; bi = io; }
            }
            if ((lane & 3) == 0) {
                int row = wm * 32 + (s >> 1) * 16 + (s & 1) * 8 + (lane >> 2);
                reinterpret_cast<float*>(smem + RF_BV)[wn * 64 + row] = v;
                reinterpret_cast<int*>(smem + RF_BI)[wn * 64 + row]   = bi;
            }
        }
    } else {
        const int pw = wid - 4;
        uint32_t pe[4] = {0, 0, 0, 0};
        const int nchunks = nt * 8;
        for (int c = pw; c < nchunks; c += 2) {
            const int slot = c & 3;
            if (c >= 4) { mbar_wait(sb + RF_MB + 32 + slot * 8, pe[slot]); pe[slot] ^= 1; }
            const int t = c >> 3, r = c & 7, kc = r >> 1;
            const float* src = reinterpret_cast<const float*>((r & 1) ? g_cl : g_ch)
                             + ((size_t)(t * 4 + kc) << 11);
            const uint32_t dst = sb + RF_SLOT + (slot << 13);
#pragma unroll
            for (int i = 0; i < 16; i++)
                cp16(dst + (uint32_t)((i * 32 + lane) << 4), src + ((i * 32 + lane) << 2));
            cp_commit(); cp_wait0();
            mbar_arrive(sb + RF_MB + slot * 8);
        }
    }
    __syncthreads();

    if (tid < 64) {
        const float* bv = reinterpret_cast<const float*>(smem + RF_BV);
        const int*   bixs = reinterpret_cast<const int*>(smem + RF_BI);
        float v0 = bv[tid], v1 = bv[64 + tid];
        int i0 = bixs[tid], i1v = bixs[64 + tid];
        int bi = (v1 < v0 || (v1 == v0 && i1v < i0)) ? i1v : i0;
        g_idx[list[tid]] = bi;
    }
}

// ============ gather + loss ============
__global__ void gather_loss(const float* __restrict__ x, const float* __restrict__ codes,
                            float* __restrict__ out_q, float* __restrict__ out_idx, int write_idx)
{
    const int tid = threadIdx.x, txg = tid & 15, grp = tid >> 4;
    const int base = blockIdx.x * 128;
    float thr_loss = 0.0f;
    for (int rr = grp; rr < 128; rr += 16) {
        int row = base + rr;
        int bi = g_idx[row];
        if (txg == 0 && write_idx) out_idx[row] = (float)bi;
        const float4* cq = reinterpret_cast<const float4*>(codes + (size_t)bi * DDIM + txg * 8);
        float4 q0 = cq[0], q1 = cq[1];
        float4* od = reinterpret_cast<float4*>(out_q + (size_t)row * DDIM + txg * 8);
        od[0] = q0; od[1] = q1;
        const float4* xp = reinterpret_cast<const float4*>(x + (size_t)row * DDIM + txg * 8);
        float4 x0 = xp[0], x1 = xp[1];
        float d;
        d = x0.x - q0.x; thr_loss = fmaf(d, d, thr_loss);
        d = x0.y - q0.y; thr_loss = fmaf(d, d, thr_loss);
        d = x0.z - q0.z; thr_loss = fmaf(d, d, thr_loss);
        d = x0.w - q0.w; thr_loss = fmaf(d, d, thr_loss);
        d = x1.x - q1.x; thr_loss = fmaf(d, d, thr_loss);
        d = x1.y - q1.y; thr_loss = fmaf(d, d, thr_loss);
        d = x1.z - q1.z; thr_loss = fmaf(d, d, thr_loss);
        d = x1.w - q1.w; thr_loss = fmaf(d, d, thr_loss);
    }
    __shared__ float red[8];
#pragma unroll
    for (int o = 16; o; o >>= 1) thr_loss += __shfl_xor_sync(0xffffffffu, thr_loss, o);
    if ((tid & 31) == 0) red[tid >> 5] = thr_loss;
    __syncthreads();
    if (tid == 0) {
        float s = 0.0f;
#pragma unroll
        for (int w = 0; w < 8; w++) s += red[w];
        g_block_loss[blockIdx.x] = s;
    }
}

__global__ void finalize_kernel(float* __restrict__ out_loss, int nblocks, float invB)
{
    __shared__ float red[256];
    float s = 0.0f;
    for (int i = threadIdx.x; i < nblocks; i += 256) s += g_block_loss[i];
    red[threadIdx.x] = s;
    __syncthreads();
    for (int o = 128; o; o >>= 1) {
        if (threadIdx.x < o) red[threadIdx.x] += red[threadIdx.x + o];
        __syncthreads();
    }
    if (threadIdx.x == 0) *out_loss = 1.25f * red[0] * invB;  // (1 + BETA) * mean ||x-q||^2
}

extern "C" void kernel_launch(void* const* d_in, const int* in_sizes, int n_in,
                              void* d_out, int out_size)
{
    const float* x     = (const float*)d_in[0];
    const float* codes = (const float*)d_in[1];
    const int B = in_sizes[0] / DDIM;
    const int C = in_sizes[1] / DDIM;

    float* out      = (float*)d_out;
    float* out_q    = out;
    float* out_idx  = out + (size_t)B * DDIM;
    float* out_loss = out + (size_t)B * DDIM + B;

    const long long need_idx  = (long long)B * DDIM + B;
    const long long need_loss = need_idx + 1;
    const int write_idx  = ((long long)out_size >= need_idx)  ? 1 : 0;
    const int write_loss = ((long long)out_size >= need_loss) ? 1 : 0;

    (void)cudaFuncSetAttribute(vq_pass1,  cudaFuncAttributeMaxDynamicSharedMemorySize, SMEM_P1);
    (void)cudaFuncSetAttribute(vq_refine, cudaFuncAttributeMaxDynamicSharedMemorySize, SMEM_RF);

    split_x<<<B / 8, 256>>>(x);
    split_c<<<C / 8, 256>>>(codes);
    vq_pass1<<<B / BM, TPB, SMEM_P1>>>(C);
    vq_refine<<<B / BM, TPB, SMEM_RF>>>(x, C);
    gather_loss<<<B / 128, 256>>>(x, codes, out_q, out_idx, write_idx);
    if (write_loss)
        finalize_kernel<<<1, 256>>>(out_loss, B / 128, 1.0f / (float)B);
}

// round 9
// speedup vs baseline: 5.4189x; 1.0732x over previous
#include <cuda_runtime.h>
#include <cuda_fp16.h>
#include <math_constants.h>
#include <cstdint>

// Quantizer_33036888441545 — VQ argmin via hh-screen + exact 3xfp16 refine (C-split refine).
// x: [65536,128] f32, codes: [4096,128] f32. out: q[B*128], idx[B], loss[1].

#define DDIM 128
#define BM   64
#define TPB  192
#define MAXB 65536
#define MAXC 4096
#define NSEG 4

__device__ __half    g_xh[MAXB * DDIM];
__device__ __half    g_xl[MAXB * DDIM];
__device__ __half    g_ch[MAXC * DDIM];
__device__ __half    g_cl[MAXC * DDIM];
__device__ float     g_cnorm[MAXC];
__device__ float     g_xhn[MAXB];
__device__ float     g_xln[MAXB];
__device__ unsigned  g_clmax;
__device__ unsigned  g_chmax;
__device__ int       g_idx[MAXB];
__device__ int       g_undec[MAXB];
__device__ int       g_count;
__device__ float     g_rv[NSEG * MAXB];
__device__ int       g_ri[NSEG * MAXB];
__device__ float     g_block_loss[1024];

// ---- pass1 smem map ----
#define P1_AH    0          // 16KB A-hi frags
#define P1_SLOT  16384      // 4 x 8KB ch ring
#define P1_MB    49152      // full[4] @+0..31, empty[4] @+32..63
#define P1_M1    49216      // float [2][64]
#define P1_M2    49728
#define P1_I1    50240
#define SMEM_P1  50752

// ---- refine smem map ----
#define RF_AH    0
#define RF_AL    16384
#define RF_SLOT  32768      // 4 x 8KB ring (ch/cl)
#define RF_MB    65536
#define RF_BV    65600      // float [2][64]
#define RF_BI    66112
#define RF_LIST  66624      // int [64]
#define SMEM_RF  66880

// ============ helpers ============
__device__ __forceinline__ uint32_t smem_u32(const void* p) {
    uint32_t a;
    asm("{ .reg .u64 t; cvta.to.shared.u64 t, %1; cvt.u32.u64 %0, t; }" : "=r"(a) : "l"(p));
    return a;
}
__device__ __forceinline__ void mbar_init(uint32_t a, uint32_t cnt) {
    asm volatile("mbarrier.init.shared.b64 [%0], %1;" :: "r"(a), "r"(cnt) : "memory");
}
__device__ __forceinline__ void mbar_arrive(uint32_t a) {
    asm volatile("mbarrier.arrive.shared.b64 _, [%0];" :: "r"(a) : "memory");
}
__device__ __forceinline__ void mbar_wait(uint32_t a, uint32_t parity) {
    uint32_t done = 0;
    while (!done) {
        asm volatile(
            "{ .reg .pred p; mbarrier.try_wait.parity.acquire.cta.shared::cta.b64 p, [%1], %2, 0x989680; selp.b32 %0,1,0,p; }"
            : "=r"(done) : "r"(a), "r"(parity) : "memory");
    }
}
__device__ __forceinline__ void cp16(uint32_t dst, const float* src) {
    asm volatile("cp.async.cg.shared.global [%0], [%1], 16;" :: "r"(dst), "l"(src) : "memory");
}
__device__ __forceinline__ void cp_commit() { asm volatile("cp.async.commit_group;" ::: "memory"); }
__device__ __forceinline__ void cp_wait0()  { asm volatile("cp.async.wait_group 0;"  ::: "memory"); }

__device__ __forceinline__ void mma16(float* c, const uint4& a, const uint2& b) {
    asm volatile(
        "mma.sync.aligned.m16n8k16.row.col.f32.f16.f16.f32 "
        "{%0,%1,%2,%3}, {%4,%5,%6,%7}, {%8,%9}, {%0,%1,%2,%3};"
        : "+f"(c[0]), "+f"(c[1]), "+f"(c[2]), "+f"(c[3])
        : "r"(a.x), "r"(a.y), "r"(a.z), "r"(a.w), "r"(b.x), "r"(b.y));
}

// A-frag half2-unit index within a 64-row block, for row mloc (0..63), even k.
__device__ __forceinline__ int a_frag_h2(int mloc, int k) {
    int ks = k >> 4, kk = k & 15, ma = mloc >> 4, r = mloc & 15;
    int lane = (r & 7) * 4 + ((kk & 7) >> 1);
    int reg  = ((kk >> 3) << 1) | (r >> 3);
    return ((ks * 4 + ma) * 32 + lane) * 4 + reg;
}

// ============ split_x: one warp per row; frags + row norms; resets ============
__global__ void split_x(const float* __restrict__ x)
{
    if (blockIdx.x == 0 && threadIdx.x == 0) { g_count = 0; g_clmax = 0u; g_chmax = 0u; }
    int row  = blockIdx.x * 8 + (threadIdx.x >> 5);
    int lane = threadIdx.x & 31;
    float4 v = reinterpret_cast<const float4*>(x)[(size_t)row * 32 + lane];
    float vv[4] = {v.x, v.y, v.z, v.w};
    __half h[4]; float l[4];
    float hs = 0.0f, ls = 0.0f;
#pragma unroll
    for (int j = 0; j < 4; j++) {
        h[j] = __float2half_rn(vv[j]);
        float hf = __half2float(h[j]);
        l[j] = vv[j] - hf;
        hs = fmaf(hf, hf, hs);
        ls = fmaf(l[j], l[j], ls);
    }
    int blk = row >> 6, mloc = row & 63;
    __half2* xh2 = reinterpret_cast<__half2*>(g_xh) + (size_t)blk * 4096;
    __half2* xl2 = reinterpret_cast<__half2*>(g_xl) + (size_t)blk * 4096;
#pragma unroll
    for (int p = 0; p < 2; p++) {
        int k = lane * 4 + p * 2;
        int u = a_frag_h2(mloc, k);
        xh2[u] = __halves2half2(h[p * 2], h[p * 2 + 1]);
        xl2[u] = __halves2half2(__float2half_rn(l[p * 2]), __float2half_rn(l[p * 2 + 1]));
    }
#pragma unroll
    for (int o = 16; o; o >>= 1) {
        hs += __shfl_xor_sync(0xffffffffu, hs, o);
        ls += __shfl_xor_sync(0xffffffffu, ls, o);
    }
    if (lane == 0) { g_xhn[row] = sqrtf(hs); g_xln[row] = sqrtf(ls); }
}

// ============ split_c: one warp per code; frags + cnorm + max split-norms ============
__global__ void split_c(const float* __restrict__ codes)
{
    int n    = blockIdx.x * 8 + (threadIdx.x >> 5);
    int lane = threadIdx.x & 31;
    float4 v = reinterpret_cast<const float4*>(codes)[(size_t)n * 32 + lane];
    float vv[4] = {v.x, v.y, v.z, v.w};
    __half h[4]; float l[4];
    float cs = 0.0f, hs = 0.0f, ls = 0.0f;
#pragma unroll
    for (int j = 0; j < 4; j++) {
        h[j] = __float2half_rn(vv[j]);
        float hf = __half2float(h[j]);
        l[j] = vv[j] - hf;
        cs = fmaf(vv[j], vv[j], cs);
        hs = fmaf(hf, hf, hs);
        ls = fmaf(l[j], l[j], ls);
    }
    int t = n >> 7, nloc = n & 127, na = nloc >> 3;
    __half2* ch2 = reinterpret_cast<__half2*>(g_ch);
    __half2* cl2 = reinterpret_cast<__half2*>(g_cl);
#pragma unroll
    for (int p = 0; p < 2; p++) {
        int k = lane * 4 + p * 2;
        int kc = k >> 5, ks2 = (k >> 4) & 1, kk = k & 15;
        int lane_f = (nloc & 7) * 4 + ((kk & 7) >> 1);
        int reg    = kk >> 3;
        size_t u = ((((size_t)(t * 4 + kc) * 2 + ks2) * 16 + na) * 32 + lane_f) * 2 + reg;
        ch2[u] = __halves2half2(h[p * 2], h[p * 2 + 1]);
        cl2[u] = __halves2half2(__float2half_rn(l[p * 2]), __float2half_rn(l[p * 2 + 1]));
    }
#pragma unroll
    for (int o = 16; o; o >>= 1) {
        cs += __shfl_xor_sync(0xffffffffu, cs, o);
        hs += __shfl_xor_sync(0xffffffffu, hs, o);
        ls += __shfl_xor_sync(0xffffffffu, ls, o);
    }
    if (lane == 0) {
        g_cnorm[n] = cs;
        atomicMax(&g_chmax, __float_as_uint(sqrtf(hs)));
        atomicMax(&g_clmax, __float_as_uint(sqrtf(ls)));
    }
}

// ============ pass1: hh-only GEMM, min1/min2/idx per row, decide/append ============
__global__ __launch_bounds__(TPB, 2)
void vq_pass1(int C)
{
    extern __shared__ char smem[];
    const uint32_t sb = smem_u32(smem);
    const int tid = threadIdx.x, wid = tid >> 5, lane = tid & 31;
    const int row0 = blockIdx.x * BM;
    const int nt = C >> 7;

    if (tid == 0) {
#pragma unroll
        for (int s = 0; s < 4; s++) {
            mbar_init(sb + P1_MB + s * 8, 32);
            mbar_init(sb + P1_MB + 32 + s * 8, 4);
        }
    }
    {   // resident A-hi (16KB)
        const float* srch = reinterpret_cast<const float*>(g_xh) + (size_t)blockIdx.x * 4096;
        for (int i = tid; i < 1024; i += TPB) cp16(sb + P1_AH + i * 16, srch + i * 4);
        cp_commit(); cp_wait0();
    }
    __syncthreads();

    if (wid < 4) {
        const int wm = wid >> 1, wn = wid & 1;
        float acc[2][8][4];
#pragma unroll
        for (int a = 0; a < 2; a++)
#pragma unroll
            for (int b = 0; b < 8; b++)
#pragma unroll
                for (int r = 0; r < 4; r++) acc[a][b][r] = 0.0f;
        float m1[4], m2[4]; int i1[4];
#pragma unroll
        for (int s = 0; s < 4; s++) { m1[s] = CUDART_INF_F; m2[s] = CUDART_INF_F; i1[s] = 0; }
        uint32_t pf[4] = {0, 0, 0, 0};

        for (int t = 0; t < nt; t++) {
            float cn[16];
            const int cb = t * 128 + wn * 64 + (lane & 3) * 2;
#pragma unroll
            for (int na = 0; na < 8; na++) {
                cn[na * 2]     = __ldg(&g_cnorm[cb + na * 8]);
                cn[na * 2 + 1] = __ldg(&g_cnorm[cb + na * 8 + 1]);
            }
#pragma unroll 1
            for (int kc = 0; kc < 4; kc++) {
                const int slot = kc;
                const uint32_t bch = (uint32_t)(P1_SLOT + (slot << 13));
                mbar_wait(sb + P1_MB + slot * 8, pf[slot]); pf[slot] ^= 1;
#pragma unroll
                for (int ks2 = 0; ks2 < 2; ks2++) {
                    const int ks = kc * 2 + ks2;
                    uint4 af[2]; uint2 bf[8];
#pragma unroll
                    for (int ma = 0; ma < 2; ma++)
                        af[ma] = *reinterpret_cast<const uint4*>(
                            smem + P1_AH + (((ks * 4) + wm * 2 + ma) * 32 + lane) * 16);
#pragma unroll
                    for (int na = 0; na < 8; na++)
                        bf[na] = *reinterpret_cast<const uint2*>(
                            smem + bch + (((ks2 * 16) + wn * 8 + na) * 32 + lane) * 8);
#pragma unroll
                    for (int ma = 0; ma < 2; ma++)
#pragma unroll
                        for (int na = 0; na < 8; na++)
                            mma16(acc[ma][na], af[ma], bf[na]);
                }
                if (lane == 0) mbar_arrive(sb + P1_MB + 32 + slot * 8);
            }
#pragma unroll
            for (int ma = 0; ma < 2; ma++) {
                const int slo = ma * 2, shi = ma * 2 + 1;
#pragma unroll
                for (int na = 0; na < 8; na++) {
                    const int c0 = t * 128 + wn * 64 + na * 8 + (lane & 3) * 2;
                    float k00 = fmaf(-2.0f, acc[ma][na][0], cn[na * 2]);
                    float k01 = fmaf(-2.0f, acc[ma][na][1], cn[na * 2 + 1]);
                    float k10 = fmaf(-2.0f, acc[ma][na][2], cn[na * 2]);
                    float k11 = fmaf(-2.0f, acc[ma][na][3], cn[na * 2 + 1]);
                    {
                        bool p = k00 < m1[slo];
                        m2[slo] = p ? m1[slo] : fminf(m2[slo], k00);
                        i1[slo] = p ? c0 : i1[slo];
                        m1[slo] = p ? k00 : m1[slo];
                    }
                    {
                        bool p = k01 < m1[slo];
                        m2[slo] = p ? m1[slo] : fminf(m2[slo], k01);
                        i1[slo] = p ? (c0 + 1) : i1[slo];
                        m1[slo] = p ? k01 : m1[slo];
                    }
                    {
                        bool p = k10 < m1[shi];
                        m2[shi] = p ? m1[shi] : fminf(m2[shi], k10);
                        i1[shi] = p ? c0 : i1[shi];
                        m1[shi] = p ? k10 : m1[shi];
                    }
                    {
                        bool p = k11 < m1[shi];
                        m2[shi] = p ? m1[shi] : fminf(m2[shi], k11);
                        i1[shi] = p ? (c0 + 1) : i1[shi];
                        m1[shi] = p ? k11 : m1[shi];
                    }
                    acc[ma][na][0] = 0.0f; acc[ma][na][1] = 0.0f;
                    acc[ma][na][2] = 0.0f; acc[ma][na][3] = 0.0f;
                }
            }
        }
#pragma unroll
        for (int s = 0; s < 4; s++) {
            float v1 = m1[s], v2 = m2[s]; int ii = i1[s];
#pragma unroll
            for (int o = 1; o <= 2; o <<= 1) {
                float a1 = __shfl_xor_sync(0xffffffffu, v1, o);
                float a2 = __shfl_xor_sync(0xffffffffu, v2, o);
                int   ai = __shfl_xor_sync(0xffffffffu, ii, o);
                bool bwin = (a1 < v1) || (a1 == v1 && ai < ii);
                float loser1 = bwin ? v1 : a1;
                v2 = fminf(fminf(v2, a2), loser1);
                v1 = bwin ? a1 : v1;
                ii = bwin ? ai : ii;
            }
            if ((lane & 3) == 0) {
                int row = wm * 32 + (s >> 1) * 16 + (s & 1) * 8 + (lane >> 2);
                reinterpret_cast<float*>(smem + P1_M1)[wn * 64 + row] = v1;
                reinterpret_cast<float*>(smem + P1_M2)[wn * 64 + row] = v2;
                reinterpret_cast<int*>(smem + P1_I1)[wn * 64 + row]   = ii;
            }
        }
    } else {
        const int pw = wid - 4;
        uint32_t pe[4] = {0, 0, 0, 0};
        const int nchunks = nt * 4;
        for (int c = pw; c < nchunks; c += 2) {
            const int slot = c & 3;
            if (c >= 4) { mbar_wait(sb + P1_MB + 32 + slot * 8, pe[slot]); pe[slot] ^= 1; }
            const float* src = reinterpret_cast<const float*>(g_ch) + ((size_t)c << 11);
            const uint32_t dst = sb + P1_SLOT + (slot << 13);
#pragma unroll
            for (int i = 0; i < 16; i++)
                cp16(dst + (uint32_t)((i * 32 + lane) << 4), src + ((i * 32 + lane) << 2));
            cp_commit(); cp_wait0();
            mbar_arrive(sb + P1_MB + slot * 8);
        }
    }
    __syncthreads();

    if (tid < 64) {
        const float* sm1 = reinterpret_cast<const float*>(smem + P1_M1);
        const float* sm2 = reinterpret_cast<const float*>(smem + P1_M2);
        const int*   si1 = reinterpret_cast<const int*>(smem + P1_I1);
        float v1 = sm1[tid], v2 = sm2[tid]; int ii = si1[tid];
        float b1 = sm1[64 + tid], b2 = sm2[64 + tid]; int bi = si1[64 + tid];
        bool bwin = (b1 < v1) || (b1 == v1 && bi < ii);
        float loser1 = bwin ? v1 : b1;
        float m2f = fminf(fminf(v2, b2), loser1);
        float m1f = bwin ? b1 : v1;
        int   idx = bwin ? bi : ii;
        int grow = row0 + tid;
        g_idx[grow] = idx;
        float xhn = g_xhn[grow], xln = g_xln[grow];
        float clm = __uint_as_float(g_clmax), chm = __uint_as_float(g_chmax);
        float eb = xhn * clm + xln * chm + xln * clm;
        float thr = 5.0f * eb + 0.125f;
        if (!((m2f - m1f) > thr)) {
            int p = atomicAdd(&g_count, 1);
            g_undec[p] = grow;
        }
    }
}

// ============ refine: exact 3-pass, C split into NSEG segments ============
__global__ __launch_bounds__(TPB, 2)
void vq_refine(const float* __restrict__ x, int C)
{
    const int cnt = *(volatile int*)&g_count;
    const int rg  = blockIdx.x >> 2;          // row group
    const int seg = blockIdx.x & 3;           // code segment
    if (rg * 64 >= cnt) return;

    extern __shared__ char smem[];
    const uint32_t sb = smem_u32(smem);
    const int tid = threadIdx.x, wid = tid >> 5, lane = tid & 31;
    const int ntseg = (C >> 7) / NSEG;        // tiles per segment (8)
    const int t0 = seg * ntseg;

    if (tid == 0) {
#pragma unroll
        for (int s = 0; s < 4; s++) {
            mbar_init(sb + RF_MB + s * 8, 32);
            mbar_init(sb + RF_MB + 32 + s * 8, 4);
        }
    }
    // row list
    int* list = reinterpret_cast<int*>(smem + RF_LIST);
    if (tid < 64) {
        int li = rg * 64 + tid;
        list[tid] = g_undec[(li < cnt) ? li : (cnt - 1)];
    }
    __syncthreads();
    // A-pack from x: 128 threads, 2 per row (16 float4 each)
    if (tid < 128) {
        int r_loc = tid >> 1, half = tid & 1;
        int r = list[r_loc];
        const float4* xp = reinterpret_cast<const float4*>(x + (size_t)r * DDIM) + half * 16;
        __half2* ah = reinterpret_cast<__half2*>(smem + RF_AH);
        __half2* al = reinterpret_cast<__half2*>(smem + RF_AL);
#pragma unroll 4
        for (int qq = 0; qq < 16; qq++) {
            int q = half * 16 + qq;
            float4 v = xp[qq];
            float vv[4] = {v.x, v.y, v.z, v.w};
            __half h[4]; __half l[4];
#pragma unroll
            for (int j = 0; j < 4; j++) {
                h[j] = __float2half_rn(vv[j]);
                l[j] = __float2half_rn(vv[j] - __half2float(h[j]));
            }
#pragma unroll
            for (int p = 0; p < 2; p++) {
                int k = q * 4 + p * 2;
                int u = a_frag_h2(r_loc, k);
                ah[u] = __halves2half2(h[p * 2], h[p * 2 + 1]);
                al[u] = __halves2half2(l[p * 2], l[p * 2 + 1]);
            }
        }
    }
    __syncthreads();

    if (wid < 4) {
        const int wm = wid >> 1, wn = wid & 1;
        float acc[2][8][4];
#pragma unroll
        for (int a = 0; a < 2; a++)
#pragma unroll
            for (int b = 0; b < 8; b++)
#pragma unroll
                for (int r = 0; r < 4; r++) acc[a][b][r] = 0.0f;
        float bestv[4]; int besti[4];
#pragma unroll
        for (int s = 0; s < 4; s++) { bestv[s] = CUDART_INF_F; besti[s] = 0; }
        uint32_t pf[4] = {0, 0, 0, 0};

        for (int tt = 0; tt < ntseg; tt++) {
            const int t = t0 + tt;
            float cn[16];
            const int cb = t * 128 + wn * 64 + (lane & 3) * 2;
#pragma unroll
            for (int na = 0; na < 8; na++) {
                cn[na * 2]     = __ldg(&g_cnorm[cb + na * 8]);
                cn[na * 2 + 1] = __ldg(&g_cnorm[cb + na * 8 + 1]);
            }
#pragma unroll 1
            for (int kc = 0; kc < 4; kc++) {
                const int sch = (kc * 2) & 3, scl = sch + 1;
                const uint32_t bch = (uint32_t)(RF_SLOT + (sch << 13));
                const uint32_t bcl = (uint32_t)(RF_SLOT + (scl << 13));
                mbar_wait(sb + RF_MB + sch * 8, pf[sch]); pf[sch] ^= 1;
#pragma unroll
                for (int pass = 0; pass < 2; pass++) {
                    const uint32_t abase = pass ? RF_AL : RF_AH;
#pragma unroll
                    for (int ks2 = 0; ks2 < 2; ks2++) {
                        const int ks = kc * 2 + ks2;
                        uint4 af[2]; uint2 bf[8];
#pragma unroll
                        for (int ma = 0; ma < 2; ma++)
                            af[ma] = *reinterpret_cast<const uint4*>(
                                smem + abase + (((ks * 4) + wm * 2 + ma) * 32 + lane) * 16);
#pragma unroll
                        for (int na = 0; na < 8; na++)
                            bf[na] = *reinterpret_cast<const uint2*>(
                                smem + bch + (((ks2 * 16) + wn * 8 + na) * 32 + lane) * 8);
#pragma unroll
                        for (int ma = 0; ma < 2; ma++)
#pragma unroll
                            for (int na = 0; na < 8; na++)
                                mma16(acc[ma][na], af[ma], bf[na]);
                    }
                }
                if (lane == 0) mbar_arrive(sb + RF_MB + 32 + sch * 8);

                mbar_wait(sb + RF_MB + scl * 8, pf[scl]); pf[scl] ^= 1;
#pragma unroll
                for (int ks2 = 0; ks2 < 2; ks2++) {
                    const int ks = kc * 2 + ks2;
                    uint4 af[2]; uint2 bf[8];
#pragma unroll
                    for (int ma = 0; ma < 2; ma++)
                        af[ma] = *reinterpret_cast<const uint4*>(
                            smem + RF_AH + (((ks * 4) + wm * 2 + ma) * 32 + lane) * 16);
#pragma unroll
                    for (int na = 0; na < 8; na++)
                        bf[na] = *reinterpret_cast<const uint2*>(
                            smem + bcl + (((ks2 * 16) + wn * 8 + na) * 32 + lane) * 8);
#pragma unroll
                    for (int ma = 0; ma < 2; ma++)
#pragma unroll
                        for (int na = 0; na < 8; na++)
                            mma16(acc[ma][na], af[ma], bf[na]);
                }
                if (lane == 0) mbar_arrive(sb + RF_MB + 32 + scl * 8);
            }
#pragma unroll
            for (int ma = 0; ma < 2; ma++) {
                const int slo = ma * 2, shi = ma * 2 + 1;
#pragma unroll
                for (int na = 0; na < 8; na++) {
                    const int c0 = t * 128 + wn * 64 + na * 8 + (lane & 3) * 2;
                    float k00 = fmaf(-2.0f, acc[ma][na][0], cn[na * 2]);
                    float k01 = fmaf(-2.0f, acc[ma][na][1], cn[na * 2 + 1]);
                    float k10 = fmaf(-2.0f, acc[ma][na][2], cn[na * 2]);
                    float k11 = fmaf(-2.0f, acc[ma][na][3], cn[na * 2 + 1]);
                    if (k00 < bestv[slo]) { bestv[slo] = k00; besti[slo] = c0; }
                    if (k01 < bestv[slo]) { bestv[slo] = k01; besti[slo] = c0 + 1; }
                    if (k10 < bestv[shi]) { bestv[shi] = k10; besti[shi] = c0; }
                    if (k11 < bestv[shi]) { bestv[shi] = k11; besti[shi] = c0 + 1; }
                    acc[ma][na][0] = 0.0f; acc[ma][na][1] = 0.0f;
                    acc[ma][na][2] = 0.0f; acc[ma][na][3] = 0.0f;
                }
            }
        }
#pragma unroll
        for (int s = 0; s < 4; s++) {
            float v = bestv[s]; int bi = besti[s];
#pragma unroll
            for (int o = 1; o <= 2; o <<= 1) {
                float vo = __shfl_xor_sync(0xffffffffu, v, o);
                int   io = __shfl_xor_sync(0xffffffffu, bi, o);
                if (vo < v || (vo == v && io < bi)) { v = vo; bi = io; }
            }
            if ((lane & 3) == 0) {
                int row = wm * 32 + (s >> 1) * 16 + (s & 1) * 8 + (lane >> 2);
                reinterpret_cast<float*>(smem + RF_BV)[wn * 64 + row] = v;
                reinterpret_cast<int*>(smem + RF_BI)[wn * 64 + row]   = bi;
            }
        }
    } else {
        const int pw = wid - 4;
        uint32_t pe[4] = {0, 0, 0, 0};
        const int nchunks = ntseg * 8;
        for (int c = pw; c < nchunks; c += 2) {
            const int slot = c & 3;
            if (c >= 4) { mbar_wait(sb + RF_MB + 32 + slot * 8, pe[slot]); pe[slot] ^= 1; }
            const int t = t0 + (c >> 3), r = c & 7, kc = r >> 1;
            const float* src = reinterpret_cast<const float*>((r & 1) ? g_cl : g_ch)
                             + ((size_t)(t * 4 + kc) << 11);
            const uint32_t dst = sb + RF_SLOT + (slot << 13);
#pragma unroll
            for (int i = 0; i < 16; i++)
                cp16(dst + (uint32_t)((i * 32 + lane) << 4), src + ((i * 32 + lane) << 2));
            cp_commit(); cp_wait0();
            mbar_arrive(sb + RF_MB + slot * 8);
        }
    }
    __syncthreads();

    if (tid < 64) {
        const float* bv = reinterpret_cast<const float*>(smem + RF_BV);
        const int*   bixs = reinterpret_cast<const int*>(smem + RF_BI);
        float v0 = bv[tid], v1 = bv[64 + tid];
        int i0 = bixs[tid], i1v = bixs[64 + tid];
        int bi = (v1 < v0 || (v1 == v0 && i1v < i0)) ? i1v : i0;
        float vv = (v1 < v0 || (v1 == v0 && i1v < i0)) ? v1 : v0;
        int li = rg * 64 + tid;
        g_rv[seg * MAXB + li] = vv;
        g_ri[seg * MAXB + li] = bi;
    }
}

// ============ merge refine segments ============
__global__ void merge_refine()
{
    const int cnt = *(volatile int*)&g_count;
    int li = blockIdx.x * 256 + threadIdx.x;
    if (li >= cnt) return;
    float v = g_rv[li]; int bi = g_ri[li];
#pragma unroll
    for (int s = 1; s < NSEG; s++) {
        float vo = g_rv[s * MAXB + li];
        int   io = g_ri[s * MAXB + li];
        if (vo < v) { v = vo; bi = io; }   // segments index-ordered; strict < keeps first-min
    }
    g_idx[g_undec[li]] = bi;
}

// ============ gather + loss ============
__global__ void gather_loss(const float* __restrict__ x, const float* __restrict__ codes,
                            float* __restrict__ out_q, float* __restrict__ out_idx, int write_idx)
{
    const int tid = threadIdx.x, txg = tid & 15, grp = tid >> 4;
    const int base = blockIdx.x * 128;
    float thr_loss = 0.0f;
    for (int rr = grp; rr < 128; rr += 16) {
        int row = base + rr;
        int bi = g_idx[row];
        if (txg == 0 && write_idx) out_idx[row] = (float)bi;
        const float4* cq = reinterpret_cast<const float4*>(codes + (size_t)bi * DDIM + txg * 8);
        float4 q0 = cq[0], q1 = cq[1];
        float4* od = reinterpret_cast<float4*>(out_q + (size_t)row * DDIM + txg * 8);
        od[0] = q0; od[1] = q1;
        const float4* xp = reinterpret_cast<const float4*>(x + (size_t)row * DDIM + txg * 8);
        float4 x0 = xp[0], x1 = xp[1];
        float d;
        d = x0.x - q0.x; thr_loss = fmaf(d, d, thr_loss);
        d = x0.y - q0.y; thr_loss = fmaf(d, d, thr_loss);
        d = x0.z - q0.z; thr_loss = fmaf(d, d, thr_loss);
        d = x0.w - q0.w; thr_loss = fmaf(d, d, thr_loss);
        d = x1.x - q1.x; thr_loss = fmaf(d, d, thr_loss);
        d = x1.y - q1.y; thr_loss = fmaf(d, d, thr_loss);
        d = x1.z - q1.z; thr_loss = fmaf(d, d, thr_loss);
        d = x1.w - q1.w; thr_loss = fmaf(d, d, thr_loss);
    }
    __shared__ float red[8];
#pragma unroll
    for (int o = 16; o; o >>= 1) thr_loss += __shfl_xor_sync(0xffffffffu, thr_loss, o);
    if ((tid & 31) == 0) red[tid >> 5] = thr_loss;
    __syncthreads();
    if (tid == 0) {
        float s = 0.0f;
#pragma unroll
        for (int w = 0; w < 8; w++) s += red[w];
        g_block_loss[blockIdx.x] = s;
    }
}

__global__ void finalize_kernel(float* __restrict__ out_loss, int nblocks, float invB)
{
    __shared__ float red[256];
    float s = 0.0f;
    for (int i = threadIdx.x; i < nblocks; i += 256) s += g_block_loss[i];
    red[threadIdx.x] = s;
    __syncthreads();
    for (int o = 128; o; o >>= 1) {
        if (threadIdx.x < o) red[threadIdx.x] += red[threadIdx.x + o];
        __syncthreads();
    }
    if (threadIdx.x == 0) *out_loss = 1.25f * red[0] * invB;  // (1 + BETA) * mean ||x-q||^2
}

extern "C" void kernel_launch(void* const* d_in, const int* in_sizes, int n_in,
                              void* d_out, int out_size)
{
    const float* x     = (const float*)d_in[0];
    const float* codes = (const float*)d_in[1];
    const int B = in_sizes[0] / DDIM;
    const int C = in_sizes[1] / DDIM;

    float* out      = (float*)d_out;
    float* out_q    = out;
    float* out_idx  = out + (size_t)B * DDIM;
    float* out_loss = out + (size_t)B * DDIM + B;

    const long long need_idx  = (long long)B * DDIM + B;
    const long long need_loss = need_idx + 1;
    const int write_idx  = ((long long)out_size >= need_idx)  ? 1 : 0;
    const int write_loss = ((long long)out_size >= need_loss) ? 1 : 0;

    (void)cudaFuncSetAttribute(vq_pass1,  cudaFuncAttributeMaxDynamicSharedMemorySize, SMEM_P1);
    (void)cudaFuncSetAttribute(vq_refine, cudaFuncAttributeMaxDynamicSharedMemorySize, SMEM_RF);

    split_x<<<B / 8, 256>>>(x);
    split_c<<<C / 8, 256>>>(codes);
    vq_pass1<<<B / BM, TPB, SMEM_P1>>>(C);
    vq_refine<<<(B / BM) * NSEG, TPB, SMEM_RF>>>(x, C);
    merge_refine<<<B / 256, 256>>>();
    gather_loss<<<B / 128, 256>>>(x, codes, out_q, out_idx, write_idx);
    if (write_loss)
        finalize_kernel<<<1, 256>>>(out_loss, B / 128, 1.0f / (float)B);
}

// round 10
// speedup vs baseline: 5.5135x; 1.0175x over previous
#include <cuda_runtime.h>
#include <cuda_fp16.h>
#include <math_constants.h>
#include <cstdint>

// Quantizer_33036888441545 — VQ argmin via hh-screen (C-split) + exact 3xfp16 refine (C-split).
// x: [65536,128] f32, codes: [4096,128] f32. out: q[B*128], idx[B], loss[1].

#define DDIM 128
#define BM   64
#define TPB  192
#define MAXB 65536
#define MAXC 4096
#define NSEG_P1 2
#define NSEG_RF 8

__device__ __half    g_xh[MAXB * DDIM];
__device__ __half    g_xl[MAXB * DDIM];
__device__ __half    g_ch[MAXC * DDIM];
__device__ __half    g_cl[MAXC * DDIM];
__device__ float     g_cnorm[MAXC];
__device__ float     g_xhn[MAXB];
__device__ float     g_xln[MAXB];
__device__ unsigned  g_clmax;
__device__ unsigned  g_chmax;
__device__ int       g_idx[MAXB];
__device__ int       g_undec[MAXB];
__device__ int       g_count;
__device__ float     g_p1v1[NSEG_P1 * MAXB];
__device__ float     g_p1v2[NSEG_P1 * MAXB];
__device__ int       g_p1i1[NSEG_P1 * MAXB];
__device__ float     g_rv[NSEG_RF * MAXB];
__device__ int       g_ri[NSEG_RF * MAXB];
__device__ float     g_block_loss[1024];

// ---- pass1 smem map ----
#define P1_AH    0          // 16KB A-hi frags
#define P1_SLOT  16384      // 4 x 8KB ch ring
#define P1_MB    49152      // full[4] @+0..31, empty[4] @+32..63
#define P1_M1    49216      // float [2][64]
#define P1_M2    49728
#define P1_I1    50240
#define SMEM_P1  50752

// ---- refine smem map ----
#define RF_AH    0
#define RF_AL    16384
#define RF_SLOT  32768      // 4 x 8KB ring (ch/cl)
#define RF_MB    65536
#define RF_BV    65600      // float [2][64]
#define RF_BI    66112
#define RF_LIST  66624      // int [64]
#define SMEM_RF  66880

// ============ helpers ============
__device__ __forceinline__ uint32_t smem_u32(const void* p) {
    uint32_t a;
    asm("{ .reg .u64 t; cvta.to.shared.u64 t, %1; cvt.u32.u64 %0, t; }" : "=r"(a) : "l"(p));
    return a;
}
__device__ __forceinline__ void mbar_init(uint32_t a, uint32_t cnt) {
    asm volatile("mbarrier.init.shared.b64 [%0], %1;" :: "r"(a), "r"(cnt) : "memory");
}
__device__ __forceinline__ void mbar_arrive(uint32_t a) {
    asm volatile("mbarrier.arrive.shared.b64 _, [%0];" :: "r"(a) : "memory");
}
__device__ __forceinline__ void mbar_wait(uint32_t a, uint32_t parity) {
    uint32_t done = 0;
    while (!done) {
        asm volatile(
            "{ .reg .pred p; mbarrier.try_wait.parity.acquire.cta.shared::cta.b64 p, [%1], %2, 0x989680; selp.b32 %0,1,0,p; }"
            : "=r"(done) : "r"(a), "r"(parity) : "memory");
    }
}
__device__ __forceinline__ void cp16(uint32_t dst, const float* src) {
    asm volatile("cp.async.cg.shared.global [%0], [%1], 16;" :: "r"(dst), "l"(src) : "memory");
}
__device__ __forceinline__ void cp_commit() { asm volatile("cp.async.commit_group;" ::: "memory"); }
__device__ __forceinline__ void cp_wait0()  { asm volatile("cp.async.wait_group 0;"  ::: "memory"); }

__device__ __forceinline__ void mma16(float* c, const uint4& a, const uint2& b) {
    asm volatile(
        "mma.sync.aligned.m16n8k16.row.col.f32.f16.f16.f32 "
        "{%0,%1,%2,%3}, {%4,%5,%6,%7}, {%8,%9}, {%0,%1,%2,%3};"
        : "+f"(c[0]), "+f"(c[1]), "+f"(c[2]), "+f"(c[3])
        : "r"(a.x), "r"(a.y), "r"(a.z), "r"(a.w), "r"(b.x), "r"(b.y));
}

// A-frag half2-unit index within a 64-row block, for row mloc (0..63), even k.
__device__ __forceinline__ int a_frag_h2(int mloc, int k) {
    int ks = k >> 4, kk = k & 15, ma = mloc >> 4, r = mloc & 15;
    int lane = (r & 7) * 4 + ((kk & 7) >> 1);
    int reg  = ((kk >> 3) << 1) | (r >> 3);
    return ((ks * 4 + ma) * 32 + lane) * 4 + reg;
}

// ============ split_x ============
__global__ void split_x(const float* __restrict__ x)
{
    if (blockIdx.x == 0 && threadIdx.x == 0) { g_count = 0; g_clmax = 0u; g_chmax = 0u; }
    int row  = blockIdx.x * 8 + (threadIdx.x >> 5);
    int lane = threadIdx.x & 31;
    float4 v = reinterpret_cast<const float4*>(x)[(size_t)row * 32 + lane];
    float vv[4] = {v.x, v.y, v.z, v.w};
    __half h[4]; float l[4];
    float hs = 0.0f, ls = 0.0f;
#pragma unroll
    for (int j = 0; j < 4; j++) {
        h[j] = __float2half_rn(vv[j]);
        float hf = __half2float(h[j]);
        l[j] = vv[j] - hf;
        hs = fmaf(hf, hf, hs);
        ls = fmaf(l[j], l[j], ls);
    }
    int blk = row >> 6, mloc = row & 63;
    __half2* xh2 = reinterpret_cast<__half2*>(g_xh) + (size_t)blk * 4096;
    __half2* xl2 = reinterpret_cast<__half2*>(g_xl) + (size_t)blk * 4096;
#pragma unroll
    for (int p = 0; p < 2; p++) {
        int k = lane * 4 + p * 2;
        int u = a_frag_h2(mloc, k);
        xh2[u] = __halves2half2(h[p * 2], h[p * 2 + 1]);
        xl2[u] = __halves2half2(__float2half_rn(l[p * 2]), __float2half_rn(l[p * 2 + 1]));
    }
#pragma unroll
    for (int o = 16; o; o >>= 1) {
        hs += __shfl_xor_sync(0xffffffffu, hs, o);
        ls += __shfl_xor_sync(0xffffffffu, ls, o);
    }
    if (lane == 0) { g_xhn[row] = sqrtf(hs); g_xln[row] = sqrtf(ls); }
}

// ============ split_c ============
__global__ void split_c(const float* __restrict__ codes)
{
    int n    = blockIdx.x * 8 + (threadIdx.x >> 5);
    int lane = threadIdx.x & 31;
    float4 v = reinterpret_cast<const float4*>(codes)[(size_t)n * 32 + lane];
    float vv[4] = {v.x, v.y, v.z, v.w};
    __half h[4]; float l[4];
    float cs = 0.0f, hs = 0.0f, ls = 0.0f;
#pragma unroll
    for (int j = 0; j < 4; j++) {
        h[j] = __float2half_rn(vv[j]);
        float hf = __half2float(h[j]);
        l[j] = vv[j] - hf;
        cs = fmaf(vv[j], vv[j], cs);
        hs = fmaf(hf, hf, hs);
        ls = fmaf(l[j], l[j], ls);
    }
    int t = n >> 7, nloc = n & 127, na = nloc >> 3;
    __half2* ch2 = reinterpret_cast<__half2*>(g_ch);
    __half2* cl2 = reinterpret_cast<__half2*>(g_cl);
#pragma unroll
    for (int p = 0; p < 2; p++) {
        int k = lane * 4 + p * 2;
        int kc = k >> 5, ks2 = (k >> 4) & 1, kk = k & 15;
        int lane_f = (nloc & 7) * 4 + ((kk & 7) >> 1);
        int reg    = kk >> 3;
        size_t u = ((((size_t)(t * 4 + kc) * 2 + ks2) * 16 + na) * 32 + lane_f) * 2 + reg;
        ch2[u] = __halves2half2(h[p * 2], h[p * 2 + 1]);
        cl2[u] = __halves2half2(__float2half_rn(l[p * 2]), __float2half_rn(l[p * 2 + 1]));
    }
#pragma unroll
    for (int o = 16; o; o >>= 1) {
        cs += __shfl_xor_sync(0xffffffffu, cs, o);
        hs += __shfl_xor_sync(0xffffffffu, hs, o);
        ls += __shfl_xor_sync(0xffffffffu, ls, o);
    }
    if (lane == 0) {
        g_cnorm[n] = cs;
        atomicMax(&g_chmax, __float_as_uint(sqrtf(hs)));
        atomicMax(&g_clmax, __float_as_uint(sqrtf(ls)));
    }
}

// ============ pass1: hh-only GEMM over one C-segment; per-(row,seg) top-2 to gmem ============
__global__ __launch_bounds__(TPB, 2)
void vq_pass1(int C)
{
    extern __shared__ char smem[];
    const uint32_t sb = smem_u32(smem);
    const int tid = threadIdx.x, wid = tid >> 5, lane = tid & 31;
    const int rb  = blockIdx.x >> 1;           // row block
    const int seg = blockIdx.x & 1;            // code segment
    const int row0 = rb * BM;
    const int ntseg = (C >> 7) / NSEG_P1;      // 16 tiles
    const int t0 = seg * ntseg;

    if (tid == 0) {
#pragma unroll
        for (int s = 0; s < 4; s++) {
            mbar_init(sb + P1_MB + s * 8, 32);
            mbar_init(sb + P1_MB + 32 + s * 8, 4);
        }
    }
    {   // resident A-hi (16KB)
        const float* srch = reinterpret_cast<const float*>(g_xh) + (size_t)rb * 4096;
        for (int i = tid; i < 1024; i += TPB) cp16(sb + P1_AH + i * 16, srch + i * 4);
        cp_commit(); cp_wait0();
    }
    __syncthreads();

    if (wid < 4) {
        const int wm = wid >> 1, wn = wid & 1;
        float acc[2][8][4];
#pragma unroll
        for (int a = 0; a < 2; a++)
#pragma unroll
            for (int b = 0; b < 8; b++)
#pragma unroll
                for (int r = 0; r < 4; r++) acc[a][b][r] = 0.0f;
        float m1[4], m2[4]; int i1[4];
#pragma unroll
        for (int s = 0; s < 4; s++) { m1[s] = CUDART_INF_F; m2[s] = CUDART_INF_F; i1[s] = 0; }
        uint32_t pf[4] = {0, 0, 0, 0};

        for (int tt = 0; tt < ntseg; tt++) {
            const int t = t0 + tt;
            float cn[16];
            const int cb = t * 128 + wn * 64 + (lane & 3) * 2;
#pragma unroll
            for (int na = 0; na < 8; na++) {
                cn[na * 2]     = __ldg(&g_cnorm[cb + na * 8]);
                cn[na * 2 + 1] = __ldg(&g_cnorm[cb + na * 8 + 1]);
            }
#pragma unroll 1
            for (int kc = 0; kc < 4; kc++) {
                const int slot = kc;
                const uint32_t bch = (uint32_t)(P1_SLOT + (slot << 13));
                mbar_wait(sb + P1_MB + slot * 8, pf[slot]); pf[slot] ^= 1;
#pragma unroll
                for (int ks2 = 0; ks2 < 2; ks2++) {
                    const int ks = kc * 2 + ks2;
                    uint4 af[2]; uint2 bf[8];
#pragma unroll
                    for (int ma = 0; ma < 2; ma++)
                        af[ma] = *reinterpret_cast<const uint4*>(
                            smem + P1_AH + (((ks * 4) + wm * 2 + ma) * 32 + lane) * 16);
#pragma unroll
                    for (int na = 0; na < 8; na++)
                        bf[na] = *reinterpret_cast<const uint2*>(
                            smem + bch + (((ks2 * 16) + wn * 8 + na) * 32 + lane) * 8);
#pragma unroll
                    for (int ma = 0; ma < 2; ma++)
#pragma unroll
                        for (int na = 0; na < 8; na++)
                            mma16(acc[ma][na], af[ma], bf[na]);
                }
                if (lane == 0) mbar_arrive(sb + P1_MB + 32 + slot * 8);
            }
#pragma unroll
            for (int ma = 0; ma < 2; ma++) {
                const int slo = ma * 2, shi = ma * 2 + 1;
#pragma unroll
                for (int na = 0; na < 8; na++) {
                    const int c0 = t * 128 + wn * 64 + na * 8 + (lane & 3) * 2;
                    float k00 = fmaf(-2.0f, acc[ma][na][0], cn[na * 2]);
                    float k01 = fmaf(-2.0f, acc[ma][na][1], cn[na * 2 + 1]);
                    float k10 = fmaf(-2.0f, acc[ma][na][2], cn[na * 2]);
                    float k11 = fmaf(-2.0f, acc[ma][na][3], cn[na * 2 + 1]);
                    {
                        bool p = k00 < m1[slo];
                        m2[slo] = p ? m1[slo] : fminf(m2[slo], k00);
                        i1[slo] = p ? c0 : i1[slo];
                        m1[slo] = p ? k00 : m1[slo];
                    }
                    {
                        bool p = k01 < m1[slo];
                        m2[slo] = p ? m1[slo] : fminf(m2[slo], k01);
                        i1[slo] = p ? (c0 + 1) : i1[slo];
                        m1[slo] = p ? k01 : m1[slo];
                    }
                    {
                        bool p = k10 < m1[shi];
                        m2[shi] = p ? m1[shi] : fminf(m2[shi], k10);
                        i1[shi] = p ? c0 : i1[shi];
                        m1[shi] = p ? k10 : m1[shi];
                    }
                    {
                        bool p = k11 < m1[shi];
                        m2[shi] = p ? m1[shi] : fminf(m2[shi], k11);
                        i1[shi] = p ? (c0 + 1) : i1[shi];
                        m1[shi] = p ? k11 : m1[shi];
                    }
                    acc[ma][na][0] = 0.0f; acc[ma][na][1] = 0.0f;
                    acc[ma][na][2] = 0.0f; acc[ma][na][3] = 0.0f;
                }
            }
        }
#pragma unroll
        for (int s = 0; s < 4; s++) {
            float v1 = m1[s], v2 = m2[s]; int ii = i1[s];
#pragma unroll
            for (int o = 1; o <= 2; o <<= 1) {
                float a1 = __shfl_xor_sync(0xffffffffu, v1, o);
                float a2 = __shfl_xor_sync(0xffffffffu, v2, o);
                int   ai = __shfl_xor_sync(0xffffffffu, ii, o);
                bool bwin = (a1 < v1) || (a1 == v1 && ai < ii);
                float loser1 = bwin ? v1 : a1;
                v2 = fminf(fminf(v2, a2), loser1);
                v1 = bwin ? a1 : v1;
                ii = bwin ? ai : ii;
            }
            if ((lane & 3) == 0) {
                int row = wm * 32 + (s >> 1) * 16 + (s & 1) * 8 + (lane >> 2);
                reinterpret_cast<float*>(smem + P1_M1)[wn * 64 + row] = v1;
                reinterpret_cast<float*>(smem + P1_M2)[wn * 64 + row] = v2;
                reinterpret_cast<int*>(smem + P1_I1)[wn * 64 + row]   = ii;
            }
        }
    } else {
        const int pw = wid - 4;
        uint32_t pe[4] = {0, 0, 0, 0};
        const int nchunks = ntseg * 4;
        for (int c = pw; c < nchunks; c += 2) {
            const int slot = c & 3;
            if (c >= 4) { mbar_wait(sb + P1_MB + 32 + slot * 8, pe[slot]); pe[slot] ^= 1; }
            const float* src = reinterpret_cast<const float*>(g_ch) + ((size_t)(t0 * 4 + c) << 11);
            const uint32_t dst = sb + P1_SLOT + (slot << 13);
#pragma unroll
            for (int i = 0; i < 16; i++)
                cp16(dst + (uint32_t)((i * 32 + lane) << 4), src + ((i * 32 + lane) << 2));
            cp_commit(); cp_wait0();
            mbar_arrive(sb + P1_MB + slot * 8);
        }
    }
    __syncthreads();

    // merge wn stripes -> per-(row,seg) top-2 out to gmem
    if (tid < 64) {
        const float* sm1 = reinterpret_cast<const float*>(smem + P1_M1);
        const float* sm2 = reinterpret_cast<const float*>(smem + P1_M2);
        const int*   si1 = reinterpret_cast<const int*>(smem + P1_I1);
        float v1 = sm1[tid], v2 = sm2[tid]; int ii = si1[tid];
        float b1 = sm1[64 + tid], b2 = sm2[64 + tid]; int bi = si1[64 + tid];
        bool bwin = (b1 < v1) || (b1 == v1 && bi < ii);
        float loser1 = bwin ? v1 : b1;
        float m2f = fminf(fminf(v2, b2), loser1);
        float m1f = bwin ? b1 : v1;
        int   idx = bwin ? bi : ii;
        int o = seg * MAXB + row0 + tid;
        g_p1v1[o] = m1f; g_p1v2[o] = m2f; g_p1i1[o] = idx;
    }
}

// ============ decide: merge pass1 segments, threshold, compact undecided ============
__global__ void decide_kernel()
{
    int row = blockIdx.x * 256 + threadIdx.x;
    float v1 = g_p1v1[row], v2 = g_p1v2[row]; int ii = g_p1i1[row];
    float b1 = g_p1v1[MAXB + row], b2 = g_p1v2[MAXB + row]; int bi = g_p1i1[MAXB + row];
    bool bwin = b1 < v1;                      // seg0 indices < seg1 indices: ties keep seg0
    float loser1 = bwin ? v1 : b1;
    float m2f = fminf(fminf(v2, b2), loser1);
    float m1f = bwin ? b1 : v1;
    int   idx = bwin ? bi : ii;
    g_idx[row] = idx;
    float xhn = g_xhn[row], xln = g_xln[row];
    float clm = __uint_as_float(g_clmax), chm = __uint_as_float(g_chmax);
    float eb = xhn * clm + xln * chm + xln * clm;
    float thr = 5.0f * eb + 0.125f;
    if (!((m2f - m1f) > thr)) {
        int p = atomicAdd(&g_count, 1);
        g_undec[p] = row;
    }
}

// ============ refine: exact 3-pass, C split into NSEG_RF segments ============
__global__ __launch_bounds__(TPB, 2)
void vq_refine(const float* __restrict__ x, int C)
{
    const int cnt = *(volatile int*)&g_count;
    const int rg  = blockIdx.x >> 3;          // row group
    const int seg = blockIdx.x & 7;           // code segment
    if (rg * 64 >= cnt) return;

    extern __shared__ char smem[];
    const uint32_t sb = smem_u32(smem);
    const int tid = threadIdx.x, wid = tid >> 5, lane = tid & 31;
    const int ntseg = (C >> 7) / NSEG_RF;     // 4 tiles
    const int t0 = seg * ntseg;

    if (tid == 0) {
#pragma unroll
        for (int s = 0; s < 4; s++) {
            mbar_init(sb + RF_MB + s * 8, 32);
            mbar_init(sb + RF_MB + 32 + s * 8, 4);
        }
    }
    int* list = reinterpret_cast<int*>(smem + RF_LIST);
    if (tid < 64) {
        int li = rg * 64 + tid;
        list[tid] = g_undec[(li < cnt) ? li : (cnt - 1)];
    }
    __syncthreads();
    if (tid < 128) {
        int r_loc = tid >> 1, half = tid & 1;
        int r = list[r_loc];
        const float4* xp = reinterpret_cast<const float4*>(x + (size_t)r * DDIM) + half * 16;
        __half2* ah = reinterpret_cast<__half2*>(smem + RF_AH);
        __half2* al = reinterpret_cast<__half2*>(smem + RF_AL);
#pragma unroll 4
        for (int qq = 0; qq < 16; qq++) {
            int q = half * 16 + qq;
            float4 v = xp[qq];
            float vv[4] = {v.x, v.y, v.z, v.w};
            __half h[4]; __half l[4];
#pragma unroll
            for (int j = 0; j < 4; j++) {
                h[j] = __float2half_rn(vv[j]);
                l[j] = __float2half_rn(vv[j] - __half2float(h[j]));
            }
#pragma unroll
            for (int p = 0; p < 2; p++) {
                int k = q * 4 + p * 2;
                int u = a_frag_h2(r_loc, k);
                ah[u] = __halves2half2(h[p * 2], h[p * 2 + 1]);
                al[u] = __halves2half2(l[p * 2], l[p * 2 + 1]);
            }
        }
    }
    __syncthreads();

    if (wid < 4) {
        const int wm = wid >> 1, wn = wid & 1;
        float acc[2][8][4];
#pragma unroll
        for (int a = 0; a < 2; a++)
#pragma unroll
            for (int b = 0; b < 8; b++)
#pragma unroll
                for (int r = 0; r < 4; r++) acc[a][b][r] = 0.0f;
        float bestv[4]; int besti[4];
#pragma unroll
        for (int s = 0; s < 4; s++) { bestv[s] = CUDART_INF_F; besti[s] = 0; }
        uint32_t pf[4] = {0, 0, 0, 0};

        for (int tt = 0; tt < ntseg; tt++) {
            const int t = t0 + tt;
            float cn[16];
            const int cb = t * 128 + wn * 64 + (lane & 3) * 2;
#pragma unroll
            for (int na = 0; na < 8; na++) {
                cn[na * 2]     = __ldg(&g_cnorm[cb + na * 8]);
                cn[na * 2 + 1] = __ldg(&g_cnorm[cb + na * 8 + 1]);
            }
#pragma unroll 1
            for (int kc = 0; kc < 4; kc++) {
                const int sch = (kc * 2) & 3, scl = sch + 1;
                const uint32_t bch = (uint32_t)(RF_SLOT + (sch << 13));
                const uint32_t bcl = (uint32_t)(RF_SLOT + (scl << 13));
                mbar_wait(sb + RF_MB + sch * 8, pf[sch]); pf[sch] ^= 1;
#pragma unroll
                for (int pass = 0; pass < 2; pass++) {
                    const uint32_t abase = pass ? RF_AL : RF_AH;
#pragma unroll
                    for (int ks2 = 0; ks2 < 2; ks2++) {
                        const int ks = kc * 2 + ks2;
                        uint4 af[2]; uint2 bf[8];
#pragma unroll
                        for (int ma = 0; ma < 2; ma++)
                            af[ma] = *reinterpret_cast<const uint4*>(
                                smem + abase + (((ks * 4) + wm * 2 + ma) * 32 + lane) * 16);
#pragma unroll
                        for (int na = 0; na < 8; na++)
                            bf[na] = *reinterpret_cast<const uint2*>(
                                smem + bch + (((ks2 * 16) + wn * 8 + na) * 32 + lane) * 8);
#pragma unroll
                        for (int ma = 0; ma < 2; ma++)
#pragma unroll
                            for (int na = 0; na < 8; na++)
                                mma16(acc[ma][na], af[ma], bf[na]);
                    }
                }
                if (lane == 0) mbar_arrive(sb + RF_MB + 32 + sch * 8);

                mbar_wait(sb + RF_MB + scl * 8, pf[scl]); pf[scl] ^= 1;
#pragma unroll
                for (int ks2 = 0; ks2 < 2; ks2++) {
                    const int ks = kc * 2 + ks2;
                    uint4 af[2]; uint2 bf[8];
#pragma unroll
                    for (int ma = 0; ma < 2; ma++)
                        af[ma] = *reinterpret_cast<const uint4*>(
                            smem + RF_AH + (((ks * 4) + wm * 2 + ma) * 32 + lane) * 16);
#pragma unroll
                    for (int na = 0; na < 8; na++)
                        bf[na] = *reinterpret_cast<const uint2*>(
                            smem + bcl + (((ks2 * 16) + wn * 8 + na) * 32 + lane) * 8);
#pragma unroll
                    for (int ma = 0; ma < 2; ma++)
#pragma unroll
                        for (int na = 0; na < 8; na++)
                            mma16(acc[ma][na], af[ma], bf[na]);
                }
                if (lane == 0) mbar_arrive(sb + RF_MB + 32 + scl * 8);
            }
#pragma unroll
            for (int ma = 0; ma < 2; ma++) {
                const int slo = ma * 2, shi = ma * 2 + 1;
#pragma unroll
                for (int na = 0; na < 8; na++) {
                    const int c0 = t * 128 + wn * 64 + na * 8 + (lane & 3) * 2;
                    float k00 = fmaf(-2.0f, acc[ma][na][0], cn[na * 2]);
                    float k01 = fmaf(-2.0f, acc[ma][na][1], cn[na * 2 + 1]);
                    float k10 = fmaf(-2.0f, acc[ma][na][2], cn[na * 2]);
                    float k11 = fmaf(-2.0f, acc[ma][na][3], cn[na * 2 + 1]);
                    if (k00 < bestv[slo]) { bestv[slo] = k00; besti[slo] = c0; }
                    if (k01 < bestv[slo]) { bestv[slo] = k01; besti[slo] = c0 + 1; }
                    if (k10 < bestv[shi]) { bestv[shi] = k10; besti[shi] = c0; }
                    if (k11 < bestv[shi]) { bestv[shi] = k11; besti[shi] = c0 + 1; }
                    acc[ma][na][0] = 0.0f; acc[ma][na][1] = 0.0f;
                    acc[ma][na][2] = 0.0f; acc[ma][na][3] = 0.0f;
                }
            }
        }
#pragma unroll
        for (int s = 0; s < 4; s++) {
            float v = bestv[s]; int bi = besti[s];
#pragma unroll
            for (int o = 1; o <= 2; o <<= 1) {
                float vo = __shfl_xor_sync(0xffffffffu, v, o);
                int   io = __shfl_xor_sync(0xffffffffu, bi, o);
                if (vo < v || (vo == v && io < bi)) { v = vo; bi = io; }
            }
            if ((lane & 3) == 0) {
                int row = wm * 32 + (s >> 1) * 16 + (s & 1) * 8 + (lane >> 2);
                reinterpret_cast<float*>(smem + RF_BV)[wn * 64 + row] = v;
                reinterpret_cast<int*>(smem + RF_BI)[wn * 64 + row]   = bi;
            }
        }
    } else {
        const int pw = wid - 4;
        uint32_t pe[4] = {0, 0, 0, 0};
        const int nchunks = ntseg * 8;
        for (int c = pw; c < nchunks; c += 2) {
            const int slot = c & 3;
            if (c >= 4) { mbar_wait(sb + RF_MB + 32 + slot * 8, pe[slot]); pe[slot] ^= 1; }
            const int t = t0 + (c >> 3), r = c & 7, kc = r >> 1;
            const float* src = reinterpret_cast<const float*>((r & 1) ? g_cl : g_ch)
                             + ((size_t)(t * 4 + kc) << 11);
            const uint32_t dst = sb + RF_SLOT + (slot << 13);
#pragma unroll
            for (int i = 0; i < 16; i++)
                cp16(dst + (uint32_t)((i * 32 + lane) << 4), src + ((i * 32 + lane) << 2));
            cp_commit(); cp_wait0();
            mbar_arrive(sb + RF_MB + slot * 8);
        }
    }
    __syncthreads();

    if (tid < 64) {
        const float* bv = reinterpret_cast<const float*>(smem + RF_BV);
        const int*   bixs = reinterpret_cast<const int*>(smem + RF_BI);
        float v0 = bv[tid], v1 = bv[64 + tid];
        int i0 = bixs[tid], i1v = bixs[64 + tid];
        int bi = (v1 < v0 || (v1 == v0 && i1v < i0)) ? i1v : i0;
        float vv = (v1 < v0 || (v1 == v0 && i1v < i0)) ? v1 : v0;
        int li = rg * 64 + tid;
        g_rv[seg * MAXB + li] = vv;
        g_ri[seg * MAXB + li] = bi;
    }
}

// ============ merge refine segments ============
__global__ void merge_refine()
{
    const int cnt = *(volatile int*)&g_count;
    int li = blockIdx.x * 256 + threadIdx.x;
    if (li >= cnt) return;
    float v = g_rv[li]; int bi = g_ri[li];
#pragma unroll
    for (int s = 1; s < NSEG_RF; s++) {
        float vo = g_rv[s * MAXB + li];
        int   io = g_ri[s * MAXB + li];
        if (vo < v) { v = vo; bi = io; }   // segments index-ordered; strict < keeps first-min
    }
    g_idx[g_undec[li]] = bi;
}

// ============ gather + loss ============
__global__ void gather_loss(const float* __restrict__ x, const float* __restrict__ codes,
                            float* __restrict__ out_q, float* __restrict__ out_idx, int write_idx)
{
    const int tid = threadIdx.x, txg = tid & 15, grp = tid >> 4;
    const int base = blockIdx.x * 128;
    float thr_loss = 0.0f;
    for (int rr = grp; rr < 128; rr += 16) {
        int row = base + rr;
        int bi = g_idx[row];
        if (txg == 0 && write_idx) out_idx[row] = (float)bi;
        const float4* cq = reinterpret_cast<const float4*>(codes + (size_t)bi * DDIM + txg * 8);
        float4 q0 = cq[0], q1 = cq[1];
        float4* od = reinterpret_cast<float4*>(out_q + (size_t)row * DDIM + txg * 8);
        od[0] = q0; od[1] = q1;
        const float4* xp = reinterpret_cast<const float4*>(x + (size_t)row * DDIM + txg * 8);
        float4 x0 = xp[0], x1 = xp[1];
        float d;
        d = x0.x - q0.x; thr_loss = fmaf(d, d, thr_loss);
        d = x0.y - q0.y; thr_loss = fmaf(d, d, thr_loss);
        d = x0.z - q0.z; thr_loss = fmaf(d, d, thr_loss);
        d = x0.w - q0.w; thr_loss = fmaf(d, d, thr_loss);
        d = x1.x - q1.x; thr_loss = fmaf(d, d, thr_loss);
        d = x1.y - q1.y; thr_loss = fmaf(d, d, thr_loss);
        d = x1.z - q1.z; thr_loss = fmaf(d, d, thr_loss);
        d = x1.w - q1.w; thr_loss = fmaf(d, d, thr_loss);
    }
    __shared__ float red[8];
#pragma unroll
    for (int o = 16; o; o >>= 1) thr_loss += __shfl_xor_sync(0xffffffffu, thr_loss, o);
    if ((tid & 31) == 0) red[tid >> 5] = thr_loss;
    __syncthreads();
    if (tid == 0) {
        float s = 0.0f;
#pragma unroll
        for (int w = 0; w < 8; w++) s += red[w];
        g_block_loss[blockIdx.x] = s;
    }
}

__global__ void finalize_kernel(float* __restrict__ out_loss, int nblocks, float invB)
{
    __shared__ float red[256];
    float s = 0.0f;
    for (int i = threadIdx.x; i < nblocks; i += 256) s += g_block_loss[i];
    red[threadIdx.x] = s;
    __syncthreads();
    for (int o = 128; o; o >>= 1) {
        if (threadIdx.x < o) red[threadIdx.x] += red[threadIdx.x + o];
        __syncthreads();
    }
    if (threadIdx.x == 0) *out_loss = 1.25f * red[0] * invB;  // (1 + BETA) * mean ||x-q||^2
}

extern "C" void kernel_launch(void* const* d_in, const int* in_sizes, int n_in,
                              void* d_out, int out_size)
{
    const float* x     = (const float*)d_in[0];
    const float* codes = (const float*)d_in[1];
    const int B = in_sizes[0] / DDIM;
    const int C = in_sizes[1] / DDIM;

    float* out      = (float*)d_out;
    float* out_q    = out;
    float* out_idx  = out + (size_t)B * DDIM;
    float* out_loss = out + (size_t)B * DDIM + B;

    const long long need_idx  = (long long)B * DDIM + B;
    const long long need_loss = need_idx + 1;
    const int write_idx  = ((long long)out_size >= need_idx)  ? 1 : 0;
    const int write_loss = ((long long)out_size >= need_loss) ? 1 : 0;

    (void)cudaFuncSetAttribute(vq_pass1,  cudaFuncAttributeMaxDynamicSharedMemorySize, SMEM_P1);
    (void)cudaFuncSetAttribute(vq_refine, cudaFuncAttributeMaxDynamicSharedMemorySize, SMEM_RF);

    split_x<<<B / 8, 256>>>(x);
    split_c<<<C / 8, 256>>>(codes);
    vq_pass1<<<(B / BM) * NSEG_P1, TPB, SMEM_P1>>>(C);
    decide_kernel<<<B / 256, 256>>>();
    vq_refine<<<(B / BM) * NSEG_RF, TPB, SMEM_RF>>>(x, C);
    merge_refine<<<B / 256, 256>>>();
    gather_loss<<<B / 128, 256>>>(x, codes, out_q, out_idx, write_idx);
    if (write_loss)
        finalize_kernel<<<1, 256>>>(out_loss, B / 128, 1.0f / (float)B);
}

// round 11
// speedup vs baseline: 5.9633x; 1.0816x over previous
#include <cuda_runtime.h>
#include <cuda_fp16.h>
#include <math_constants.h>
#include <cstdint>

// Quantizer_33036888441545 — VQ argmin via hh-screen (acc-folded cn, 16 math warps) + exact 3xfp16 refine.
// x: [65536,128] f32, codes: [4096,128] f32. out: q[B*128], idx[B], loss[1].

#define DDIM 128
#define MAXB 65536
#define MAXC 4096
#define NSEG_P1 2
#define NSEG_RF 8
#define TPB_P1 576
#define TPB_RF 192

__device__ __half    g_xh[MAXB * DDIM];
__device__ __half    g_ch[MAXC * DDIM];
__device__ __half    g_cl[MAXC * DDIM];
__device__ float     g_cnorm[MAXC];
__device__ float     g_xhn[MAXB];
__device__ float     g_xln[MAXB];
__device__ unsigned  g_clmax;
__device__ unsigned  g_chmax;
__device__ int       g_idx[MAXB];
__device__ int       g_undec[MAXB];
__device__ int       g_count;
__device__ float     g_p1v1[NSEG_P1 * MAXB];   // acc-domain max1
__device__ float     g_p1v2[NSEG_P1 * MAXB];   // acc-domain max2
__device__ int       g_p1i1[NSEG_P1 * MAXB];
__device__ float     g_rv[NSEG_RF * MAXB];
__device__ int       g_ri[NSEG_RF * MAXB];
__device__ float     g_block_loss[1024];

// ---- pass1 smem map (BM=128) ----
#define P1_AH    0          // 32KB A-hi frags (128 rows)
#define P1_SLOT  32768      // 4 x 8KB ch ring
#define P1_MB    65536      // full[4] @+0..31, empty[4] @+32..63
#define P1_M1    65600      // float [4][128]
#define P1_M2    67648
#define P1_I1    69696
#define SMEM_P1  71744

// ---- refine smem map (BM=64, unchanged from R10) ----
#define RF_AH    0
#define RF_AL    16384
#define RF_SLOT  32768      // 4 x 8KB ring (ch/cl)
#define RF_MB    65536
#define RF_BV    65600      // float [2][64]
#define RF_BI    66112
#define RF_LIST  66624      // int [64]
#define SMEM_RF  66880

// ============ helpers ============
__device__ __forceinline__ uint32_t smem_u32(const void* p) {
    uint32_t a;
    asm("{ .reg .u64 t; cvta.to.shared.u64 t, %1; cvt.u32.u64 %0, t; }" : "=r"(a) : "l"(p));
    return a;
}
__device__ __forceinline__ void mbar_init(uint32_t a, uint32_t cnt) {
    asm volatile("mbarrier.init.shared.b64 [%0], %1;" :: "r"(a), "r"(cnt) : "memory");
}
__device__ __forceinline__ void mbar_arrive(uint32_t a) {
    asm volatile("mbarrier.arrive.shared.b64 _, [%0];" :: "r"(a) : "memory");
}
__device__ __forceinline__ void mbar_wait(uint32_t a, uint32_t parity) {
    uint32_t done = 0;
    while (!done) {
        asm volatile(
            "{ .reg .pred p; mbarrier.try_wait.parity.acquire.cta.shared::cta.b64 p, [%1], %2, 0x989680; selp.b32 %0,1,0,p; }"
            : "=r"(done) : "r"(a), "r"(parity) : "memory");
    }
}
__device__ __forceinline__ void cp16(uint32_t dst, const float* src) {
    asm volatile("cp.async.cg.shared.global [%0], [%1], 16;" :: "r"(dst), "l"(src) : "memory");
}
__device__ __forceinline__ void cp_commit() { asm volatile("cp.async.commit_group;" ::: "memory"); }
__device__ __forceinline__ void cp_wait0()  { asm volatile("cp.async.wait_group 0;"  ::: "memory"); }

__device__ __forceinline__ void mma16(float* c, const uint4& a, const uint2& b) {
    asm volatile(
        "mma.sync.aligned.m16n8k16.row.col.f32.f16.f16.f32 "
        "{%0,%1,%2,%3}, {%4,%5,%6,%7}, {%8,%9}, {%0,%1,%2,%3};"
        : "+f"(c[0]), "+f"(c[1]), "+f"(c[2]), "+f"(c[3])
        : "r"(a.x), "r"(a.y), "r"(a.z), "r"(a.w), "r"(b.x), "r"(b.y));
}

// A-frag half2-unit index, 64-row block (refine layout), row mloc (0..63), even k.
__device__ __forceinline__ int a_frag_h2_64(int mloc, int k) {
    int ks = k >> 4, kk = k & 15, ma = mloc >> 4, r = mloc & 15;
    int lane = (r & 7) * 4 + ((kk & 7) >> 1);
    int reg  = ((kk >> 3) << 1) | (r >> 3);
    return ((ks * 4 + ma) * 32 + lane) * 4 + reg;
}
// A-frag half2-unit index, 128-row block (pass1 layout), row mloc (0..127), even k.
__device__ __forceinline__ int a_frag_h2_128(int mloc, int k) {
    int ks = k >> 4, kk = k & 15, ma = mloc >> 4, r = mloc & 15;
    int lane = (r & 7) * 4 + ((kk & 7) >> 1);
    int reg  = ((kk >> 3) << 1) | (r >> 3);
    return ((ks * 8 + ma) * 32 + lane) * 4 + reg;
}

// ============ split_x: frags (128-row layout, hi only) + row norms; resets ============
__global__ void split_x(const float* __restrict__ x)
{
    if (blockIdx.x == 0 && threadIdx.x == 0) { g_count = 0; g_clmax = 0u; g_chmax = 0u; }
    int row  = blockIdx.x * 8 + (threadIdx.x >> 5);
    int lane = threadIdx.x & 31;
    float4 v = reinterpret_cast<const float4*>(x)[(size_t)row * 32 + lane];
    float vv[4] = {v.x, v.y, v.z, v.w};
    __half h[4]; float l[4];
    float hs = 0.0f, ls = 0.0f;
#pragma unroll
    for (int j = 0; j < 4; j++) {
        h[j] = __float2half_rn(vv[j]);
        float hf = __half2float(h[j]);
        l[j] = vv[j] - hf;
        hs = fmaf(hf, hf, hs);
        ls = fmaf(l[j], l[j], ls);
    }
    int blk = row >> 7, mloc = row & 127;
    __half2* xh2 = reinterpret_cast<__half2*>(g_xh) + (size_t)blk * 8192;
#pragma unroll
    for (int p = 0; p < 2; p++) {
        int k = lane * 4 + p * 2;
        int u = a_frag_h2_128(mloc, k);
        xh2[u] = __halves2half2(h[p * 2], h[p * 2 + 1]);
    }
#pragma unroll
    for (int o = 16; o; o >>= 1) {
        hs += __shfl_xor_sync(0xffffffffu, hs, o);
        ls += __shfl_xor_sync(0xffffffffu, ls, o);
    }
    if (lane == 0) { g_xhn[row] = sqrtf(hs); g_xln[row] = sqrtf(ls); }
}

// ============ split_c (unchanged) ============
__global__ void split_c(const float* __restrict__ codes)
{
    int n    = blockIdx.x * 8 + (threadIdx.x >> 5);
    int lane = threadIdx.x & 31;
    float4 v = reinterpret_cast<const float4*>(codes)[(size_t)n * 32 + lane];
    float vv[4] = {v.x, v.y, v.z, v.w};
    __half h[4]; float l[4];
    float cs = 0.0f, hs = 0.0f, ls = 0.0f;
#pragma unroll
    for (int j = 0; j < 4; j++) {
        h[j] = __float2half_rn(vv[j]);
        float hf = __half2float(h[j]);
        l[j] = vv[j] - hf;
        cs = fmaf(vv[j], vv[j], cs);
        hs = fmaf(hf, hf, hs);
        ls = fmaf(l[j], l[j], ls);
    }
    int t = n >> 7, nloc = n & 127, na = nloc >> 3;
    __half2* ch2 = reinterpret_cast<__half2*>(g_ch);
    __half2* cl2 = reinterpret_cast<__half2*>(g_cl);
#pragma unroll
    for (int p = 0; p < 2; p++) {
        int k = lane * 4 + p * 2;
        int kc = k >> 5, ks2 = (k >> 4) & 1, kk = k & 15;
        int lane_f = (nloc & 7) * 4 + ((kk & 7) >> 1);
        int reg    = kk >> 3;
        size_t u = ((((size_t)(t * 4 + kc) * 2 + ks2) * 16 + na) * 32 + lane_f) * 2 + reg;
        ch2[u] = __halves2half2(h[p * 2], h[p * 2 + 1]);
        cl2[u] = __halves2half2(__float2half_rn(l[p * 2]), __float2half_rn(l[p * 2 + 1]));
    }
#pragma unroll
    for (int o = 16; o; o >>= 1) {
        cs += __shfl_xor_sync(0xffffffffu, cs, o);
        hs += __shfl_xor_sync(0xffffffffu, hs, o);
        ls += __shfl_xor_sync(0xffffffffu, ls, o);
    }
    if (lane == 0) {
        g_cnorm[n] = cs;
        atomicMax(&g_chmax, __float_as_uint(sqrtf(hs)));
        atomicMax(&g_clmax, __float_as_uint(sqrtf(ls)));
    }
}

// ============ pass1: hh GEMM (acc init -cn/2; argmax acc), 16 math + 2 producer warps ============
__global__ __launch_bounds__(TPB_P1, 1)
void vq_pass1(int C)
{
    extern __shared__ char smem[];
    const uint32_t sb = smem_u32(smem);
    const int tid = threadIdx.x, wid = tid >> 5, lane = tid & 31;
    const int rb  = blockIdx.x >> 1;           // 128-row block
    const int seg = blockIdx.x & 1;            // code segment
    const int row0 = rb * 128;
    const int ntseg = (C >> 7) / NSEG_P1;      // 16 tiles
    const int t0 = seg * ntseg;

    if (tid == 0) {
#pragma unroll
        for (int s = 0; s < 4; s++) {
            mbar_init(sb + P1_MB + s * 8, 32);       // full: producer warp lanes
            mbar_init(sb + P1_MB + 32 + s * 8, 16);  // empty: 16 math warps
        }
    }
    {   // resident A-hi (32KB = 2048 float4)
        const float* srch = reinterpret_cast<const float*>(g_xh) + (size_t)rb * 8192;
        for (int i = tid; i < 2048; i += TPB_P1) cp16(sb + P1_AH + i * 16, srch + i * 4);
        cp_commit(); cp_wait0();
    }
    __syncthreads();

    if (wid < 16) {
        // ---------------- math warps: 32 rows (wm) x 32 cols (wn) ----------------
        const int wm = wid >> 2, wn = wid & 3;
        float m1[4], m2[4]; int i1[4];
#pragma unroll
        for (int s = 0; s < 4; s++) { m1[s] = -CUDART_INF_F; m2[s] = -CUDART_INF_F; i1[s] = 0; }
        uint32_t pf[4] = {0, 0, 0, 0};
        float acc[2][4][4];

        for (int tt = 0; tt < ntseg; tt++) {
            const int t = t0 + tt;
            float cnh[8];
            const int cb = t * 128 + wn * 32 + (lane & 3) * 2;
#pragma unroll
            for (int na = 0; na < 4; na++) {
                cnh[na * 2]     = -0.5f * __ldg(&g_cnorm[cb + na * 8]);
                cnh[na * 2 + 1] = -0.5f * __ldg(&g_cnorm[cb + na * 8 + 1]);
            }
            // init acc = -cn/2  (so final acc = x.c - cn/2; key = -2*acc)
#pragma unroll
            for (int ma = 0; ma < 2; ma++)
#pragma unroll
                for (int na = 0; na < 4; na++) {
                    acc[ma][na][0] = cnh[na * 2];
                    acc[ma][na][1] = cnh[na * 2 + 1];
                    acc[ma][na][2] = cnh[na * 2];
                    acc[ma][na][3] = cnh[na * 2 + 1];
                }

#pragma unroll 1
            for (int kc = 0; kc < 4; kc++) {
                const int slot = kc;
                const uint32_t bch = (uint32_t)(P1_SLOT + (slot << 13));
                mbar_wait(sb + P1_MB + slot * 8, pf[slot]); pf[slot] ^= 1;
#pragma unroll
                for (int ks2 = 0; ks2 < 2; ks2++) {
                    const int ks = kc * 2 + ks2;
                    uint4 af[2]; uint2 bf[4];
#pragma unroll
                    for (int ma = 0; ma < 2; ma++)
                        af[ma] = *reinterpret_cast<const uint4*>(
                            smem + P1_AH + (((ks * 8) + wm * 2 + ma) * 32 + lane) * 16);
#pragma unroll
                    for (int na = 0; na < 4; na++)
                        bf[na] = *reinterpret_cast<const uint2*>(
                            smem + bch + (((ks2 * 16) + wn * 4 + na) * 32 + lane) * 8);
#pragma unroll
                    for (int ma = 0; ma < 2; ma++)
#pragma unroll
                        for (int na = 0; na < 4; na++)
                            mma16(acc[ma][na], af[ma], bf[na]);
                }
                if (lane == 0) mbar_arrive(sb + P1_MB + 32 + slot * 8);
            }
            // epilogue: running top-2 MAX of acc (key = -2*acc), first-index on ties via strict >
#pragma unroll
            for (int ma = 0; ma < 2; ma++) {
                const int slo = ma * 2, shi = ma * 2 + 1;
#pragma unroll
                for (int na = 0; na < 4; na++) {
                    const int c0 = t * 128 + wn * 32 + na * 8 + (lane & 3) * 2;
                    float a00 = acc[ma][na][0], a01 = acc[ma][na][1];
                    float a10 = acc[ma][na][2], a11 = acc[ma][na][3];
                    {
                        bool p = a00 > m1[slo];
                        m2[slo] = p ? m1[slo] : fmaxf(m2[slo], a00);
                        i1[slo] = p ? c0 : i1[slo];
                        m1[slo] = p ? a00 : m1[slo];
                    }
                    {
                        bool p = a01 > m1[slo];
                        m2[slo] = p ? m1[slo] : fmaxf(m2[slo], a01);
                        i1[slo] = p ? (c0 + 1) : i1[slo];
                        m1[slo] = p ? a01 : m1[slo];
                    }
                    {
                        bool p = a10 > m1[shi];
                        m2[shi] = p ? m1[shi] : fmaxf(m2[shi], a10);
                        i1[shi] = p ? c0 : i1[shi];
                        m1[shi] = p ? a10 : m1[shi];
                    }
                    {
                        bool p = a11 > m1[shi];
                        m2[shi] = p ? m1[shi] : fmaxf(m2[shi], a11);
                        i1[shi] = p ? (c0 + 1) : i1[shi];
                        m1[shi] = p ? a11 : m1[shi];
                    }
                }
            }
        }
        // lane merge (4 lanes per row), max domain, first-index ties
#pragma unroll
        for (int s = 0; s < 4; s++) {
            float v1 = m1[s], v2 = m2[s]; int ii = i1[s];
#pragma unroll
            for (int o = 1; o <= 2; o <<= 1) {
                float a1 = __shfl_xor_sync(0xffffffffu, v1, o);
                float a2 = __shfl_xor_sync(0xffffffffu, v2, o);
                int   ai = __shfl_xor_sync(0xffffffffu, ii, o);
                bool bwin = (a1 > v1) || (a1 == v1 && ai < ii);
                float loser1 = bwin ? v1 : a1;
                v2 = fmaxf(fmaxf(v2, a2), loser1);
                v1 = bwin ? a1 : v1;
                ii = bwin ? ai : ii;
            }
            if ((lane & 3) == 0) {
                int row = wm * 32 + (s >> 1) * 16 + (s & 1) * 8 + (lane >> 2);
                reinterpret_cast<float*>(smem + P1_M1)[wn * 128 + row] = v1;
                reinterpret_cast<float*>(smem + P1_M2)[wn * 128 + row] = v2;
                reinterpret_cast<int*>(smem + P1_I1)[wn * 128 + row]   = ii;
            }
        }
    } else {
        // ---------------- producer warps (2), 4-slot ch ring ----------------
        const int pw = wid - 16;
        uint32_t pe[4] = {0, 0, 0, 0};
        const int nchunks = ntseg * 4;
        for (int c = pw; c < nchunks; c += 2) {
            const int slot = c & 3;
            if (c >= 4) { mbar_wait(sb + P1_MB + 32 + slot * 8, pe[slot]); pe[slot] ^= 1; }
            const float* src = reinterpret_cast<const float*>(g_ch) + ((size_t)(t0 * 4 + c) << 11);
            const uint32_t dst = sb + P1_SLOT + (slot << 13);
#pragma unroll
            for (int i = 0; i < 16; i++)
                cp16(dst + (uint32_t)((i * 32 + lane) << 4), src + ((i * 32 + lane) << 2));
            cp_commit(); cp_wait0();
            mbar_arrive(sb + P1_MB + slot * 8);
        }
    }
    __syncthreads();

    // merge 4 wn stripes -> per-(row,seg) top-2 (max domain) out to gmem
    if (tid < 128) {
        const float* sm1 = reinterpret_cast<const float*>(smem + P1_M1);
        const float* sm2 = reinterpret_cast<const float*>(smem + P1_M2);
        const int*   si1 = reinterpret_cast<const int*>(smem + P1_I1);
        float v1 = sm1[tid], v2 = sm2[tid]; int ii = si1[tid];
#pragma unroll
        for (int wnn = 1; wnn < 4; wnn++) {
            float b1 = sm1[wnn * 128 + tid], b2 = sm2[wnn * 128 + tid];
            int   bi = si1[wnn * 128 + tid];
            bool bwin = (b1 > v1) || (b1 == v1 && bi < ii);
            float loser1 = bwin ? v1 : b1;
            v2 = fmaxf(fmaxf(v2, b2), loser1);
            v1 = bwin ? b1 : v1;
            ii = bwin ? bi : ii;
        }
        int o = seg * MAXB + row0 + tid;
        g_p1v1[o] = v1; g_p1v2[o] = v2; g_p1i1[o] = ii;
    }
}

// ============ decide: merge pass1 segments (max domain), threshold, compact undecided ============
__global__ void decide_kernel()
{
    int row = blockIdx.x * 256 + threadIdx.x;
    float v1 = g_p1v1[row], v2 = g_p1v2[row]; int ii = g_p1i1[row];
    float b1 = g_p1v1[MAXB + row], b2 = g_p1v2[MAXB + row]; int bi = g_p1i1[MAXB + row];
    bool bwin = b1 > v1;                      // strict: ties keep seg0 (smaller indices)
    float loser1 = bwin ? v1 : b1;
    float m2f = fmaxf(fmaxf(v2, b2), loser1);
    float m1f = bwin ? b1 : v1;
    int   idx = bwin ? bi : ii;
    g_idx[row] = idx;
    float xhn = g_xhn[row], xln = g_xln[row];
    float clm = __uint_as_float(g_clmax), chm = __uint_as_float(g_chmax);
    float eb = xhn * clm + xln * chm + xln * clm;
    float thr = 5.0f * eb + 0.125f;
    float gap = 2.0f * (m1f - m2f);           // key-domain gap
    if (!(gap > thr)) {
        int p = atomicAdd(&g_count, 1);
        g_undec[p] = row;
    }
}

// ============ refine: exact 3-pass, C split into NSEG_RF segments (unchanged from R10) ============
__global__ __launch_bounds__(TPB_RF, 2)
void vq_refine(const float* __restrict__ x, int C)
{
    const int cnt = *(volatile int*)&g_count;
    const int rg  = blockIdx.x >> 3;
    const int seg = blockIdx.x & 7;
    if (rg * 64 >= cnt) return;

    extern __shared__ char smem[];
    const uint32_t sb = smem_u32(smem);
    const int tid = threadIdx.x, wid = tid >> 5, lane = tid & 31;
    const int ntseg = (C >> 7) / NSEG_RF;
    const int t0 = seg * ntseg;

    if (tid == 0) {
#pragma unroll
        for (int s = 0; s < 4; s++) {
            mbar_init(sb + RF_MB + s * 8, 32);
            mbar_init(sb + RF_MB + 32 + s * 8, 4);
        }
    }
    int* list = reinterpret_cast<int*>(smem + RF_LIST);
    if (tid < 64) {
        int li = rg * 64 + tid;
        list[tid] = g_undec[(li < cnt) ? li : (cnt - 1)];
    }
    __syncthreads();
    if (tid < 128) {
        int r_loc = tid >> 1, half = tid & 1;
        int r = list[r_loc];
        const float4* xp = reinterpret_cast<const float4*>(x + (size_t)r * DDIM) + half * 16;
        __half2* ah = reinterpret_cast<__half2*>(smem + RF_AH);
        __half2* al = reinterpret_cast<__half2*>(smem + RF_AL);
#pragma unroll 4
        for (int qq = 0; qq < 16; qq++) {
            int q = half * 16 + qq;
            float4 v = xp[qq];
            float vv[4] = {v.x, v.y, v.z, v.w};
            __half h[4]; __half l[4];
#pragma unroll
            for (int j = 0; j < 4; j++) {
                h[j] = __float2half_rn(vv[j]);
                l[j] = __float2half_rn(vv[j] - __half2float(h[j]));
            }
#pragma unroll
            for (int p = 0; p < 2; p++) {
                int k = q * 4 + p * 2;
                int u = a_frag_h2_64(r_loc, k);
                ah[u] = __halves2half2(h[p * 2], h[p * 2 + 1]);
                al[u] = __halves2half2(l[p * 2], l[p * 2 + 1]);
            }
        }
    }
    __syncthreads();

    if (wid < 4) {
        const int wm = wid >> 1, wn = wid & 1;
        float acc[2][8][4];
#pragma unroll
        for (int a = 0; a < 2; a++)
#pragma unroll
            for (int b = 0; b < 8; b++)
#pragma unroll
                for (int r = 0; r < 4; r++) acc[a][b][r] = 0.0f;
        float bestv[4]; int besti[4];
#pragma unroll
        for (int s = 0; s < 4; s++) { bestv[s] = CUDART_INF_F; besti[s] = 0; }
        uint32_t pf[4] = {0, 0, 0, 0};

        for (int tt = 0; tt < ntseg; tt++) {
            const int t = t0 + tt;
            float cn[16];
            const int cb = t * 128 + wn * 64 + (lane & 3) * 2;
#pragma unroll
            for (int na = 0; na < 8; na++) {
                cn[na * 2]     = __ldg(&g_cnorm[cb + na * 8]);
                cn[na * 2 + 1] = __ldg(&g_cnorm[cb + na * 8 + 1]);
            }
#pragma unroll 1
            for (int kc = 0; kc < 4; kc++) {
                const int sch = (kc * 2) & 3, scl = sch + 1;
                const uint32_t bch = (uint32_t)(RF_SLOT + (sch << 13));
                const uint32_t bcl = (uint32_t)(RF_SLOT + (scl << 13));
                mbar_wait(sb + RF_MB + sch * 8, pf[sch]); pf[sch] ^= 1;
#pragma unroll
                for (int pass = 0; pass < 2; pass++) {
                    const uint32_t abase = pass ? RF_AL : RF_AH;
#pragma unroll
                    for (int ks2 = 0; ks2 < 2; ks2++) {
                        const int ks = kc * 2 + ks2;
                        uint4 af[2]; uint2 bf[8];
#pragma unroll
                        for (int ma = 0; ma < 2; ma++)
                            af[ma] = *reinterpret_cast<const uint4*>(
                                smem + abase + (((ks * 4) + wm * 2 + ma) * 32 + lane) * 16);
#pragma unroll
                        for (int na = 0; na < 8; na++)
                            bf[na] = *reinterpret_cast<const uint2*>(
                                smem + bch + (((ks2 * 16) + wn * 8 + na) * 32 + lane) * 8);
#pragma unroll
                        for (int ma = 0; ma < 2; ma++)
#pragma unroll
                            for (int na = 0; na < 8; na++)
                                mma16(acc[ma][na], af[ma], bf[na]);
                    }
                }
                if (lane == 0) mbar_arrive(sb + RF_MB + 32 + sch * 8);

                mbar_wait(sb + RF_MB + scl * 8, pf[scl]); pf[scl] ^= 1;
#pragma unroll
                for (int ks2 = 0; ks2 < 2; ks2++) {
                    const int ks = kc * 2 + ks2;
                    uint4 af[2]; uint2 bf[8];
#pragma unroll
                    for (int ma = 0; ma < 2; ma++)
                        af[ma] = *reinterpret_cast<const uint4*>(
                            smem + RF_AH + (((ks * 4) + wm * 2 + ma) * 32 + lane) * 16);
#pragma unroll
                    for (int na = 0; na < 8; na++)
                        bf[na] = *reinterpret_cast<const uint2*>(
                            smem + bcl + (((ks2 * 16) + wn * 8 + na) * 32 + lane) * 8);
#pragma unroll
                    for (int ma = 0; ma < 2; ma++)
#pragma unroll
                        for (int na = 0; na < 8; na++)
                            mma16(acc[ma][na], af[ma], bf[na]);
                }
                if (lane == 0) mbar_arrive(sb + RF_MB + 32 + scl * 8);
            }
#pragma unroll
            for (int ma = 0; ma < 2; ma++) {
                const int slo = ma * 2, shi = ma * 2 + 1;
#pragma unroll
                for (int na = 0; na < 8; na++) {
                    const int c0 = t * 128 + wn * 64 + na * 8 + (lane & 3) * 2;
                    float k00 = fmaf(-2.0f, acc[ma][na][0], cn[na * 2]);
                    float k01 = fmaf(-2.0f, acc[ma][na][1], cn[na * 2 + 1]);
                    float k10 = fmaf(-2.0f, acc[ma][na][2], cn[na * 2]);
                    float k11 = fmaf(-2.0f, acc[ma][na][3], cn[na * 2 + 1]);
                    if (k00 < bestv[slo]) { bestv[slo] = k00; besti[slo] = c0; }
                    if (k01 < bestv[slo]) { bestv[slo] = k01; besti[slo] = c0 + 1; }
                    if (k10 < bestv[shi]) { bestv[shi] = k10; besti[shi] = c0; }
                    if (k11 < bestv[shi]) { bestv[shi] = k11; besti[shi] = c0 + 1; }
                    acc[ma][na][0] = 0.0f; acc[ma][na][1] = 0.0f;
                    acc[ma][na][2] = 0.0f; acc[ma][na][3] = 0.0f;
                }
            }
        }
#pragma unroll
        for (int s = 0; s < 4; s++) {
            float v = bestv[s]; int bi = besti[s];
#pragma unroll
            for (int o = 1; o <= 2; o <<= 1) {
                float vo = __shfl_xor_sync(0xffffffffu, v, o);
                int   io = __shfl_xor_sync(0xffffffffu, bi, o);
                if (vo < v || (vo == v && io < bi)) { v = vo; bi = io; }
            }
            if ((lane & 3) == 0) {
                int row = wm * 32 + (s >> 1) * 16 + (s & 1) * 8 + (lane >> 2);
                reinterpret_cast<float*>(smem + RF_BV)[wn * 64 + row] = v;
                reinterpret_cast<int*>(smem + RF_BI)[wn * 64 + row]   = bi;
            }
        }
    } else {
        const int pw = wid - 4;
        uint32_t pe[4] = {0, 0, 0, 0};
        const int nchunks = ntseg * 8;
        for (int c = pw; c < nchunks; c += 2) {
            const int slot = c & 3;
            if (c >= 4) { mbar_wait(sb + RF_MB + 32 + slot * 8, pe[slot]); pe[slot] ^= 1; }
            const int t = t0 + (c >> 3), r = c & 7, kc = r >> 1;
            const float* src = reinterpret_cast<const float*>((r & 1) ? g_cl : g_ch)
                             + ((size_t)(t * 4 + kc) << 11);
            const uint32_t dst = sb + RF_SLOT + (slot << 13);
#pragma unroll
            for (int i = 0; i < 16; i++)
                cp16(dst + (uint32_t)((i * 32 + lane) << 4), src + ((i * 32 + lane) << 2));
            cp_commit(); cp_wait0();
            mbar_arrive(sb + RF_MB + slot * 8);
        }
    }
    __syncthreads();

    if (tid < 64) {
        const float* bv = reinterpret_cast<const float*>(smem + RF_BV);
        const int*   bixs = reinterpret_cast<const int*>(smem + RF_BI);
        float v0 = bv[tid], v1 = bv[64 + tid];
        int i0 = bixs[tid], i1v = bixs[64 + tid];
        int bi = (v1 < v0 || (v1 == v0 && i1v < i0)) ? i1v : i0;
        float vv = (v1 < v0 || (v1 == v0 && i1v < i0)) ? v1 : v0;
        int li = rg * 64 + tid;
        g_rv[seg * MAXB + li] = vv;
        g_ri[seg * MAXB + li] = bi;
    }
}

// ============ merge refine segments ============
__global__ void merge_refine()
{
    const int cnt = *(volatile int*)&g_count;
    int li = blockIdx.x * 256 + threadIdx.x;
    if (li >= cnt) return;
    float v = g_rv[li]; int bi = g_ri[li];
#pragma unroll
    for (int s = 1; s < NSEG_RF; s++) {
        float vo = g_rv[s * MAXB + li];
        int   io = g_ri[s * MAXB + li];
        if (vo < v) { v = vo; bi = io; }
    }
    g_idx[g_undec[li]] = bi;
}

// ============ gather + loss ============
__global__ void gather_loss(const float* __restrict__ x, const float* __restrict__ codes,
                            float* __restrict__ out_q, float* __restrict__ out_idx, int write_idx)
{
    const int tid = threadIdx.x, txg = tid & 15, grp = tid >> 4;
    const int base = blockIdx.x * 128;
    float thr_loss = 0.0f;
    for (int rr = grp; rr < 128; rr += 16) {
        int row = base + rr;
        int bi = g_idx[row];
        if (txg == 0 && write_idx) out_idx[row] = (float)bi;
        const float4* cq = reinterpret_cast<const float4*>(codes + (size_t)bi * DDIM + txg * 8);
        float4 q0 = cq[0], q1 = cq[1];
        float4* od = reinterpret_cast<float4*>(out_q + (size_t)row * DDIM + txg * 8);
        od[0] = q0; od[1] = q1;
        const float4* xp = reinterpret_cast<const float4*>(x + (size_t)row * DDIM + txg * 8);
        float4 x0 = xp[0], x1 = xp[1];
        float d;
        d = x0.x - q0.x; thr_loss = fmaf(d, d, thr_loss);
        d = x0.y - q0.y; thr_loss = fmaf(d, d, thr_loss);
        d = x0.z - q0.z; thr_loss = fmaf(d, d, thr_loss);
        d = x0.w - q0.w; thr_loss = fmaf(d, d, thr_loss);
        d = x1.x - q1.x; thr_loss = fmaf(d, d, thr_loss);
        d = x1.y - q1.y; thr_loss = fmaf(d, d, thr_loss);
        d = x1.z - q1.z; thr_loss = fmaf(d, d, thr_loss);
        d = x1.w - q1.w; thr_loss = fmaf(d, d, thr_loss);
    }
    __shared__ float red[8];
#pragma unroll
    for (int o = 16; o; o >>= 1) thr_loss += __shfl_xor_sync(0xffffffffu, thr_loss, o);
    if ((tid & 31) == 0) red[tid >> 5] = thr_loss;
    __syncthreads();
    if (tid == 0) {
        float s = 0.0f;
#pragma unroll
        for (int w = 0; w < 8; w++) s += red[w];
        g_block_loss[blockIdx.x] = s;
    }
}

__global__ void finalize_kernel(float* __restrict__ out_loss, int nblocks, float invB)
{
    __shared__ float red[256];
    float s = 0.0f;
    for (int i = threadIdx.x; i < nblocks; i += 256) s += g_block_loss[i];
    red[threadIdx.x] = s;
    __syncthreads();
    for (int o = 128; o; o >>= 1) {
        if (threadIdx.x < o) red[threadIdx.x] += red[threadIdx.x + o];
        __syncthreads();
    }
    if (threadIdx.x == 0) *out_loss = 1.25f * red[0] * invB;  // (1 + BETA) * mean ||x-q||^2
}

extern "C" void kernel_launch(void* const* d_in, const int* in_sizes, int n_in,
                              void* d_out, int out_size)
{
    const float* x     = (const float*)d_in[0];
    const float* codes = (const float*)d_in[1];
    const int B = in_sizes[0] / DDIM;
    const int C = in_sizes[1] / DDIM;

    float* out      = (float*)d_out;
    float* out_q    = out;
    float* out_idx  = out + (size_t)B * DDIM;
    float* out_loss = out + (size_t)B * DDIM + B;

    const long long need_idx  = (long long)B * DDIM + B;
    const long long need_loss = need_idx + 1;
    const int write_idx  = ((long long)out_size >= need_idx)  ? 1 : 0;
    const int write_loss = ((long long)out_size >= need_loss) ? 1 : 0;

    (void)cudaFuncSetAttribute(vq_pass1,  cudaFuncAttributeMaxDynamicSharedMemorySize, SMEM_P1);
    (void)cudaFuncSetAttribute(vq_refine, cudaFuncAttributeMaxDynamicSharedMemorySize, SMEM_RF);

    split_x<<<B / 8, 256>>>(x);
    split_c<<<C / 8, 256>>>(codes);
    vq_pass1<<<(B / 128) * NSEG_P1, TPB_P1, SMEM_P1>>>(C);
    decide_kernel<<<B / 256, 256>>>();
    vq_refine<<<(B / 64) * NSEG_RF, TPB_RF, SMEM_RF>>>(x, C);
    merge_refine<<<B / 256, 256>>>();
    gather_loss<<<B / 128, 256>>>(x, codes, out_q, out_idx, write_idx);
    if (write_loss)
        finalize_kernel<<<1, 256>>>(out_loss, B / 128, 1.0f / (float)B);
}

// round 12
// speedup vs baseline: 6.2173x; 1.0426x over previous
#include <cuda_runtime.h>
#include <cuda_fp16.h>
#include <math_constants.h>
#include <cstdint>

// Quantizer_33036888441545 — VQ argmin via hh-screen (acc-folded cn) + exact 3xfp16 refine.
// R12: coalesced split_x (smem staging), tightened screen threshold (4eb + slack).

#define DDIM 128
#define MAXB 65536
#define MAXC 4096
#define NSEG_P1 2
#define NSEG_RF 8
#define TPB_P1 576
#define TPB_RF 192

__device__ __half    g_xh[MAXB * DDIM];
__device__ __half    g_ch[MAXC * DDIM];
__device__ __half    g_cl[MAXC * DDIM];
__device__ float     g_cnorm[MAXC];
__device__ float     g_xhn[MAXB];
__device__ float     g_xln[MAXB];
__device__ unsigned  g_clmax;
__device__ unsigned  g_chmax;
__device__ int       g_idx[MAXB];
__device__ int       g_undec[MAXB];
__device__ int       g_count;
__device__ float     g_p1v1[NSEG_P1 * MAXB];   // acc-domain max1
__device__ float     g_p1v2[NSEG_P1 * MAXB];   // acc-domain max2
__device__ int       g_p1i1[NSEG_P1 * MAXB];
__device__ float     g_rv[NSEG_RF * MAXB];
__device__ int       g_ri[NSEG_RF * MAXB];
__device__ float     g_block_loss[1024];

// ---- pass1 smem map (BM=128) ----
#define P1_AH    0          // 32KB A-hi frags (128 rows)
#define P1_SLOT  32768      // 4 x 8KB ch ring
#define P1_MB    65536      // full[4] @+0..31, empty[4] @+32..63
#define P1_M1    65600      // float [4][128]
#define P1_M2    67648
#define P1_I1    69696
#define SMEM_P1  71744

// ---- refine smem map (BM=64) ----
#define RF_AH    0
#define RF_AL    16384
#define RF_SLOT  32768      // 4 x 8KB ring (ch/cl)
#define RF_MB    65536
#define RF_BV    65600      // float [2][64]
#define RF_BI    66112
#define RF_LIST  66624      // int [64]
#define SMEM_RF  66880

// ============ helpers ============
__device__ __forceinline__ uint32_t smem_u32(const void* p) {
    uint32_t a;
    asm("{ .reg .u64 t; cvta.to.shared.u64 t, %1; cvt.u32.u64 %0, t; }" : "=r"(a) : "l"(p));
    return a;
}
__device__ __forceinline__ void mbar_init(uint32_t a, uint32_t cnt) {
    asm volatile("mbarrier.init.shared.b64 [%0], %1;" :: "r"(a), "r"(cnt) : "memory");
}
__device__ __forceinline__ void mbar_arrive(uint32_t a) {
    asm volatile("mbarrier.arrive.shared.b64 _, [%0];" :: "r"(a) : "memory");
}
__device__ __forceinline__ void mbar_wait(uint32_t a, uint32_t parity) {
    uint32_t done = 0;
    while (!done) {
        asm volatile(
            "{ .reg .pred p; mbarrier.try_wait.parity.acquire.cta.shared::cta.b64 p, [%1], %2, 0x989680; selp.b32 %0,1,0,p; }"
            : "=r"(done) : "r"(a), "r"(parity) : "memory");
    }
}
__device__ __forceinline__ void cp16(uint32_t dst, const float* src) {
    asm volatile("cp.async.cg.shared.global [%0], [%1], 16;" :: "r"(dst), "l"(src) : "memory");
}
__device__ __forceinline__ void cp_commit() { asm volatile("cp.async.commit_group;" ::: "memory"); }
__device__ __forceinline__ void cp_wait0()  { asm volatile("cp.async.wait_group 0;"  ::: "memory"); }

__device__ __forceinline__ void mma16(float* c, const uint4& a, const uint2& b) {
    asm volatile(
        "mma.sync.aligned.m16n8k16.row.col.f32.f16.f16.f32 "
        "{%0,%1,%2,%3}, {%4,%5,%6,%7}, {%8,%9}, {%0,%1,%2,%3};"
        : "+f"(c[0]), "+f"(c[1]), "+f"(c[2]), "+f"(c[3])
        : "r"(a.x), "r"(a.y), "r"(a.z), "r"(a.w), "r"(b.x), "r"(b.y));
}

// A-frag half2-unit index, 64-row block (refine layout), row mloc (0..63), even k.
__device__ __forceinline__ int a_frag_h2_64(int mloc, int k) {
    int ks = k >> 4, kk = k & 15, ma = mloc >> 4, r = mloc & 15;
    int lane = (r & 7) * 4 + ((kk & 7) >> 1);
    int reg  = ((kk >> 3) << 1) | (r >> 3);
    return ((ks * 4 + ma) * 32 + lane) * 4 + reg;
}
// A-frag half2-unit index, 128-row block (pass1 layout), row mloc (0..127), even k.
__device__ __forceinline__ int a_frag_h2_128(int mloc, int k) {
    int ks = k >> 4, kk = k & 15, ma = mloc >> 4, r = mloc & 15;
    int lane = (r & 7) * 4 + ((kk & 7) >> 1);
    int reg  = ((kk >> 3) << 1) | (r >> 3);
    return ((ks * 8 + ma) * 32 + lane) * 4 + reg;
}

// ============ split_x v2: smem-staged, coalesced frag output; one block per 128-row blk ============
__global__ void split_x(const float* __restrict__ x)
{
    if (blockIdx.x == 0 && threadIdx.x == 0) { g_count = 0; g_clmax = 0u; g_chmax = 0u; }
    __shared__ __half2 stage[8192];     // 32KB frag tile
    const int tid = threadIdx.x, wid = tid >> 5, lane = tid & 31;
    const int blk = blockIdx.x;

#pragma unroll 4
    for (int it = 0; it < 16; it++) {
        int mloc = wid * 16 + it;       // warp wid handles rows wid*16 .. wid*16+15
        int row = blk * 128 + mloc;
        float4 v = reinterpret_cast<const float4*>(x)[(size_t)row * 32 + lane];
        float vv[4] = {v.x, v.y, v.z, v.w};
        __half h[4];
        float hs = 0.0f, ls = 0.0f;
#pragma unroll
        for (int j = 0; j < 4; j++) {
            h[j] = __float2half_rn(vv[j]);
            float hf = __half2float(h[j]);
            float l = vv[j] - hf;
            hs = fmaf(hf, hf, hs);
            ls = fmaf(l, l, ls);
        }
        int u = a_frag_h2_128(mloc, lane * 4);
        stage[u]     = __halves2half2(h[0], h[1]);
        stage[u + 4] = __halves2half2(h[2], h[3]);
#pragma unroll
        for (int o = 16; o; o >>= 1) {
            hs += __shfl_xor_sync(0xffffffffu, hs, o);
            ls += __shfl_xor_sync(0xffffffffu, ls, o);
        }
        if (lane == 0) { g_xhn[row] = sqrtf(hs); g_xln[row] = sqrtf(ls); }
    }
    __syncthreads();
    // coalesced copy out: 2048 float4
    float4* dst = reinterpret_cast<float4*>(g_xh) + (size_t)blk * 2048;
    const float4* src = reinterpret_cast<const float4*>(stage);
    for (int i = tid; i < 2048; i += 256) dst[i] = src[i];
}

// ============ split_c (unchanged) ============
__global__ void split_c(const float* __restrict__ codes)
{
    int n    = blockIdx.x * 8 + (threadIdx.x >> 5);
    int lane = threadIdx.x & 31;
    float4 v = reinterpret_cast<const float4*>(codes)[(size_t)n * 32 + lane];
    float vv[4] = {v.x, v.y, v.z, v.w};
    __half h[4]; float l[4];
    float cs = 0.0f, hs = 0.0f, ls = 0.0f;
#pragma unroll
    for (int j = 0; j < 4; j++) {
        h[j] = __float2half_rn(vv[j]);
        float hf = __half2float(h[j]);
        l[j] = vv[j] - hf;
        cs = fmaf(vv[j], vv[j], cs);
        hs = fmaf(hf, hf, hs);
        ls = fmaf(l[j], l[j], ls);
    }
    int t = n >> 7, nloc = n & 127, na = nloc >> 3;
    __half2* ch2 = reinterpret_cast<__half2*>(g_ch);
    __half2* cl2 = reinterpret_cast<__half2*>(g_cl);
#pragma unroll
    for (int p = 0; p < 2; p++) {
        int k = lane * 4 + p * 2;
        int kc = k >> 5, ks2 = (k >> 4) & 1, kk = k & 15;
        int lane_f = (nloc & 7) * 4 + ((kk & 7) >> 1);
        int reg    = kk >> 3;
        size_t u = ((((size_t)(t * 4 + kc) * 2 + ks2) * 16 + na) * 32 + lane_f) * 2 + reg;
        ch2[u] = __halves2half2(h[p * 2], h[p * 2 + 1]);
        cl2[u] = __halves2half2(__float2half_rn(l[p * 2]), __float2half_rn(l[p * 2 + 1]));
    }
#pragma unroll
    for (int o = 16; o; o >>= 1) {
        cs += __shfl_xor_sync(0xffffffffu, cs, o);
        hs += __shfl_xor_sync(0xffffffffu, hs, o);
        ls += __shfl_xor_sync(0xffffffffu, ls, o);
    }
    if (lane == 0) {
        g_cnorm[n] = cs;
        atomicMax(&g_chmax, __float_as_uint(sqrtf(hs)));
        atomicMax(&g_clmax, __float_as_uint(sqrtf(ls)));
    }
}

// ============ pass1: hh GEMM (acc init -cn/2; argmax acc), 16 math + 2 producer warps ============
__global__ __launch_bounds__(TPB_P1, 1)
void vq_pass1(int C)
{
    extern __shared__ char smem[];
    const uint32_t sb = smem_u32(smem);
    const int tid = threadIdx.x, wid = tid >> 5, lane = tid & 31;
    const int rb  = blockIdx.x >> 1;
    const int seg = blockIdx.x & 1;
    const int row0 = rb * 128;
    const int ntseg = (C >> 7) / NSEG_P1;
    const int t0 = seg * ntseg;

    if (tid == 0) {
#pragma unroll
        for (int s = 0; s < 4; s++) {
            mbar_init(sb + P1_MB + s * 8, 32);
            mbar_init(sb + P1_MB + 32 + s * 8, 16);
        }
    }
    {
        const float* srch = reinterpret_cast<const float*>(g_xh) + (size_t)rb * 8192;
        for (int i = tid; i < 2048; i += TPB_P1) cp16(sb + P1_AH + i * 16, srch + i * 4);
        cp_commit(); cp_wait0();
    }
    __syncthreads();

    if (wid < 16) {
        const int wm = wid >> 2, wn = wid & 3;
        float m1[4], m2[4]; int i1[4];
#pragma unroll
        for (int s = 0; s < 4; s++) { m1[s] = -CUDART_INF_F; m2[s] = -CUDART_INF_F; i1[s] = 0; }
        uint32_t pf[4] = {0, 0, 0, 0};
        float acc[2][4][4];

        for (int tt = 0; tt < ntseg; tt++) {
            const int t = t0 + tt;
            float cnh[8];
            const int cb = t * 128 + wn * 32 + (lane & 3) * 2;
#pragma unroll
            for (int na = 0; na < 4; na++) {
                cnh[na * 2]     = -0.5f * __ldg(&g_cnorm[cb + na * 8]);
                cnh[na * 2 + 1] = -0.5f * __ldg(&g_cnorm[cb + na * 8 + 1]);
            }
#pragma unroll
            for (int ma = 0; ma < 2; ma++)
#pragma unroll
                for (int na = 0; na < 4; na++) {
                    acc[ma][na][0] = cnh[na * 2];
                    acc[ma][na][1] = cnh[na * 2 + 1];
                    acc[ma][na][2] = cnh[na * 2];
                    acc[ma][na][3] = cnh[na * 2 + 1];
                }

#pragma unroll 1
            for (int kc = 0; kc < 4; kc++) {
                const int slot = kc;
                const uint32_t bch = (uint32_t)(P1_SLOT + (slot << 13));
                mbar_wait(sb + P1_MB + slot * 8, pf[slot]); pf[slot] ^= 1;
#pragma unroll
                for (int ks2 = 0; ks2 < 2; ks2++) {
                    const int ks = kc * 2 + ks2;
                    uint4 af[2]; uint2 bf[4];
#pragma unroll
                    for (int ma = 0; ma < 2; ma++)
                        af[ma] = *reinterpret_cast<const uint4*>(
                            smem + P1_AH + (((ks * 8) + wm * 2 + ma) * 32 + lane) * 16);
#pragma unroll
                    for (int na = 0; na < 4; na++)
                        bf[na] = *reinterpret_cast<const uint2*>(
                            smem + bch + (((ks2 * 16) + wn * 4 + na) * 32 + lane) * 8);
#pragma unroll
                    for (int ma = 0; ma < 2; ma++)
#pragma unroll
                        for (int na = 0; na < 4; na++)
                            mma16(acc[ma][na], af[ma], bf[na]);
                }
                if (lane == 0) mbar_arrive(sb + P1_MB + 32 + slot * 8);
            }
#pragma unroll
            for (int ma = 0; ma < 2; ma++) {
                const int slo = ma * 2, shi = ma * 2 + 1;
#pragma unroll
                for (int na = 0; na < 4; na++) {
                    const int c0 = t * 128 + wn * 32 + na * 8 + (lane & 3) * 2;
                    float a00 = acc[ma][na][0], a01 = acc[ma][na][1];
                    float a10 = acc[ma][na][2], a11 = acc[ma][na][3];
                    {
                        bool p = a00 > m1[slo];
                        m2[slo] = p ? m1[slo] : fmaxf(m2[slo], a00);
                        i1[slo] = p ? c0 : i1[slo];
                        m1[slo] = p ? a00 : m1[slo];
                    }
                    {
                        bool p = a01 > m1[slo];
                        m2[slo] = p ? m1[slo] : fmaxf(m2[slo], a01);
                        i1[slo] = p ? (c0 + 1) : i1[slo];
                        m1[slo] = p ? a01 : m1[slo];
                    }
                    {
                        bool p = a10 > m1[shi];
                        m2[shi] = p ? m1[shi] : fmaxf(m2[shi], a10);
                        i1[shi] = p ? c0 : i1[shi];
                        m1[shi] = p ? a10 : m1[shi];
                    }
                    {
                        bool p = a11 > m1[shi];
                        m2[shi] = p ? m1[shi] : fmaxf(m2[shi], a11);
                        i1[shi] = p ? (c0 + 1) : i1[shi];
                        m1[shi] = p ? a11 : m1[shi];
                    }
                }
            }
        }
#pragma unroll
        for (int s = 0; s < 4; s++) {
            float v1 = m1[s], v2 = m2[s]; int ii = i1[s];
#pragma unroll
            for (int o = 1; o <= 2; o <<= 1) {
                float a1 = __shfl_xor_sync(0xffffffffu, v1, o);
                float a2 = __shfl_xor_sync(0xffffffffu, v2, o);
                int   ai = __shfl_xor_sync(0xffffffffu, ii, o);
                bool bwin = (a1 > v1) || (a1 == v1 && ai < ii);
                float loser1 = bwin ? v1 : a1;
                v2 = fmaxf(fmaxf(v2, a2), loser1);
                v1 = bwin ? a1 : v1;
                ii = bwin ? ai : ii;
            }
            if ((lane & 3) == 0) {
                int row = wm * 32 + (s >> 1) * 16 + (s & 1) * 8 + (lane >> 2);
                reinterpret_cast<float*>(smem + P1_M1)[wn * 128 + row] = v1;
                reinterpret_cast<float*>(smem + P1_M2)[wn * 128 + row] = v2;
                reinterpret_cast<int*>(smem + P1_I1)[wn * 128 + row]   = ii;
            }
        }
    } else {
        const int pw = wid - 16;
        uint32_t pe[4] = {0, 0, 0, 0};
        const int nchunks = ntseg * 4;
        for (int c = pw; c < nchunks; c += 2) {
            const int slot = c & 3;
            if (c >= 4) { mbar_wait(sb + P1_MB + 32 + slot * 8, pe[slot]); pe[slot] ^= 1; }
            const float* src = reinterpret_cast<const float*>(g_ch) + ((size_t)(t0 * 4 + c) << 11);
            const uint32_t dst = sb + P1_SLOT + (slot << 13);
#pragma unroll
            for (int i = 0; i < 16; i++)
                cp16(dst + (uint32_t)((i * 32 + lane) << 4), src + ((i * 32 + lane) << 2));
            cp_commit(); cp_wait0();
            mbar_arrive(sb + P1_MB + slot * 8);
        }
    }
    __syncthreads();

    if (tid < 128) {
        const float* sm1 = reinterpret_cast<const float*>(smem + P1_M1);
        const float* sm2 = reinterpret_cast<const float*>(smem + P1_M2);
        const int*   si1 = reinterpret_cast<const int*>(smem + P1_I1);
        float v1 = sm1[tid], v2 = sm2[tid]; int ii = si1[tid];
#pragma unroll
        for (int wnn = 1; wnn < 4; wnn++) {
            float b1 = sm1[wnn * 128 + tid], b2 = sm2[wnn * 128 + tid];
            int   bi = si1[wnn * 128 + tid];
            bool bwin = (b1 > v1) || (b1 == v1 && bi < ii);
            float loser1 = bwin ? v1 : b1;
            v2 = fmaxf(fmaxf(v2, b2), loser1);
            v1 = bwin ? b1 : v1;
            ii = bwin ? bi : ii;
        }
        int o = seg * MAXB + row0 + tid;
        g_p1v1[o] = v1; g_p1v2[o] = v2; g_p1i1[o] = ii;
    }
}

// ============ decide: merge pass1 segments (max domain), tightened threshold ============
__global__ void decide_kernel()
{
    int row = blockIdx.x * 256 + threadIdx.x;
    float v1 = g_p1v1[row], v2 = g_p1v2[row]; int ii = g_p1i1[row];
    float b1 = g_p1v1[MAXB + row], b2 = g_p1v2[MAXB + row]; int bi = g_p1i1[MAXB + row];
    bool bwin = b1 > v1;
    float loser1 = bwin ? v1 : b1;
    float m2f = fmaxf(fmaxf(v2, b2), loser1);
    float m1f = bwin ? b1 : v1;
    int   idx = bwin ? bi : ii;
    g_idx[row] = idx;
    float xhn = g_xhn[row], xln = g_xln[row];
    float clm = __uint_as_float(g_clmax), chm = __uint_as_float(g_chmax);
    float eb = xhn * clm + xln * chm + xln * clm;   // per-code |key_hh - key_exact| <= 2*eb
    float thr = 4.0f * eb + 0.03125f;               // gap needs > 2*(2*eb) + accum slack
    float gap = 2.0f * (m1f - m2f);
    if (!(gap > thr)) {
        int p = atomicAdd(&g_count, 1);
        g_undec[p] = row;
    }
}

// ============ refine: exact 3-pass, C split into NSEG_RF segments (unchanged) ============
__global__ __launch_bounds__(TPB_RF, 2)
void vq_refine(const float* __restrict__ x, int C)
{
    const int cnt = *(volatile int*)&g_count;
    const int rg  = blockIdx.x >> 3;
    const int seg = blockIdx.x & 7;
    if (rg * 64 >= cnt) return;

    extern __shared__ char smem[];
    const uint32_t sb = smem_u32(smem);
    const int tid = threadIdx.x, wid = tid >> 5, lane = tid & 31;
    const int ntseg = (C >> 7) / NSEG_RF;
    const int t0 = seg * ntseg;

    if (tid == 0) {
#pragma unroll
        for (int s = 0; s < 4; s++) {
            mbar_init(sb + RF_MB + s * 8, 32);
            mbar_init(sb + RF_MB + 32 + s * 8, 4);
        }
    }
    int* list = reinterpret_cast<int*>(smem + RF_LIST);
    if (tid < 64) {
        int li = rg * 64 + tid;
        list[tid] = g_undec[(li < cnt) ? li : (cnt - 1)];
    }
    __syncthreads();
    if (tid < 128) {
        int r_loc = tid >> 1, half = tid & 1;
        int r = list[r_loc];
        const float4* xp = reinterpret_cast<const float4*>(x + (size_t)r * DDIM) + half * 16;
        __half2* ah = reinterpret_cast<__half2*>(smem + RF_AH);
        __half2* al = reinterpret_cast<__half2*>(smem + RF_AL);
#pragma unroll 4
        for (int qq = 0; qq < 16; qq++) {
            int q = half * 16 + qq;
            float4 v = xp[qq];
            float vv[4] = {v.x, v.y, v.z, v.w};
            __half h[4]; __half l[4];
#pragma unroll
            for (int j = 0; j < 4; j++) {
                h[j] = __float2half_rn(vv[j]);
                l[j] = __float2half_rn(vv[j] - __half2float(h[j]));
            }
#pragma unroll
            for (int p = 0; p < 2; p++) {
                int k = q * 4 + p * 2;
                int u = a_frag_h2_64(r_loc, k);
                ah[u] = __halves2half2(h[p * 2], h[p * 2 + 1]);
                al[u] = __halves2half2(l[p * 2], l[p * 2 + 1]);
            }
        }
    }
    __syncthreads();

    if (wid < 4) {
        const int wm = wid >> 1, wn = wid & 1;
        float acc[2][8][4];
#pragma unroll
        for (int a = 0; a < 2; a++)
#pragma unroll
            for (int b = 0; b < 8; b++)
#pragma unroll
                for (int r = 0; r < 4; r++) acc[a][b][r] = 0.0f;
        float bestv[4]; int besti[4];
#pragma unroll
        for (int s = 0; s < 4; s++) { bestv[s] = CUDART_INF_F; besti[s] = 0; }
        uint32_t pf[4] = {0, 0, 0, 0};

        for (int tt = 0; tt < ntseg; tt++) {
            const int t = t0 + tt;
            float cn[16];
            const int cb = t * 128 + wn * 64 + (lane & 3) * 2;
#pragma unroll
            for (int na = 0; na < 8; na++) {
                cn[na * 2]     = __ldg(&g_cnorm[cb + na * 8]);
                cn[na * 2 + 1] = __ldg(&g_cnorm[cb + na * 8 + 1]);
            }
#pragma unroll 1
            for (int kc = 0; kc < 4; kc++) {
                const int sch = (kc * 2) & 3, scl = sch + 1;
                const uint32_t bch = (uint32_t)(RF_SLOT + (sch << 13));
                const uint32_t bcl = (uint32_t)(RF_SLOT + (scl << 13));
                mbar_wait(sb + RF_MB + sch * 8, pf[sch]); pf[sch] ^= 1;
#pragma unroll
                for (int pass = 0; pass < 2; pass++) {
                    const uint32_t abase = pass ? RF_AL : RF_AH;
#pragma unroll
                    for (int ks2 = 0; ks2 < 2; ks2++) {
                        const int ks = kc * 2 + ks2;
                        uint4 af[2]; uint2 bf[8];
#pragma unroll
                        for (int ma = 0; ma < 2; ma++)
                            af[ma] = *reinterpret_cast<const uint4*>(
                                smem + abase + (((ks * 4) + wm * 2 + ma) * 32 + lane) * 16);
#pragma unroll
                        for (int na = 0; na < 8; na++)
                            bf[na] = *reinterpret_cast<const uint2*>(
                                smem + bch + (((ks2 * 16) + wn * 8 + na) * 32 + lane) * 8);
#pragma unroll
                        for (int ma = 0; ma < 2; ma++)
#pragma unroll
                            for (int na = 0; na < 8; na++)
                                mma16(acc[ma][na], af[ma], bf[na]);
                    }
                }
                if (lane == 0) mbar_arrive(sb + RF_MB + 32 + sch * 8);

                mbar_wait(sb + RF_MB + scl * 8, pf[scl]); pf[scl] ^= 1;
#pragma unroll
                for (int ks2 = 0; ks2 < 2; ks2++) {
                    const int ks = kc * 2 + ks2;
                    uint4 af[2]; uint2 bf[8];
#pragma unroll
                    for (int ma = 0; ma < 2; ma++)
                        af[ma] = *reinterpret_cast<const uint4*>(
                            smem + RF_AH + (((ks * 4) + wm * 2 + ma) * 32 + lane) * 16);
#pragma unroll
                    for (int na = 0; na < 8; na++)
                        bf[na] = *reinterpret_cast<const uint2*>(
                            smem + bcl + (((ks2 * 16) + wn * 8 + na) * 32 + lane) * 8);
#pragma unroll
                    for (int ma = 0; ma < 2; ma++)
#pragma unroll
                        for (int na = 0; na < 8; na++)
                            mma16(acc[ma][na], af[ma], bf[na]);
                }
                if (lane == 0) mbar_arrive(sb + RF_MB + 32 + scl * 8);
            }
#pragma unroll
            for (int ma = 0; ma < 2; ma++) {
                const int slo = ma * 2, shi = ma * 2 + 1;
#pragma unroll
                for (int na = 0; na < 8; na++) {
                    const int c0 = t * 128 + wn * 64 + na * 8 + (lane & 3) * 2;
                    float k00 = fmaf(-2.0f, acc[ma][na][0], cn[na * 2]);
                    float k01 = fmaf(-2.0f, acc[ma][na][1], cn[na * 2 + 1]);
                    float k10 = fmaf(-2.0f, acc[ma][na][2], cn[na * 2]);
                    float k11 = fmaf(-2.0f, acc[ma][na][3], cn[na * 2 + 1]);
                    if (k00 < bestv[slo]) { bestv[slo] = k00; besti[slo] = c0; }
                    if (k01 < bestv[slo]) { bestv[slo] = k01; besti[slo] = c0 + 1; }
                    if (k10 < bestv[shi]) { bestv[shi] = k10; besti[shi] = c0; }
                    if (k11 < bestv[shi]) { bestv[shi] = k11; besti[shi] = c0 + 1; }
                    acc[ma][na][0] = 0.0f; acc[ma][na][1] = 0.0f;
                    acc[ma][na][2] = 0.0f; acc[ma][na][3] = 0.0f;
                }
            }
        }
#pragma unroll
        for (int s = 0; s < 4; s++) {
            float v = bestv[s]; int bi = besti[s];
#pragma unroll
            for (int o = 1; o <= 2; o <<= 1) {
                float vo = __shfl_xor_sync(0xffffffffu, v, o);
                int   io = __shfl_xor_sync(0xffffffffu, bi, o);
                if (vo < v || (vo == v && io < bi)) { v = vo; bi = io; }
            }
            if ((lane & 3) == 0) {
                int row = wm * 32 + (s >> 1) * 16 + (s & 1) * 8 + (lane >> 2);
                reinterpret_cast<float*>(smem + RF_BV)[wn * 64 + row] = v;
                reinterpret_cast<int*>(smem + RF_BI)[wn * 64 + row]   = bi;
            }
        }
    } else {
        const int pw = wid - 4;
        uint32_t pe[4] = {0, 0, 0, 0};
        const int nchunks = ntseg * 8;
        for (int c = pw; c < nchunks; c += 2) {
            const int slot = c & 3;
            if (c >= 4) { mbar_wait(sb + RF_MB + 32 + slot * 8, pe[slot]); pe[slot] ^= 1; }
            const int t = t0 + (c >> 3), r = c & 7, kc = r >> 1;
            const float* src = reinterpret_cast<const float*>((r & 1) ? g_cl : g_ch)
                             + ((size_t)(t * 4 + kc) << 11);
            const uint32_t dst = sb + RF_SLOT + (slot << 13);
#pragma unroll
            for (int i = 0; i < 16; i++)
                cp16(dst + (uint32_t)((i * 32 + lane) << 4), src + ((i * 32 + lane) << 2));
            cp_commit(); cp_wait0();
            mbar_arrive(sb + RF_MB + slot * 8);
        }
    }
    __syncthreads();

    if (tid < 64) {
        const float* bv = reinterpret_cast<const float*>(smem + RF_BV);
        const int*   bixs = reinterpret_cast<const int*>(smem + RF_BI);
        float v0 = bv[tid], v1 = bv[64 + tid];
        int i0 = bixs[tid], i1v = bixs[64 + tid];
        int bi = (v1 < v0 || (v1 == v0 && i1v < i0)) ? i1v : i0;
        float vv = (v1 < v0 || (v1 == v0 && i1v < i0)) ? v1 : v0;
        int li = rg * 64 + tid;
        g_rv[seg * MAXB + li] = vv;
        g_ri[seg * MAXB + li] = bi;
    }
}

// ============ merge refine segments ============
__global__ void merge_refine()
{
    const int cnt = *(volatile int*)&g_count;
    int li = blockIdx.x * 256 + threadIdx.x;
    if (li >= cnt) return;
    float v = g_rv[li]; int bi = g_ri[li];
#pragma unroll
    for (int s = 1; s < NSEG_RF; s++) {
        float vo = g_rv[s * MAXB + li];
        int   io = g_ri[s * MAXB + li];
        if (vo < v) { v = vo; bi = io; }
    }
    g_idx[g_undec[li]] = bi;
}

// ============ gather + loss ============
__global__ void gather_loss(const float* __restrict__ x, const float* __restrict__ codes,
                            float* __restrict__ out_q, float* __restrict__ out_idx, int write_idx)
{
    const int tid = threadIdx.x, txg = tid & 15, grp = tid >> 4;
    const int base = blockIdx.x * 128;
    float thr_loss = 0.0f;
    for (int rr = grp; rr < 128; rr += 16) {
        int row = base + rr;
        int bi = g_idx[row];
        if (txg == 0 && write_idx) out_idx[row] = (float)bi;
        const float4* cq = reinterpret_cast<const float4*>(codes + (size_t)bi * DDIM + txg * 8);
        float4 q0 = cq[0], q1 = cq[1];
        float4* od = reinterpret_cast<float4*>(out_q + (size_t)row * DDIM + txg * 8);
        od[0] = q0; od[1] = q1;
        const float4* xp = reinterpret_cast<const float4*>(x + (size_t)row * DDIM + txg * 8);
        float4 x0 = xp[0], x1 = xp[1];
        float d;
        d = x0.x - q0.x; thr_loss = fmaf(d, d, thr_loss);
        d = x0.y - q0.y; thr_loss = fmaf(d, d, thr_loss);
        d = x0.z - q0.z; thr_loss = fmaf(d, d, thr_loss);
        d = x0.w - q0.w; thr_loss = fmaf(d, d, thr_loss);
        d = x1.x - q1.x; thr_loss = fmaf(d, d, thr_loss);
        d = x1.y - q1.y; thr_loss = fmaf(d, d, thr_loss);
        d = x1.z - q1.z; thr_loss = fmaf(d, d, thr_loss);
        d = x1.w - q1.w; thr_loss = fmaf(d, d, thr_loss);
    }
    __shared__ float red[8];
#pragma unroll
    for (int o = 16; o; o >>= 1) thr_loss += __shfl_xor_sync(0xffffffffu, thr_loss, o);
    if ((tid & 31) == 0) red[tid >> 5] = thr_loss;
    __syncthreads();
    if (tid == 0) {
        float s = 0.0f;
#pragma unroll
        for (int w = 0; w < 8; w++) s += red[w];
        g_block_loss[blockIdx.x] = s;
    }
}

__global__ void finalize_kernel(float* __restrict__ out_loss, int nblocks, float invB)
{
    __shared__ float red[256];
    float s = 0.0f;
    for (int i = threadIdx.x; i < nblocks; i += 256) s += g_block_loss[i];
    red[threadIdx.x] = s;
    __syncthreads();
    for (int o = 128; o; o >>= 1) {
        if (threadIdx.x < o) red[threadIdx.x] += red[threadIdx.x + o];
        __syncthreads();
    }
    if (threadIdx.x == 0) *out_loss = 1.25f * red[0] * invB;  // (1 + BETA) * mean ||x-q||^2
}

extern "C" void kernel_launch(void* const* d_in, const int* in_sizes, int n_in,
                              void* d_out, int out_size)
{
    const float* x     = (const float*)d_in[0];
    const float* codes = (const float*)d_in[1];
    const int B = in_sizes[0] / DDIM;
    const int C = in_sizes[1] / DDIM;

    float* out      = (float*)d_out;
    float* out_q    = out;
    float* out_idx  = out + (size_t)B * DDIM;
    float* out_loss = out + (size_t)B * DDIM + B;

    const long long need_idx  = (long long)B * DDIM + B;
    const long long need_loss = need_idx + 1;
    const int write_idx  = ((long long)out_size >= need_idx)  ? 1 : 0;
    const int write_loss = ((long long)out_size >= need_loss) ? 1 : 0;

    (void)cudaFuncSetAttribute(vq_pass1,  cudaFuncAttributeMaxDynamicSharedMemorySize, SMEM_P1);
    (void)cudaFuncSetAttribute(vq_refine, cudaFuncAttributeMaxDynamicSharedMemorySize, SMEM_RF);

    split_x<<<B / 128, 256>>>(x);
    split_c<<<C / 8, 256>>>(codes);
    vq_pass1<<<(B / 128) * NSEG_P1, TPB_P1, SMEM_P1>>>(C);
    decide_kernel<<<B / 256, 256>>>();
    vq_refine<<<(B / 64) * NSEG_RF, TPB_RF, SMEM_RF>>>(x, C);
    merge_refine<<<B / 256, 256>>>();
    gather_loss<<<B / 128, 256>>>(x, codes, out_q, out_idx, write_idx);
    if (write_loss)
        finalize_kernel<<<1, 256>>>(out_loss, B / 128, 1.0f / (float)B);
}

// round 13
// speedup vs baseline: 6.6285x; 1.0661x over previous
#include <cuda_runtime.h>
#include <cuda_fp16.h>
#include <math_constants.h>
#include <cstdint>

// Quantizer_33036888441545 — VQ argmin via hh-screen + exact 3xfp16 refine.
// R13: pass1 full-K ring slots (1 wait/tile, warp drift), branchless top-2,
//      merge_refine fused into gather, gather grid x2.

#define DDIM 128
#define MAXB 65536
#define MAXC 4096
#define NSEG_P1 2
#define NSEG_RF 8
#define TPB_P1 576
#define TPB_RF 192

__device__ __half    g_xh[MAXB * DDIM];
__device__ __half    g_ch[MAXC * DDIM];
__device__ __half    g_cl[MAXC * DDIM];
__device__ float     g_cnorm[MAXC];
__device__ float     g_xhn[MAXB];
__device__ float     g_xln[MAXB];
__device__ unsigned  g_clmax;
__device__ unsigned  g_chmax;
__device__ int       g_idx[MAXB];
__device__ int       g_undec[MAXB];
__device__ int       g_count;
__device__ float     g_p1v1[NSEG_P1 * MAXB];
__device__ float     g_p1v2[NSEG_P1 * MAXB];
__device__ int       g_p1i1[NSEG_P1 * MAXB];
__device__ float     g_rv[NSEG_RF * MAXB];
__device__ int       g_ri[NSEG_RF * MAXB];
__device__ float     g_block_loss[1024];

// ---- pass1 smem map (BM=128, 3 full-K slots) ----
#define P1_AH    0          // 32KB A-hi frags
#define P1_SLOT  32768      // 3 x 32KB B slots
#define P1_MB    131072     // full[3] @+0..16 ; empty[3] @+24..40
#define P1_M1    131136     // float [4][128]
#define P1_M2    133184
#define P1_I1    135232
#define SMEM_P1  137280

// ---- refine smem map (BM=64, unchanged) ----
#define RF_AH    0
#define RF_AL    16384
#define RF_SLOT  32768
#define RF_MB    65536
#define RF_BV    65600
#define RF_BI    66112
#define RF_LIST  66624
#define SMEM_RF  66880

// ============ helpers ============
__device__ __forceinline__ uint32_t smem_u32(const void* p) {
    uint32_t a;
    asm("{ .reg .u64 t; cvta.to.shared.u64 t, %1; cvt.u32.u64 %0, t; }" : "=r"(a) : "l"(p));
    return a;
}
__device__ __forceinline__ void mbar_init(uint32_t a, uint32_t cnt) {
    asm volatile("mbarrier.init.shared.b64 [%0], %1;" :: "r"(a), "r"(cnt) : "memory");
}
__device__ __forceinline__ void mbar_arrive(uint32_t a) {
    asm volatile("mbarrier.arrive.shared.b64 _, [%0];" :: "r"(a) : "memory");
}
__device__ __forceinline__ void mbar_wait(uint32_t a, uint32_t parity) {
    uint32_t done = 0;
    while (!done) {
        asm volatile(
            "{ .reg .pred p; mbarrier.try_wait.parity.acquire.cta.shared::cta.b64 p, [%1], %2, 0x989680; selp.b32 %0,1,0,p; }"
            : "=r"(done) : "r"(a), "r"(parity) : "memory");
    }
}
__device__ __forceinline__ void cp16(uint32_t dst, const float* src) {
    asm volatile("cp.async.cg.shared.global [%0], [%1], 16;" :: "r"(dst), "l"(src) : "memory");
}
__device__ __forceinline__ void cp_commit() { asm volatile("cp.async.commit_group;" ::: "memory"); }
__device__ __forceinline__ void cp_wait0()  { asm volatile("cp.async.wait_group 0;"  ::: "memory"); }

__device__ __forceinline__ void mma16(float* c, const uint4& a, const uint2& b) {
    asm volatile(
        "mma.sync.aligned.m16n8k16.row.col.f32.f16.f16.f32 "
        "{%0,%1,%2,%3}, {%4,%5,%6,%7}, {%8,%9}, {%0,%1,%2,%3};"
        : "+f"(c[0]), "+f"(c[1]), "+f"(c[2]), "+f"(c[3])
        : "r"(a.x), "r"(a.y), "r"(a.z), "r"(a.w), "r"(b.x), "r"(b.y));
}

// A-frag half2-unit index, 64-row block (refine), row mloc (0..63), even k.
__device__ __forceinline__ int a_frag_h2_64(int mloc, int k) {
    int ks = k >> 4, kk = k & 15, ma = mloc >> 4, r = mloc & 15;
    int lane = (r & 7) * 4 + ((kk & 7) >> 1);
    int reg  = ((kk >> 3) << 1) | (r >> 3);
    return ((ks * 4 + ma) * 32 + lane) * 4 + reg;
}
// A-frag half2-unit index, 128-row block (pass1), row mloc (0..127), even k.
__device__ __forceinline__ int a_frag_h2_128(int mloc, int k) {
    int ks = k >> 4, kk = k & 15, ma = mloc >> 4, r = mloc & 15;
    int lane = (r & 7) * 4 + ((kk & 7) >> 1);
    int reg  = ((kk >> 3) << 1) | (r >> 3);
    return ((ks * 8 + ma) * 32 + lane) * 4 + reg;
}

// ============ split_x: smem-staged coalesced frag output (unchanged from R12) ============
__global__ void split_x(const float* __restrict__ x)
{
    if (blockIdx.x == 0 && threadIdx.x == 0) { g_count = 0; g_clmax = 0u; g_chmax = 0u; }
    __shared__ __half2 stage[8192];
    const int tid = threadIdx.x, wid = tid >> 5, lane = tid & 31;
    const int blk = blockIdx.x;

#pragma unroll 4
    for (int it = 0; it < 16; it++) {
        int mloc = wid * 16 + it;
        int row = blk * 128 + mloc;
        float4 v = reinterpret_cast<const float4*>(x)[(size_t)row * 32 + lane];
        float vv[4] = {v.x, v.y, v.z, v.w};
        __half h[4];
        float hs = 0.0f, ls = 0.0f;
#pragma unroll
        for (int j = 0; j < 4; j++) {
            h[j] = __float2half_rn(vv[j]);
            float hf = __half2float(h[j]);
            float l = vv[j] - hf;
            hs = fmaf(hf, hf, hs);
            ls = fmaf(l, l, ls);
        }
        int u = a_frag_h2_128(mloc, lane * 4);
        stage[u]     = __halves2half2(h[0], h[1]);
        stage[u + 4] = __halves2half2(h[2], h[3]);
#pragma unroll
        for (int o = 16; o; o >>= 1) {
            hs += __shfl_xor_sync(0xffffffffu, hs, o);
            ls += __shfl_xor_sync(0xffffffffu, ls, o);
        }
        if (lane == 0) { g_xhn[row] = sqrtf(hs); g_xln[row] = sqrtf(ls); }
    }
    __syncthreads();
    float4* dst = reinterpret_cast<float4*>(g_xh) + (size_t)blk * 2048;
    const float4* src = reinterpret_cast<const float4*>(stage);
    for (int i = tid; i < 2048; i += 256) dst[i] = src[i];
}

// ============ split_c (unchanged) ============
__global__ void split_c(const float* __restrict__ codes)
{
    int n    = blockIdx.x * 8 + (threadIdx.x >> 5);
    int lane = threadIdx.x & 31;
    float4 v = reinterpret_cast<const float4*>(codes)[(size_t)n * 32 + lane];
    float vv[4] = {v.x, v.y, v.z, v.w};
    __half h[4]; float l[4];
    float cs = 0.0f, hs = 0.0f, ls = 0.0f;
#pragma unroll
    for (int j = 0; j < 4; j++) {
        h[j] = __float2half_rn(vv[j]);
        float hf = __half2float(h[j]);
        l[j] = vv[j] - hf;
        cs = fmaf(vv[j], vv[j], cs);
        hs = fmaf(hf, hf, hs);
        ls = fmaf(l[j], l[j], ls);
    }
    int t = n >> 7, nloc = n & 127, na = nloc >> 3;
    __half2* ch2 = reinterpret_cast<__half2*>(g_ch);
    __half2* cl2 = reinterpret_cast<__half2*>(g_cl);
#pragma unroll
    for (int p = 0; p < 2; p++) {
        int k = lane * 4 + p * 2;
        int kc = k >> 5, ks2 = (k >> 4) & 1, kk = k & 15;
        int lane_f = (nloc & 7) * 4 + ((kk & 7) >> 1);
        int reg    = kk >> 3;
        size_t u = ((((size_t)(t * 4 + kc) * 2 + ks2) * 16 + na) * 32 + lane_f) * 2 + reg;
        ch2[u] = __halves2half2(h[p * 2], h[p * 2 + 1]);
        cl2[u] = __halves2half2(__float2half_rn(l[p * 2]), __float2half_rn(l[p * 2 + 1]));
    }
#pragma unroll
    for (int o = 16; o; o >>= 1) {
        cs += __shfl_xor_sync(0xffffffffu, cs, o);
        hs += __shfl_xor_sync(0xffffffffu, hs, o);
        ls += __shfl_xor_sync(0xffffffffu, ls, o);
    }
    if (lane == 0) {
        g_cnorm[n] = cs;
        atomicMax(&g_chmax, __float_as_uint(sqrtf(hs)));
        atomicMax(&g_clmax, __float_as_uint(sqrtf(ls)));
    }
}

// ============ pass1: hh GEMM, full-K slots, 1 wait/tile, branchless top-2 ============
__global__ __launch_bounds__(TPB_P1, 1)
void vq_pass1(int C)
{
    extern __shared__ char smem[];
    const uint32_t sb = smem_u32(smem);
    const int tid = threadIdx.x, wid = tid >> 5, lane = tid & 31;
    const int rb  = blockIdx.x >> 1;
    const int seg = blockIdx.x & 1;
    const int row0 = rb * 128;
    const int ntseg = (C >> 7) / NSEG_P1;      // 16 tiles
    const int t0 = seg * ntseg;

    if (tid == 0) {
#pragma unroll
        for (int s = 0; s < 3; s++) {
            mbar_init(sb + P1_MB + s * 8, 64);        // full: 2 producer warps x 32 lanes
            mbar_init(sb + P1_MB + 24 + s * 8, 16);   // empty: 16 math warps
        }
    }
    {   // resident A-hi (32KB)
        const float* srch = reinterpret_cast<const float*>(g_xh) + (size_t)rb * 8192;
        for (int i = tid; i < 2048; i += TPB_P1) cp16(sb + P1_AH + i * 16, srch + i * 4);
        cp_commit(); cp_wait0();
    }
    __syncthreads();

    if (wid < 16) {
        const int wm = wid >> 2, wn = wid & 3;
        float m1[4], m2[4]; int i1[4];
#pragma unroll
        for (int s = 0; s < 4; s++) { m1[s] = -CUDART_INF_F; m2[s] = -CUDART_INF_F; i1[s] = 0; }
        uint32_t pf[3] = {0, 0, 0};
        float acc[2][4][4];

        for (int tt = 0; tt < ntseg; tt++) {
            const int t = t0 + tt;
            const int slot = tt % 3;
            const uint32_t bbase = (uint32_t)(P1_SLOT + slot * 32768);
            float cnh[8];
            const int cb = t * 128 + wn * 32 + (lane & 3) * 2;
#pragma unroll
            for (int na = 0; na < 4; na++) {
                cnh[na * 2]     = -0.5f * __ldg(&g_cnorm[cb + na * 8]);
                cnh[na * 2 + 1] = -0.5f * __ldg(&g_cnorm[cb + na * 8 + 1]);
            }
#pragma unroll
            for (int ma = 0; ma < 2; ma++)
#pragma unroll
                for (int na = 0; na < 4; na++) {
                    acc[ma][na][0] = cnh[na * 2];
                    acc[ma][na][1] = cnh[na * 2 + 1];
                    acc[ma][na][2] = cnh[na * 2];
                    acc[ma][na][3] = cnh[na * 2 + 1];
                }

            mbar_wait(sb + P1_MB + slot * 8, pf[slot]); pf[slot] ^= 1;
#pragma unroll
            for (int ks = 0; ks < 8; ks++) {
                uint4 af[2]; uint2 bf[4];
#pragma unroll
                for (int ma = 0; ma < 2; ma++)
                    af[ma] = *reinterpret_cast<const uint4*>(
                        smem + P1_AH + (((ks * 8) + wm * 2 + ma) * 32 + lane) * 16);
#pragma unroll
                for (int na = 0; na < 4; na++)
                    bf[na] = *reinterpret_cast<const uint2*>(
                        smem + bbase + (((ks * 16) + wn * 4 + na) * 32 + lane) * 8);
#pragma unroll
                for (int ma = 0; ma < 2; ma++)
#pragma unroll
                    for (int na = 0; na < 4; na++)
                        mma16(acc[ma][na], af[ma], bf[na]);
            }
            if (lane == 0) mbar_arrive(sb + P1_MB + 24 + slot * 8);

            // branchless top-2 (max domain); ties keep first index; gap 0 -> refine
#pragma unroll
            for (int ma = 0; ma < 2; ma++) {
                const int slo = ma * 2, shi = ma * 2 + 1;
#pragma unroll
                for (int na = 0; na < 4; na++) {
                    const int c0 = t * 128 + wn * 32 + na * 8 + (lane & 3) * 2;
                    float a00 = acc[ma][na][0], a01 = acc[ma][na][1];
                    float a10 = acc[ma][na][2], a11 = acc[ma][na][3];
                    m2[slo] = fmaxf(m2[slo], fminf(a00, m1[slo]));
                    i1[slo] = (a00 > m1[slo]) ? c0 : i1[slo];
                    m1[slo] = fmaxf(m1[slo], a00);
                    m2[slo] = fmaxf(m2[slo], fminf(a01, m1[slo]));
                    i1[slo] = (a01 > m1[slo]) ? (c0 + 1) : i1[slo];
                    m1[slo] = fmaxf(m1[slo], a01);
                    m2[shi] = fmaxf(m2[shi], fminf(a10, m1[shi]));
                    i1[shi] = (a10 > m1[shi]) ? c0 : i1[shi];
                    m1[shi] = fmaxf(m1[shi], a10);
                    m2[shi] = fmaxf(m2[shi], fminf(a11, m1[shi]));
                    i1[shi] = (a11 > m1[shi]) ? (c0 + 1) : i1[shi];
                    m1[shi] = fmaxf(m1[shi], a11);
                }
            }
        }
#pragma unroll
        for (int s = 0; s < 4; s++) {
            float v1 = m1[s], v2 = m2[s]; int ii = i1[s];
#pragma unroll
            for (int o = 1; o <= 2; o <<= 1) {
                float a1 = __shfl_xor_sync(0xffffffffu, v1, o);
                float a2 = __shfl_xor_sync(0xffffffffu, v2, o);
                int   ai = __shfl_xor_sync(0xffffffffu, ii, o);
                bool bwin = (a1 > v1) || (a1 == v1 && ai < ii);
                float loser1 = bwin ? v1 : a1;
                v2 = fmaxf(fmaxf(v2, a2), loser1);
                v1 = bwin ? a1 : v1;
                ii = bwin ? ai : ii;
            }
            if ((lane & 3) == 0) {
                int row = wm * 32 + (s >> 1) * 16 + (s & 1) * 8 + (lane >> 2);
                reinterpret_cast<float*>(smem + P1_M1)[wn * 128 + row] = v1;
                reinterpret_cast<float*>(smem + P1_M2)[wn * 128 + row] = v2;
                reinterpret_cast<int*>(smem + P1_I1)[wn * 128 + row]   = ii;
            }
        }
    } else {
        // ---------------- 2 producer warps co-fill full-K slots ----------------
        const int pw = wid - 16;
        uint32_t pe[3] = {0, 0, 0};
        for (int tt = 0; tt < ntseg; tt++) {
            const int slot = tt % 3;
            if (tt >= 3) { mbar_wait(sb + P1_MB + 24 + slot * 8, pe[slot]); pe[slot] ^= 1; }
            const float* src = reinterpret_cast<const float*>(g_ch)
                             + ((size_t)(t0 + tt) * 8192) + pw * 4096;
            const uint32_t dst = sb + P1_SLOT + slot * 32768 + pw * 16384;
#pragma unroll
            for (int i = 0; i < 32; i++)
                cp16(dst + (uint32_t)((i * 32 + lane) << 4), src + ((i * 32 + lane) << 2));
            cp_commit(); cp_wait0();
            mbar_arrive(sb + P1_MB + slot * 8);   // 32 lanes x 2 warps -> 64
        }
    }
    __syncthreads();

    if (tid < 128) {
        const float* sm1 = reinterpret_cast<const float*>(smem + P1_M1);
        const float* sm2 = reinterpret_cast<const float*>(smem + P1_M2);
        const int*   si1 = reinterpret_cast<const int*>(smem + P1_I1);
        float v1 = sm1[tid], v2 = sm2[tid]; int ii = si1[tid];
#pragma unroll
        for (int wnn = 1; wnn < 4; wnn++) {
            float b1 = sm1[wnn * 128 + tid], b2 = sm2[wnn * 128 + tid];
            int   bi = si1[wnn * 128 + tid];
            bool bwin = (b1 > v1) || (b1 == v1 && bi < ii);
            float loser1 = bwin ? v1 : b1;
            v2 = fmaxf(fmaxf(v2, b2), loser1);
            v1 = bwin ? b1 : v1;
            ii = bwin ? bi : ii;
        }
        int o = seg * MAXB + row0 + tid;
        g_p1v1[o] = v1; g_p1v2[o] = v2; g_p1i1[o] = ii;
    }
}

// ============ decide: merge segs, threshold; undecided marked -(li+1) in g_idx ============
__global__ void decide_kernel()
{
    int row = blockIdx.x * 256 + threadIdx.x;
    float v1 = g_p1v1[row], v2 = g_p1v2[row]; int ii = g_p1i1[row];
    float b1 = g_p1v1[MAXB + row], b2 = g_p1v2[MAXB + row]; int bi = g_p1i1[MAXB + row];
    bool bwin = b1 > v1;
    float loser1 = bwin ? v1 : b1;
    float m2f = fmaxf(fmaxf(v2, b2), loser1);
    float m1f = bwin ? b1 : v1;
    int   idx = bwin ? bi : ii;
    float xhn = g_xhn[row], xln = g_xln[row];
    float clm = __uint_as_float(g_clmax), chm = __uint_as_float(g_chmax);
    float eb = xhn * clm + xln * chm + xln * clm;
    float thr = 4.0f * eb + 0.03125f;
    float gap = 2.0f * (m1f - m2f);
    if (gap > thr) {
        g_idx[row] = idx;
    } else {
        int p = atomicAdd(&g_count, 1);
        g_undec[p] = row;
        g_idx[row] = -(p + 1);
    }
}

// ============ refine: exact 3-pass, C split into NSEG_RF segments (unchanged) ============
__global__ __launch_bounds__(TPB_RF, 2)
void vq_refine(const float* __restrict__ x, int C)
{
    const int cnt = *(volatile int*)&g_count;
    const int rg  = blockIdx.x >> 3;
    const int seg = blockIdx.x & 7;
    if (rg * 64 >= cnt) return;

    extern __shared__ char smem[];
    const uint32_t sb = smem_u32(smem);
    const int tid = threadIdx.x, wid = tid >> 5, lane = tid & 31;
    const int ntseg = (C >> 7) / NSEG_RF;
    const int t0 = seg * ntseg;

    if (tid == 0) {
#pragma unroll
        for (int s = 0; s < 4; s++) {
            mbar_init(sb + RF_MB + s * 8, 32);
            mbar_init(sb + RF_MB + 32 + s * 8, 4);
        }
    }
    int* list = reinterpret_cast<int*>(smem + RF_LIST);
    if (tid < 64) {
        int li = rg * 64 + tid;
        list[tid] = g_undec[(li < cnt) ? li : (cnt - 1)];
    }
    __syncthreads();
    if (tid < 128) {
        int r_loc = tid >> 1, half = tid & 1;
        int r = list[r_loc];
        const float4* xp = reinterpret_cast<const float4*>(x + (size_t)r * DDIM) + half * 16;
        __half2* ah = reinterpret_cast<__half2*>(smem + RF_AH);
        __half2* al = reinterpret_cast<__half2*>(smem + RF_AL);
#pragma unroll 4
        for (int qq = 0; qq < 16; qq++) {
            int q = half * 16 + qq;
            float4 v = xp[qq];
            float vv[4] = {v.x, v.y, v.z, v.w};
            __half h[4]; __half l[4];
#pragma unroll
            for (int j = 0; j < 4; j++) {
                h[j] = __float2half_rn(vv[j]);
                l[j] = __float2half_rn(vv[j] - __half2float(h[j]));
            }
#pragma unroll
            for (int p = 0; p < 2; p++) {
                int k = q * 4 + p * 2;
                int u = a_frag_h2_64(r_loc, k);
                ah[u] = __halves2half2(h[p * 2], h[p * 2 + 1]);
                al[u] = __halves2half2(l[p * 2], l[p * 2 + 1]);
            }
        }
    }
    __syncthreads();

    if (wid < 4) {
        const int wm = wid >> 1, wn = wid & 1;
        float acc[2][8][4];
#pragma unroll
        for (int a = 0; a < 2; a++)
#pragma unroll
            for (int b = 0; b < 8; b++)
#pragma unroll
                for (int r = 0; r < 4; r++) acc[a][b][r] = 0.0f;
        float bestv[4]; int besti[4];
#pragma unroll
        for (int s = 0; s < 4; s++) { bestv[s] = CUDART_INF_F; besti[s] = 0; }
        uint32_t pf[4] = {0, 0, 0, 0};

        for (int tt = 0; tt < ntseg; tt++) {
            const int t = t0 + tt;
            float cn[16];
            const int cb = t * 128 + wn * 64 + (lane & 3) * 2;
#pragma unroll
            for (int na = 0; na < 8; na++) {
                cn[na * 2]     = __ldg(&g_cnorm[cb + na * 8]);
                cn[na * 2 + 1] = __ldg(&g_cnorm[cb + na * 8 + 1]);
            }
#pragma unroll 1
            for (int kc = 0; kc < 4; kc++) {
                const int sch = (kc * 2) & 3, scl = sch + 1;
                const uint32_t bch = (uint32_t)(RF_SLOT + (sch << 13));
                const uint32_t bcl = (uint32_t)(RF_SLOT + (scl << 13));
                mbar_wait(sb + RF_MB + sch * 8, pf[sch]); pf[sch] ^= 1;
#pragma unroll
                for (int pass = 0; pass < 2; pass++) {
                    const uint32_t abase = pass ? RF_AL : RF_AH;
#pragma unroll
                    for (int ks2 = 0; ks2 < 2; ks2++) {
                        const int ks = kc * 2 + ks2;
                        uint4 af[2]; uint2 bf[8];
#pragma unroll
                        for (int ma = 0; ma < 2; ma++)
                            af[ma] = *reinterpret_cast<const uint4*>(
                                smem + abase + (((ks * 4) + wm * 2 + ma) * 32 + lane) * 16);
#pragma unroll
                        for (int na = 0; na < 8; na++)
                            bf[na] = *reinterpret_cast<const uint2*>(
                                smem + bch + (((ks2 * 16) + wn * 8 + na) * 32 + lane) * 8);
#pragma unroll
                        for (int ma = 0; ma < 2; ma++)
#pragma unroll
                            for (int na = 0; na < 8; na++)
                                mma16(acc[ma][na], af[ma], bf[na]);
                    }
                }
                if (lane == 0) mbar_arrive(sb + RF_MB + 32 + sch * 8);

                mbar_wait(sb + RF_MB + scl * 8, pf[scl]); pf[scl] ^= 1;
#pragma unroll
                for (int ks2 = 0; ks2 < 2; ks2++) {
                    const int ks = kc * 2 + ks2;
                    uint4 af[2]; uint2 bf[8];
#pragma unroll
                    for (int ma = 0; ma < 2; ma++)
                        af[ma] = *reinterpret_cast<const uint4*>(
                            smem + RF_AH + (((ks * 4) + wm * 2 + ma) * 32 + lane) * 16);
#pragma unroll
                    for (int na = 0; na < 8; na++)
                        bf[na] = *reinterpret_cast<const uint2*>(
                            smem + bcl + (((ks2 * 16) + wn * 8 + na) * 32 + lane) * 8);
#pragma unroll
                    for (int ma = 0; ma < 2; ma++)
#pragma unroll
                        for (int na = 0; na < 8; na++)
                            mma16(acc[ma][na], af[ma], bf[na]);
                }
                if (lane == 0) mbar_arrive(sb + RF_MB + 32 + scl * 8);
            }
#pragma unroll
            for (int ma = 0; ma < 2; ma++) {
                const int slo = ma * 2, shi = ma * 2 + 1;
#pragma unroll
                for (int na = 0; na < 8; na++) {
                    const int c0 = t * 128 + wn * 64 + na * 8 + (lane & 3) * 2;
                    float k00 = fmaf(-2.0f, acc[ma][na][0], cn[na * 2]);
                    float k01 = fmaf(-2.0f, acc[ma][na][1], cn[na * 2 + 1]);
                    float k10 = fmaf(-2.0f, acc[ma][na][2], cn[na * 2]);
                    float k11 = fmaf(-2.0f, acc[ma][na][3], cn[na * 2 + 1]);
                    if (k00 < bestv[slo]) { bestv[slo] = k00; besti[slo] = c0; }
                    if (k01 < bestv[slo]) { bestv[slo] = k01; besti[slo] = c0 + 1; }
                    if (k10 < bestv[shi]) { bestv[shi] = k10; besti[shi] = c0; }
                    if (k11 < bestv[shi]) { bestv[shi] = k11; besti[shi] = c0 + 1; }
                    acc[ma][na][0] = 0.0f; acc[ma][na][1] = 0.0f;
                    acc[ma][na][2] = 0.0f; acc[ma][na][3] = 0.0f;
                }
            }
        }
#pragma unroll
        for (int s = 0; s < 4; s++) {
            float v = bestv[s]; int bi = besti[s];
#pragma unroll
            for (int o = 1; o <= 2; o <<= 1) {
                float vo = __shfl_xor_sync(0xffffffffu, v, o);
                int   io = __shfl_xor_sync(0xffffffffu, bi, o);
                if (vo < v || (vo == v && io < bi)) { v = vo; bi = io; }
            }
            if ((lane & 3) == 0) {
                int row = wm * 32 + (s >> 1) * 16 + (s & 1) * 8 + (lane >> 2);
                reinterpret_cast<float*>(smem + RF_BV)[wn * 64 + row] = v;
                reinterpret_cast<int*>(smem + RF_BI)[wn * 64 + row]   = bi;
            }
        }
    } else {
        const int pw = wid - 4;
        uint32_t pe[4] = {0, 0, 0, 0};
        const int nchunks = ntseg * 8;
        for (int c = pw; c < nchunks; c += 2) {
            const int slot = c & 3;
            if (c >= 4) { mbar_wait(sb + RF_MB + 32 + slot * 8, pe[slot]); pe[slot] ^= 1; }
            const int t = t0 + (c >> 3), r = c & 7, kc = r >> 1;
            const float* src = reinterpret_cast<const float*>((r & 1) ? g_cl : g_ch)
                             + ((size_t)(t * 4 + kc) << 11);
            const uint32_t dst = sb + RF_SLOT + (slot << 13);
#pragma unroll
            for (int i = 0; i < 16; i++)
                cp16(dst + (uint32_t)((i * 32 + lane) << 4), src + ((i * 32 + lane) << 2));
            cp_commit(); cp_wait0();
            mbar_arrive(sb + RF_MB + slot * 8);
        }
    }
    __syncthreads();

    if (tid < 64) {
        const float* bv = reinterpret_cast<const float*>(smem + RF_BV);
        const int*   bixs = reinterpret_cast<const int*>(smem + RF_BI);
        float v0 = bv[tid], v1 = bv[64 + tid];
        int i0 = bixs[tid], i1v = bixs[64 + tid];
        int bi = (v1 < v0 || (v1 == v0 && i1v < i0)) ? i1v : i0;
        float vv = (v1 < v0 || (v1 == v0 && i1v < i0)) ? v1 : v0;
        int li = rg * 64 + tid;
        g_rv[seg * MAXB + li] = vv;
        g_ri[seg * MAXB + li] = bi;
    }
}

// ============ gather + loss (inline refine-segment merge) ============
__global__ void gather_loss(const float* __restrict__ x, const float* __restrict__ codes,
                            float* __restrict__ out_q, float* __restrict__ out_idx, int write_idx)
{
    const int tid = threadIdx.x, txg = tid & 15, grp = tid >> 4;
    const int base = blockIdx.x * 64;
    float thr_loss = 0.0f;
    for (int rr = grp; rr < 64; rr += 16) {
        int row = base + rr;
        int bi = g_idx[row];
        if (bi < 0) {                       // undecided: merge 8 refine segments
            int li = -bi - 1;
            float v = g_rv[li]; bi = g_ri[li];
#pragma unroll
            for (int s = 1; s < NSEG_RF; s++) {
                float vo = g_rv[s * MAXB + li];
                int   io = g_ri[s * MAXB + li];
                if (vo < v) { v = vo; bi = io; }   // segs index-ordered; strict < = first-min
            }
        }
        if (txg == 0 && write_idx) out_idx[row] = (float)bi;
        const float4* cq = reinterpret_cast<const float4*>(codes + (size_t)bi * DDIM + txg * 8);
        float4 q0 = cq[0], q1 = cq[1];
        float4* od = reinterpret_cast<float4*>(out_q + (size_t)row * DDIM + txg * 8);
        od[0] = q0; od[1] = q1;
        const float4* xp = reinterpret_cast<const float4*>(x + (size_t)row * DDIM + txg * 8);
        float4 x0 = xp[0], x1 = xp[1];
        float d;
        d = x0.x - q0.x; thr_loss = fmaf(d, d, thr_loss);
        d = x0.y - q0.y; thr_loss = fmaf(d, d, thr_loss);
        d = x0.z - q0.z; thr_loss = fmaf(d, d, thr_loss);
        d = x0.w - q0.w; thr_loss = fmaf(d, d, thr_loss);
        d = x1.x - q1.x; thr_loss = fmaf(d, d, thr_loss);
        d = x1.y - q1.y; thr_loss = fmaf(d, d, thr_loss);
        d = x1.z - q1.z; thr_loss = fmaf(d, d, thr_loss);
        d = x1.w - q1.w; thr_loss = fmaf(d, d, thr_loss);
    }
    __shared__ float red[8];
#pragma unroll
    for (int o = 16; o; o >>= 1) thr_loss += __shfl_xor_sync(0xffffffffu, thr_loss, o);
    if ((tid & 31) == 0) red[tid >> 5] = thr_loss;
    __syncthreads();
    if (tid == 0) {
        float s = 0.0f;
#pragma unroll
        for (int w = 0; w < 8; w++) s += red[w];
        g_block_loss[blockIdx.x] = s;
    }
}

__global__ void finalize_kernel(float* __restrict__ out_loss, int nblocks, float invB)
{
    __shared__ float red[256];
    float s = 0.0f;
    for (int i = threadIdx.x; i < nblocks; i += 256) s += g_block_loss[i];
    red[threadIdx.x] = s;
    __syncthreads();
    for (int o = 128; o; o >>= 1) {
        if (threadIdx.x < o) red[threadIdx.x] += red[threadIdx.x + o];
        __syncthreads();
    }
    if (threadIdx.x == 0) *out_loss = 1.25f * red[0] * invB;  // (1 + BETA) * mean ||x-q||^2
}

extern "C" void kernel_launch(void* const* d_in, const int* in_sizes, int n_in,
                              void* d_out, int out_size)
{
    const float* x     = (const float*)d_in[0];
    const float* codes = (const float*)d_in[1];
    const int B = in_sizes[0] / DDIM;
    const int C = in_sizes[1] / DDIM;

    float* out      = (float*)d_out;
    float* out_q    = out;
    float* out_idx  = out + (size_t)B * DDIM;
    float* out_loss = out + (size_t)B * DDIM + B;

    const long long need_idx  = (long long)B * DDIM + B;
    const long long need_loss = need_idx + 1;
    const int write_idx  = ((long long)out_size >= need_idx)  ? 1 : 0;
    const int write_loss = ((long long)out_size >= need_loss) ? 1 : 0;

    (void)cudaFuncSetAttribute(vq_pass1,  cudaFuncAttributeMaxDynamicSharedMemorySize, SMEM_P1);
    (void)cudaFuncSetAttribute(vq_refine, cudaFuncAttributeMaxDynamicSharedMemorySize, SMEM_RF);

    split_x<<<B / 128, 256>>>(x);
    split_c<<<C / 8, 256>>>(codes);
    vq_pass1<<<(B / 128) * NSEG_P1, TPB_P1, SMEM_P1>>>(C);
    decide_kernel<<<B / 256, 256>>>();
    vq_refine<<<(B / 64) * NSEG_RF, TPB_RF, SMEM_RF>>>(x, C);
    gather_loss<<<B / 64, 256>>>(x, codes, out_q, out_idx, write_idx);
    if (write_loss)
        finalize_kernel<<<1, 256>>>(out_loss, B / 64, 1.0f / (float)B);
}